// round 1
// baseline (speedup 1.0000x reference)
#include <cuda_runtime.h>

static constexpr int SEQ = 2048;
static constexpr int NB  = 2;
static constexpr int D   = 1024;
static constexpr int NH  = 16;
static constexpr int DH  = 64;
static constexpr int M_TOT = NB * SEQ; // 4096

// Scratch (allocation-free rule: __device__ globals)
__device__ float g_Q[M_TOT * D];
__device__ float g_K[M_TOT * D];
__device__ float g_V[M_TOT * D];
__device__ float g_ctx[M_TOT * D];

// ---------------------------------------------------------------------------
// GEMM: C[M,N] = A[M,K] @ W[K,N] + bias, row-major. Tiles 64x64, BK=16.
// 256 threads, each computes a 4x4 micro-tile.
// ---------------------------------------------------------------------------
__global__ __launch_bounds__(256) void gemm_bias_kernel(
    const float* __restrict__ A, const float* __restrict__ W,
    const float* __restrict__ bias, float* __restrict__ C,
    int M, int K, int N)
{
    __shared__ float As[16][64];
    __shared__ float Bs[16][68];   // +4 pad keeps float4 alignment, avoids conflicts

    const int tid = threadIdx.x;
    const int m0 = blockIdx.x * 64;
    const int n0 = blockIdx.y * 64;

    const int ty = tid / 16, tx = tid % 16;

    const int a_row = tid >> 2;            // 0..63
    const int a_c4  = (tid & 3) * 4;       // 0,4,8,12
    const int b_row = tid >> 4;            // 0..15
    const int b_c4  = (tid & 15) * 4;      // 0..60

    float acc[4][4];
#pragma unroll
    for (int i = 0; i < 4; i++)
#pragma unroll
        for (int j = 0; j < 4; j++) acc[i][j] = 0.f;

    for (int k0 = 0; k0 < K; k0 += 16) {
        float4 av = *(const float4*)&A[(m0 + a_row) * K + k0 + a_c4];
        As[a_c4 + 0][a_row] = av.x;
        As[a_c4 + 1][a_row] = av.y;
        As[a_c4 + 2][a_row] = av.z;
        As[a_c4 + 3][a_row] = av.w;
        *(float4*)&Bs[b_row][b_c4] =
            *(const float4*)&W[(k0 + b_row) * N + n0 + b_c4];
        __syncthreads();

#pragma unroll
        for (int kk = 0; kk < 16; kk++) {
            float4 af = *(const float4*)&As[kk][ty * 4];
            float4 bf = *(const float4*)&Bs[kk][tx * 4];
            float a[4] = {af.x, af.y, af.z, af.w};
            float b[4] = {bf.x, bf.y, bf.z, bf.w};
#pragma unroll
            for (int i = 0; i < 4; i++)
#pragma unroll
                for (int j = 0; j < 4; j++)
                    acc[i][j] = fmaf(a[i], b[j], acc[i][j]);
        }
        __syncthreads();
    }

#pragma unroll
    for (int i = 0; i < 4; i++) {
        int m = m0 + ty * 4 + i;
#pragma unroll
        for (int j = 0; j < 4; j++) {
            int n = n0 + tx * 4 + j;
            C[m * N + n] = acc[i][j] + bias[n];
        }
    }
}

// ---------------------------------------------------------------------------
// Causal flash attention. One thread = one query row. Block = 128 q rows for
// one (b, h). K/V tiles of 64 rows staged in static smem (32 KB).
// Online softmax with lazy rescale (only when running max increases).
// ---------------------------------------------------------------------------
__global__ __launch_bounds__(128) void attn_kernel(
    const float* __restrict__ Qg, const float* __restrict__ Kg,
    const float* __restrict__ Vg, float* __restrict__ ctx)
{
    __shared__ float Ks[64][64];
    __shared__ float Vs[64][64];

    const int tid = threadIdx.x;
    const int qt  = blockIdx.x;          // 0..15 (q tiles of 128)
    const int bh  = blockIdx.y;          // 0..31
    const int b   = bh >> 4, h = bh & 15;
    const int sq  = qt * 128 + tid;
    const float scale = 0.125f;          // 1/sqrt(64)

    float q[DH];
    const float* qp = &Qg[(size_t)(b * SEQ + sq) * D + h * DH];
#pragma unroll
    for (int d = 0; d < DH; d++) q[d] = qp[d] * scale;

    float m = -1e30f, l = 0.f;
    float acc[DH];
#pragma unroll
    for (int d = 0; d < DH; d++) acc[d] = 0.f;

    const int nkt = 2 * qt + 2;          // 64-row key tiles covering 0..(qt+1)*128-1
    for (int kt = 0; kt < nkt; kt++) {
        const size_t base = (size_t)(b * SEQ + kt * 64) * D + h * DH;
        // 64 rows x 16 float4 per matrix = 1024 float4 each; 8 per thread
        for (int i = tid; i < 1024; i += 128) {
            int r = i >> 4, c = (i & 15) * 4;
            *(float4*)&Ks[r][c] = *(const float4*)&Kg[base + (size_t)r * D + c];
            *(float4*)&Vs[r][c] = *(const float4*)&Vg[base + (size_t)r * D + c];
        }
        __syncthreads();

        const int jmax = min(64, sq - kt * 64 + 1);  // causal bound
        for (int j = 0; j < jmax; j++) {
            float s = 0.f;
#pragma unroll
            for (int d = 0; d < DH; d++) s = fmaf(q[d], Ks[j][d], s);
            if (s > m) {
                float c = __expf(m - s);
                l *= c;
#pragma unroll
                for (int d = 0; d < DH; d++) acc[d] *= c;
                m = s;
            }
            float p = __expf(s - m);
            l += p;
#pragma unroll
            for (int d = 0; d < DH; d++) acc[d] = fmaf(p, Vs[j][d], acc[d]);
        }
        __syncthreads();
    }

    const float inv = 1.f / l;
    float* op = &ctx[(size_t)(b * SEQ + sq) * D + h * DH];
#pragma unroll
    for (int d = 0; d < DH; d++) op[d] = acc[d] * inv;
}

// ---------------------------------------------------------------------------
// Launch
// ---------------------------------------------------------------------------
extern "C" void kernel_launch(void* const* d_in, const int* in_sizes, int n_in,
                              void* d_out, int out_size)
{
    const float* x  = (const float*)d_in[0];
    const float* Wq = (const float*)d_in[1];
    const float* bq = (const float*)d_in[2];
    const float* Wk = (const float*)d_in[3];
    const float* bk = (const float*)d_in[4];
    const float* Wv = (const float*)d_in[5];
    const float* bv = (const float*)d_in[6];
    const float* Wo = (const float*)d_in[7];
    const float* bo = (const float*)d_in[8];
    float* out = (float*)d_out;

    float *Qp, *Kp, *Vp, *Cp;
    cudaGetSymbolAddress((void**)&Qp, g_Q);
    cudaGetSymbolAddress((void**)&Kp, g_K);
    cudaGetSymbolAddress((void**)&Vp, g_V);
    cudaGetSymbolAddress((void**)&Cp, g_ctx);

    dim3 gg(M_TOT / 64, D / 64);
    gemm_bias_kernel<<<gg, 256>>>(x, Wq, bq, Qp, M_TOT, D, D);
    gemm_bias_kernel<<<gg, 256>>>(x, Wk, bk, Kp, M_TOT, D, D);
    gemm_bias_kernel<<<gg, 256>>>(x, Wv, bv, Vp, M_TOT, D, D);

    dim3 ga(SEQ / 128, NB * NH);
    attn_kernel<<<ga, 128>>>(Qp, Kp, Vp, Cp);

    gemm_bias_kernel<<<gg, 256>>>(Cp, Wo, bo, out, M_TOT, D, D);
}

// round 3
// speedup vs baseline: 1.2650x; 1.2650x over previous
#include <cuda_runtime.h>

static constexpr int SEQ = 2048;
static constexpr int NB  = 2;
static constexpr int D   = 1024;
static constexpr int NH  = 16;
static constexpr int DH  = 64;
static constexpr int M_TOT = NB * SEQ; // 4096

// Scratch (allocation-free rule: __device__ globals)
__device__ float g_Q[M_TOT * D];
__device__ float g_K[M_TOT * D];
__device__ float g_V[M_TOT * D];
__device__ float g_ctx[M_TOT * D];

// ---------------- packed f32x2 helpers (sm_103a FFMA2) ----------------
typedef unsigned long long ull;

__device__ __forceinline__ ull pack2(float lo, float hi) {
    ull r; asm("mov.b64 %0,{%1,%2};" : "=l"(r) : "f"(lo), "f"(hi)); return r;
}
__device__ __forceinline__ void unpack2(ull v, float& lo, float& hi) {
    asm("mov.b64 {%0,%1},%2;" : "=f"(lo), "=f"(hi) : "l"(v));
}
__device__ __forceinline__ ull fma2(ull a, ull b, ull c) {
    ull d; asm("fma.rn.f32x2 %0,%1,%2,%3;" : "=l"(d) : "l"(a), "l"(b), "l"(c)); return d;
}
__device__ __forceinline__ ull mul2(ull a, ull b) {
    ull d; asm("mul.rn.f32x2 %0,%1,%2;" : "=l"(d) : "l"(a), "l"(b)); return d;
}

// ---------------------------------------------------------------------------
// GEMM: C[M,N] = A[M,K] @ W[K,N] + bias. Tiles 128x128, BK=16, 256 threads,
// 8x8 micro-tile per thread computed with packed FFMA2 (4 ull accs per row).
// ---------------------------------------------------------------------------
__global__ __launch_bounds__(256, 2) void gemm_bias_kernel(
    const float* __restrict__ A, const float* __restrict__ W,
    const float* __restrict__ bias, float* __restrict__ C,
    int M, int K, int N)
{
    __shared__ float As[16][132];  // transposed A tile, padded
    __shared__ float Bs[16][132];

    const int tid = threadIdx.x;
    const int m0 = blockIdx.x * 128;
    const int n0 = blockIdx.y * 128;
    const int ty = tid / 16, tx = tid % 16;

    ull acc[8][4];
#pragma unroll
    for (int i = 0; i < 8; i++)
#pragma unroll
        for (int j = 0; j < 4; j++) acc[i][j] = 0ull;

    // A tile: 128 rows x 16 cols = 512 float4; B tile: 16 rows x 128 cols = 512 float4
    int a_row[2], a_c4[2], b_row[2], b_c4[2];
#pragma unroll
    for (int t = 0; t < 2; t++) {
        int idx = tid + t * 256;
        a_row[t] = idx >> 2;  a_c4[t] = (idx & 3) * 4;
        b_row[t] = idx >> 5;  b_c4[t] = (idx & 31) * 4;
    }

    float4 pa[2], pb[2];
#pragma unroll
    for (int t = 0; t < 2; t++) {
        pa[t] = *(const float4*)&A[(size_t)(m0 + a_row[t]) * K + a_c4[t]];
        pb[t] = *(const float4*)&W[(size_t)b_row[t] * N + n0 + b_c4[t]];
    }

    for (int k0 = 0; k0 < K; k0 += 16) {
        __syncthreads();
#pragma unroll
        for (int t = 0; t < 2; t++) {
            As[a_c4[t] + 0][a_row[t]] = pa[t].x;
            As[a_c4[t] + 1][a_row[t]] = pa[t].y;
            As[a_c4[t] + 2][a_row[t]] = pa[t].z;
            As[a_c4[t] + 3][a_row[t]] = pa[t].w;
            *(float4*)&Bs[b_row[t]][b_c4[t]] = pb[t];
        }
        __syncthreads();

        if (k0 + 16 < K) {
#pragma unroll
            for (int t = 0; t < 2; t++) {
                pa[t] = *(const float4*)&A[(size_t)(m0 + a_row[t]) * K + k0 + 16 + a_c4[t]];
                pb[t] = *(const float4*)&W[(size_t)(k0 + 16 + b_row[t]) * N + n0 + b_c4[t]];
            }
        }

#pragma unroll
        for (int kk = 0; kk < 16; kk++) {
            float4 a0 = *(const float4*)&As[kk][ty * 4];
            float4 a1 = *(const float4*)&As[kk][64 + ty * 4];
            float4 b0 = *(const float4*)&Bs[kk][tx * 4];
            float4 b1 = *(const float4*)&Bs[kk][64 + tx * 4];
            ull bb[4] = { pack2(b0.x, b0.y), pack2(b0.z, b0.w),
                          pack2(b1.x, b1.y), pack2(b1.z, b1.w) };
            float aa[8] = { a0.x, a0.y, a0.z, a0.w, a1.x, a1.y, a1.z, a1.w };
#pragma unroll
            for (int i = 0; i < 8; i++) {
                ull av = pack2(aa[i], aa[i]);
#pragma unroll
                for (int j = 0; j < 4; j++)
                    acc[i][j] = fma2(av, bb[j], acc[i][j]);
            }
        }
    }

    float4 bs0 = *(const float4*)&bias[n0 + tx * 4];
    float4 bs1 = *(const float4*)&bias[n0 + 64 + tx * 4];
#pragma unroll
    for (int i = 0; i < 8; i++) {
        int m = m0 + (i < 4 ? ty * 4 + i : 64 + ty * 4 + (i - 4));
        float4 v0, v1;
        unpack2(acc[i][0], v0.x, v0.y); unpack2(acc[i][1], v0.z, v0.w);
        unpack2(acc[i][2], v1.x, v1.y); unpack2(acc[i][3], v1.z, v1.w);
        v0.x += bs0.x; v0.y += bs0.y; v0.z += bs0.z; v0.w += bs0.w;
        v1.x += bs1.x; v1.y += bs1.y; v1.z += bs1.z; v1.w += bs1.w;
        *(float4*)&C[(size_t)m * N + n0 + tx * 4]      = v0;
        *(float4*)&C[(size_t)m * N + n0 + 64 + tx * 4] = v1;
    }
}

// ---------------------------------------------------------------------------
// Causal flash attention, one thread = one query row, packed FFMA2 inner loop.
// ---------------------------------------------------------------------------
__global__ __launch_bounds__(128) void attn_kernel(
    const float* __restrict__ Qg, const float* __restrict__ Kg,
    const float* __restrict__ Vg, float* __restrict__ ctx)
{
    __shared__ float Ks[64][64];
    __shared__ float Vs[64][64];

    const int tid = threadIdx.x;
    const int qt  = blockIdx.x;          // 0..15
    const int bh  = blockIdx.y;          // 0..31
    const int b   = bh >> 4, h = bh & 15;
    const int sq  = qt * 128 + tid;
    const float scale = 0.125f;          // 1/sqrt(64)

    ull q2[32];
    {
        const float* qp = &Qg[(size_t)(b * SEQ + sq) * D + h * DH];
#pragma unroll
        for (int d = 0; d < 16; d++) {
            float4 v = *(const float4*)&qp[d * 4];
            q2[d * 2 + 0] = pack2(v.x * scale, v.y * scale);
            q2[d * 2 + 1] = pack2(v.z * scale, v.w * scale);
        }
    }

    float m = -1e30f, l = 0.f;
    ull acc2[32];
#pragma unroll
    for (int d = 0; d < 32; d++) acc2[d] = 0ull;

    const int nkt = 2 * qt + 2;
    for (int kt = 0; kt < nkt; kt++) {
        const size_t base = (size_t)(b * SEQ + kt * 64) * D + h * DH;
        for (int i = tid; i < 1024; i += 128) {
            int r = i >> 4, c = (i & 15) * 4;
            *(float4*)&Ks[r][c] = *(const float4*)&Kg[base + (size_t)r * D + c];
            *(float4*)&Vs[r][c] = *(const float4*)&Vg[base + (size_t)r * D + c];
        }
        __syncthreads();

        const int jmax = min(64, sq - kt * 64 + 1);
#pragma unroll 2
        for (int j = 0; j < jmax; j++) {
            const ull* kr = (const ull*)&Ks[j][0];
            ull s0 = 0, s1 = 0, s2 = 0, s3 = 0;
#pragma unroll
            for (int d = 0; d < 32; d += 4) {
                s0 = fma2(q2[d + 0], kr[d + 0], s0);
                s1 = fma2(q2[d + 1], kr[d + 1], s1);
                s2 = fma2(q2[d + 2], kr[d + 2], s2);
                s3 = fma2(q2[d + 3], kr[d + 3], s3);
            }
            float x0, x1, y0, y1, z0, z1, w0, w1;
            unpack2(s0, x0, x1); unpack2(s1, y0, y1);
            unpack2(s2, z0, z1); unpack2(s3, w0, w1);
            float s = ((x0 + x1) + (y0 + y1)) + ((z0 + z1) + (w0 + w1));

            if (s > m) {
                float c = __expf(m - s);
                l *= c;
                ull cv = pack2(c, c);
#pragma unroll
                for (int d = 0; d < 32; d++) acc2[d] = mul2(cv, acc2[d]);
                m = s;
            }
            float p = __expf(s - m);
            l += p;
            ull pv = pack2(p, p);
            const ull* vr = (const ull*)&Vs[j][0];
#pragma unroll
            for (int d = 0; d < 32; d++) acc2[d] = fma2(pv, vr[d], acc2[d]);
        }
        __syncthreads();
    }

    const float inv = 1.f / l;
    float* op = &ctx[(size_t)(b * SEQ + sq) * D + h * DH];
#pragma unroll
    for (int d = 0; d < 16; d++) {
        float4 v;
        unpack2(acc2[d * 2 + 0], v.x, v.y);
        unpack2(acc2[d * 2 + 1], v.z, v.w);
        v.x *= inv; v.y *= inv; v.z *= inv; v.w *= inv;
        *(float4*)&op[d * 4] = v;
    }
}

// ---------------------------------------------------------------------------
// Launch
// ---------------------------------------------------------------------------
extern "C" void kernel_launch(void* const* d_in, const int* in_sizes, int n_in,
                              void* d_out, int out_size)
{
    const float* x  = (const float*)d_in[0];
    const float* Wq = (const float*)d_in[1];
    const float* bq = (const float*)d_in[2];
    const float* Wk = (const float*)d_in[3];
    const float* bk = (const float*)d_in[4];
    const float* Wv = (const float*)d_in[5];
    const float* bv = (const float*)d_in[6];
    const float* Wo = (const float*)d_in[7];
    const float* bo = (const float*)d_in[8];
    float* out = (float*)d_out;

    float *Qp, *Kp, *Vp, *Cp;
    cudaGetSymbolAddress((void**)&Qp, g_Q);
    cudaGetSymbolAddress((void**)&Kp, g_K);
    cudaGetSymbolAddress((void**)&Vp, g_V);
    cudaGetSymbolAddress((void**)&Cp, g_ctx);

    dim3 gg(M_TOT / 128, D / 128);
    gemm_bias_kernel<<<gg, 256>>>(x, Wq, bq, Qp, M_TOT, D, D);
    gemm_bias_kernel<<<gg, 256>>>(x, Wk, bk, Kp, M_TOT, D, D);
    gemm_bias_kernel<<<gg, 256>>>(x, Wv, bv, Vp, M_TOT, D, D);

    dim3 ga(SEQ / 128, NB * NH);
    attn_kernel<<<ga, 128>>>(Qp, Kp, Vp, Cp);

    gemm_bias_kernel<<<gg, 256>>>(Cp, Wo, bo, out, M_TOT, D, D);
}

// round 5
// speedup vs baseline: 1.5885x; 1.2557x over previous
#include <cuda_runtime.h>
#include <cuda_bf16.h>
#include <cstdint>

static constexpr int SEQ = 2048;
static constexpr int NB  = 2;
static constexpr int D   = 1024;
static constexpr int NH  = 16;
static constexpr int DH  = 64;
static constexpr int M_TOT = NB * SEQ; // 4096

// ---------------- scratch (__device__ globals; no allocs allowed) ----------
__device__ float g_Q[M_TOT * D];
__device__ float g_K[M_TOT * D];
__device__ float g_V[M_TOT * D];
__device__ float g_ctx[M_TOT * D];

__device__ __nv_bfloat16 g_ahi[M_TOT * D];   // x / ctx split (reused)
__device__ __nv_bfloat16 g_alo[M_TOT * D];
__device__ __nv_bfloat16 g_wh[4][D * D];     // transposed weight splits [N][K]
__device__ __nv_bfloat16 g_wl[4][D * D];

// ---------------- packed f32x2 helpers (sm_103a FFMA2) ----------------
typedef unsigned long long ull;

__device__ __forceinline__ ull pack2(float lo, float hi) {
    ull r; asm("mov.b64 %0,{%1,%2};" : "=l"(r) : "f"(lo), "f"(hi)); return r;
}
__device__ __forceinline__ void unpack2(ull v, float& lo, float& hi) {
    asm("mov.b64 {%0,%1},%2;" : "=f"(lo), "=f"(hi) : "l"(v));
}
__device__ __forceinline__ ull fma2(ull a, ull b, ull c) {
    ull d; asm("fma.rn.f32x2 %0,%1,%2,%3;" : "=l"(d) : "l"(a), "l"(b), "l"(c)); return d;
}
__device__ __forceinline__ ull mul2(ull a, ull b) {
    ull d; asm("mul.rn.f32x2 %0,%1,%2;" : "=l"(d) : "l"(a), "l"(b)); return d;
}

// ---------------- mma.sync / ldmatrix / cp.async helpers -------------------
__device__ __forceinline__ uint32_t smem_u32(const void* p) {
    uint32_t a;
    asm("{ .reg .u64 t; cvta.to.shared.u64 t, %1; cvt.u32.u64 %0, t; }" : "=r"(a) : "l"(p));
    return a;
}
__device__ __forceinline__ void ldsm_x4(uint32_t* r, uint32_t addr) {
    asm volatile("ldmatrix.sync.aligned.m8n8.x4.shared.b16 {%0,%1,%2,%3}, [%4];"
                 : "=r"(r[0]), "=r"(r[1]), "=r"(r[2]), "=r"(r[3]) : "r"(addr));
}
__device__ __forceinline__ void mma_bf16(float* d, const uint32_t* a, uint32_t b0, uint32_t b1) {
    asm volatile(
        "mma.sync.aligned.m16n8k16.row.col.f32.bf16.bf16.f32 "
        "{%0,%1,%2,%3},{%4,%5,%6,%7},{%8,%9},{%0,%1,%2,%3};"
        : "+f"(d[0]), "+f"(d[1]), "+f"(d[2]), "+f"(d[3])
        : "r"(a[0]), "r"(a[1]), "r"(a[2]), "r"(a[3]), "r"(b0), "r"(b1));
}
__device__ __forceinline__ void cp16(uint32_t dst, const void* src) {
    asm volatile("cp.async.cg.shared.global [%0], [%1], 16;" :: "r"(dst), "l"(src));
}
__device__ __forceinline__ void cp_commit() {
    asm volatile("cp.async.commit_group;" ::: "memory");
}
template <int N>
__device__ __forceinline__ void cp_wait() {
    asm volatile("cp.async.wait_group %0;" :: "n"(N) : "memory");
}

// ---------------------------------------------------------------------------
// Prep: split fp32 -> (bf16 hi, bf16 lo), elementwise.
// ---------------------------------------------------------------------------
__global__ __launch_bounds__(256) void split_kernel(
    const float* __restrict__ X, __nv_bfloat16* __restrict__ hi,
    __nv_bfloat16* __restrict__ lo, int n)
{
    int i = blockIdx.x * 1024 + threadIdx.x * 4;
    if (i + 3 < n) {
        float4 v = *(const float4*)&X[i];
        float vv[4] = {v.x, v.y, v.z, v.w};
        __nv_bfloat16 h[4], l[4];
#pragma unroll
        for (int j = 0; j < 4; j++) {
            h[j] = __float2bfloat16(vv[j]);
            l[j] = __float2bfloat16(vv[j] - __bfloat162float(h[j]));
        }
        *(__nv_bfloat162*)&hi[i]     = __nv_bfloat162(h[0], h[1]);
        *(__nv_bfloat162*)&hi[i + 2] = __nv_bfloat162(h[2], h[3]);
        *(__nv_bfloat162*)&lo[i]     = __nv_bfloat162(l[0], l[1]);
        *(__nv_bfloat162*)&lo[i + 2] = __nv_bfloat162(l[2], l[3]);
    }
}

// ---------------------------------------------------------------------------
// Prep: W[K][N] fp32 -> transposed bf16 splits Wt[N][K] (hi, lo).
// ---------------------------------------------------------------------------
__global__ __launch_bounds__(256) void splitT_kernel(
    const float* __restrict__ W, __nv_bfloat16* __restrict__ Thi,
    __nv_bfloat16* __restrict__ Tlo)
{
    __shared__ float t[32][33];
    const int n0 = blockIdx.x * 32, k0 = blockIdx.y * 32;
    const int tx = threadIdx.x, ty = threadIdx.y;
#pragma unroll
    for (int r = ty; r < 32; r += 8)
        t[r][tx] = W[(size_t)(k0 + r) * D + n0 + tx];
    __syncthreads();
#pragma unroll
    for (int r = ty; r < 32; r += 8) {
        float v = t[tx][r];                        // W[k0+tx][n0+r]
        __nv_bfloat16 h = __float2bfloat16(v);
        __nv_bfloat16 l = __float2bfloat16(v - __bfloat162float(h));
        Thi[(size_t)(n0 + r) * D + k0 + tx] = h;
        Tlo[(size_t)(n0 + r) * D + k0 + tx] = l;
    }
}

// ---------------------------------------------------------------------------
// Tensor-core GEMM via mma.sync bf16 split:
//   C[M,N] = A[M,K] @ B[N,K]^T + bias ;  D = Ahi*Bhi + Ahi*Blo + Alo*Bhi
// Block tile 128x128, 8 warps (4x2), warp tile 32x64, K-chunk 32,
// cp.async double-buffered smem. Row stride 80B -> conflict-free ldmatrix.
// ---------------------------------------------------------------------------
static constexpr int GK     = 1024;
static constexpr int BK     = 32;                  // k per chunk
static constexpr int NCHUNK = GK / BK;             // 32
static constexpr int RSTR   = 80;                  // bytes per smem row (32 bf16 + pad)
static constexpr int ARR_B  = 128 * RSTR;          // 10240 B per operand tile
static constexpr int STAGE_B = 4 * ARR_B;          // 40960 B per stage
static constexpr int GSMEM   = 2 * STAGE_B;        // 81920 B

__global__ __launch_bounds__(256) void gemm_tc(
    const __nv_bfloat16* __restrict__ Ahi, const __nv_bfloat16* __restrict__ Alo,
    const __nv_bfloat16* __restrict__ Bhi, const __nv_bfloat16* __restrict__ Blo,
    const float* __restrict__ bias, float* __restrict__ C)
{
    extern __shared__ __align__(128) char dsm[];
    const uint32_t sbase = smem_u32(dsm);

    const int tid  = threadIdx.x;
    const int wid  = tid >> 5, lane = tid & 31;
    const int m0 = blockIdx.x * 128;
    const int n0 = blockIdx.y * 128;
    const int wm = wid & 3;          // warp row block: 32*wm
    const int wn = wid >> 2;         // warp col block: 64*wn

    const char* srcs[4] = {(const char*)Ahi, (const char*)Alo,
                           (const char*)Bhi, (const char*)Blo};
    const int rowb[4] = {m0, m0, n0, n0};

    auto issue = [&](int chunk, int stage) {
#pragma unroll
        for (int t = 0; t < 8; t++) {
            int idx = tid + t * 256;
            int a = idx >> 9, rem = idx & 511, r = rem >> 2, q = rem & 3;
            uint32_t dst = sbase + stage * STAGE_B + a * ARR_B + r * RSTR + q * 16;
            const char* src = srcs[a] +
                ((size_t)(rowb[a] + r) * GK + chunk * BK) * 2 + q * 16;
            cp16(dst, src);
        }
        cp_commit();
    };

    float acc[2][8][4];
#pragma unroll
    for (int mi = 0; mi < 2; mi++)
#pragma unroll
        for (int nj = 0; nj < 8; nj++)
#pragma unroll
            for (int e = 0; e < 4; e++) acc[mi][nj][e] = 0.f;

    issue(0, 0);
    issue(1, 1);

    const int rA = lane & 15;
    const int half = (lane >> 4) * 16;   // 16B column-half select

    for (int c = 0; c < NCHUNK; c++) {
        if (c + 1 < NCHUNK) cp_wait<1>(); else cp_wait<0>();
        __syncthreads();

        const uint32_t sb = sbase + (c & 1) * STAGE_B;
#pragma unroll
        for (int s = 0; s < 2; s++) {
            const int ko = s * 32 + half;     // byte offset into 64B of k data
            uint32_t ah[2][4], al[2][4], bh[4][4], bl[4][4];
            uint32_t aAddr = sb + (wm * 32 + rA) * RSTR + ko;
            ldsm_x4(ah[0], aAddr);
            ldsm_x4(ah[1], aAddr + 16 * RSTR);
            ldsm_x4(al[0], aAddr + ARR_B);
            ldsm_x4(al[1], aAddr + ARR_B + 16 * RSTR);
            uint32_t bAddr = sb + 2 * ARR_B + (wn * 64 + rA) * RSTR + ko;
#pragma unroll
            for (int g = 0; g < 4; g++) {
                ldsm_x4(bh[g], bAddr + g * 16 * RSTR);
                ldsm_x4(bl[g], bAddr + ARR_B + g * 16 * RSTR);
            }
#pragma unroll
            for (int mi = 0; mi < 2; mi++)
#pragma unroll
                for (int nj = 0; nj < 8; nj++) {
                    const int g = nj >> 1, o = nj & 1;
                    mma_bf16(acc[mi][nj], ah[mi], bh[g][o], bh[g][o + 2]);
                    mma_bf16(acc[mi][nj], ah[mi], bl[g][o], bl[g][o + 2]);
                    mma_bf16(acc[mi][nj], al[mi], bh[g][o], bh[g][o + 2]);
                }
        }
        __syncthreads();
        if (c + 2 < NCHUNK) issue(c + 2, c & 1);
    }

    // ---- epilogue: bias add + store -------------------------------------
#pragma unroll
    for (int mi = 0; mi < 2; mi++) {
        const int row = m0 + wm * 32 + mi * 16 + (lane >> 2);
#pragma unroll
        for (int nj = 0; nj < 8; nj++) {
            const int col = n0 + wn * 64 + nj * 8 + (lane & 3) * 2;
            float2 bb = *(const float2*)&bias[col];
            float2 v0 = {acc[mi][nj][0] + bb.x, acc[mi][nj][1] + bb.y};
            float2 v1 = {acc[mi][nj][2] + bb.x, acc[mi][nj][3] + bb.y};
            *(float2*)&C[(size_t)row * D + col]       = v0;
            *(float2*)&C[(size_t)(row + 8) * D + col] = v1;
        }
    }
}

// ---------------------------------------------------------------------------
// Causal flash attention (FFMA2 version, unchanged).
// ---------------------------------------------------------------------------
__global__ __launch_bounds__(128) void attn_kernel(
    const float* __restrict__ Qg, const float* __restrict__ Kg,
    const float* __restrict__ Vg, float* __restrict__ ctx)
{
    __shared__ float Ks[64][64];
    __shared__ float Vs[64][64];

    const int tid = threadIdx.x;
    const int qt  = blockIdx.x;
    const int bh  = blockIdx.y;
    const int b   = bh >> 4, h = bh & 15;
    const int sq  = qt * 128 + tid;
    const float scale = 0.125f;

    ull q2[32];
    {
        const float* qp = &Qg[(size_t)(b * SEQ + sq) * D + h * DH];
#pragma unroll
        for (int d = 0; d < 16; d++) {
            float4 vv = *(const float4*)&qp[d * 4];
            q2[d * 2 + 0] = pack2(vv.x * scale, vv.y * scale);
            q2[d * 2 + 1] = pack2(vv.z * scale, vv.w * scale);
        }
    }

    float m = -1e30f, l = 0.f;
    ull acc2[32];
#pragma unroll
    for (int d = 0; d < 32; d++) acc2[d] = 0ull;

    const int nkt = 2 * qt + 2;
    for (int kt = 0; kt < nkt; kt++) {
        const size_t base = (size_t)(b * SEQ + kt * 64) * D + h * DH;
        for (int i = tid; i < 1024; i += 128) {
            int r = i >> 4, c = (i & 15) * 4;
            *(float4*)&Ks[r][c] = *(const float4*)&Kg[base + (size_t)r * D + c];
            *(float4*)&Vs[r][c] = *(const float4*)&Vg[base + (size_t)r * D + c];
        }
        __syncthreads();

        const int jmax = min(64, sq - kt * 64 + 1);
#pragma unroll 2
        for (int j = 0; j < jmax; j++) {
            const ull* kr = (const ull*)&Ks[j][0];
            ull s0 = 0, s1 = 0, s2 = 0, s3 = 0;
#pragma unroll
            for (int d = 0; d < 32; d += 4) {
                s0 = fma2(q2[d + 0], kr[d + 0], s0);
                s1 = fma2(q2[d + 1], kr[d + 1], s1);
                s2 = fma2(q2[d + 2], kr[d + 2], s2);
                s3 = fma2(q2[d + 3], kr[d + 3], s3);
            }
            float x0, x1, y0, y1, z0, z1, w0, w1;
            unpack2(s0, x0, x1); unpack2(s1, y0, y1);
            unpack2(s2, z0, z1); unpack2(s3, w0, w1);
            float s = ((x0 + x1) + (y0 + y1)) + ((z0 + z1) + (w0 + w1));

            if (s > m) {
                float cf = __expf(m - s);
                l *= cf;
                ull cv = pack2(cf, cf);
#pragma unroll
                for (int d = 0; d < 32; d++) acc2[d] = mul2(cv, acc2[d]);
                m = s;
            }
            float p = __expf(s - m);
            l += p;
            ull pv = pack2(p, p);
            const ull* vr = (const ull*)&Vs[j][0];
#pragma unroll
            for (int d = 0; d < 32; d++) acc2[d] = fma2(pv, vr[d], acc2[d]);
        }
        __syncthreads();
    }

    const float inv = 1.f / l;
    float* op = &ctx[(size_t)(b * SEQ + sq) * D + h * DH];
#pragma unroll
    for (int d = 0; d < 16; d++) {
        float4 vv;
        unpack2(acc2[d * 2 + 0], vv.x, vv.y);
        unpack2(acc2[d * 2 + 1], vv.z, vv.w);
        vv.x *= inv; vv.y *= inv; vv.z *= inv; vv.w *= inv;
        *(float4*)&op[d * 4] = vv;
    }
}

// ---------------------------------------------------------------------------
// Launch
// ---------------------------------------------------------------------------
extern "C" void kernel_launch(void* const* d_in, const int* in_sizes, int n_in,
                              void* d_out, int out_size)
{
    const float* x  = (const float*)d_in[0];
    const float* Wq = (const float*)d_in[1];
    const float* bq = (const float*)d_in[2];
    const float* Wk = (const float*)d_in[3];
    const float* bk = (const float*)d_in[4];
    const float* Wv = (const float*)d_in[5];
    const float* bv = (const float*)d_in[6];
    const float* Wo = (const float*)d_in[7];
    const float* bo = (const float*)d_in[8];
    float* out = (float*)d_out;

    float *Qp, *Kp, *Vp, *Cp;
    cudaGetSymbolAddress((void**)&Qp, g_Q);
    cudaGetSymbolAddress((void**)&Kp, g_K);
    cudaGetSymbolAddress((void**)&Vp, g_V);
    cudaGetSymbolAddress((void**)&Cp, g_ctx);

    __nv_bfloat16 *ahi, *alo, *wh, *wl;
    cudaGetSymbolAddress((void**)&ahi, g_ahi);
    cudaGetSymbolAddress((void**)&alo, g_alo);
    cudaGetSymbolAddress((void**)&wh, g_wh);
    cudaGetSymbolAddress((void**)&wl, g_wl);

    cudaFuncSetAttribute(gemm_tc, cudaFuncAttributeMaxDynamicSharedMemorySize, GSMEM);

    const int NELEM = M_TOT * D;

    // 1) split x -> bf16 hi/lo
    split_kernel<<<NELEM / 1024, 256>>>(x, ahi, alo, NELEM);

    // 2) split+transpose weights
    dim3 tg(32, 32), tb(32, 8);
    splitT_kernel<<<tg, tb>>>(Wq, wh + 0 * (size_t)D * D, wl + 0 * (size_t)D * D);
    splitT_kernel<<<tg, tb>>>(Wk, wh + 1 * (size_t)D * D, wl + 1 * (size_t)D * D);
    splitT_kernel<<<tg, tb>>>(Wv, wh + 2 * (size_t)D * D, wl + 2 * (size_t)D * D);
    splitT_kernel<<<tg, tb>>>(Wo, wh + 3 * (size_t)D * D, wl + 3 * (size_t)D * D);

    // 3) QKV projections (tensor cores)
    dim3 gg(M_TOT / 128, D / 128);
    gemm_tc<<<gg, 256, GSMEM>>>(ahi, alo, wh + 0 * (size_t)D * D, wl + 0 * (size_t)D * D, bq, Qp);
    gemm_tc<<<gg, 256, GSMEM>>>(ahi, alo, wh + 1 * (size_t)D * D, wl + 1 * (size_t)D * D, bk, Kp);
    gemm_tc<<<gg, 256, GSMEM>>>(ahi, alo, wh + 2 * (size_t)D * D, wl + 2 * (size_t)D * D, bv, Vp);

    // 4) attention
    dim3 ga(SEQ / 128, NB * NH);
    attn_kernel<<<ga, 128>>>(Qp, Kp, Vp, Cp);

    // 5) split ctx (reuse x split buffers), output projection
    split_kernel<<<NELEM / 1024, 256>>>(Cp, ahi, alo, NELEM);
    gemm_tc<<<gg, 256, GSMEM>>>(ahi, alo, wh + 3 * (size_t)D * D, wl + 3 * (size_t)D * D, bo, out);
}

// round 6
// speedup vs baseline: 2.9785x; 1.8751x over previous
#include <cuda_runtime.h>
#include <cuda_bf16.h>
#include <cstdint>

static constexpr int SEQ = 2048;
static constexpr int NB  = 2;
static constexpr int D   = 1024;
static constexpr int NH  = 16;
static constexpr int DH  = 64;
static constexpr int M_TOT = NB * SEQ; // 4096
static constexpr int NBH  = NB * NH;   // 32

// ---------------- scratch (__device__ globals; no allocs allowed) ----------
__device__ float g_Q[M_TOT * D];
__device__ float g_K[M_TOT * D];
__device__ float g_V[M_TOT * D];

__device__ __nv_bfloat16 g_ahi[M_TOT * D];   // GEMM A splits (x, then ctx)
__device__ __nv_bfloat16 g_alo[M_TOT * D];
__device__ __nv_bfloat16 g_wh[4][D * D];     // transposed weight splits [N][K]
__device__ __nv_bfloat16 g_wl[4][D * D];

// head-major attention operands: [bh][s][64] (Q,K) / [bh][64][s] (Vt)
static constexpr int HM = NBH * SEQ * DH;    // 4,194,304
__device__ __nv_bfloat16 g_Qh[HM], g_Ql[HM];
__device__ __nv_bfloat16 g_Kh[HM], g_Kl[HM];
__device__ __nv_bfloat16 g_Vth[HM], g_Vtl[HM];

// ---------------- mma.sync / ldmatrix / cp.async helpers -------------------
__device__ __forceinline__ uint32_t smem_u32(const void* p) {
    uint32_t a;
    asm("{ .reg .u64 t; cvta.to.shared.u64 t, %1; cvt.u32.u64 %0, t; }" : "=r"(a) : "l"(p));
    return a;
}
__device__ __forceinline__ void ldsm_x4(uint32_t* r, uint32_t addr) {
    asm volatile("ldmatrix.sync.aligned.m8n8.x4.shared.b16 {%0,%1,%2,%3}, [%4];"
                 : "=r"(r[0]), "=r"(r[1]), "=r"(r[2]), "=r"(r[3]) : "r"(addr));
}
__device__ __forceinline__ void mma_bf16(float* d, const uint32_t* a, uint32_t b0, uint32_t b1) {
    asm volatile(
        "mma.sync.aligned.m16n8k16.row.col.f32.bf16.bf16.f32 "
        "{%0,%1,%2,%3},{%4,%5,%6,%7},{%8,%9},{%0,%1,%2,%3};"
        : "+f"(d[0]), "+f"(d[1]), "+f"(d[2]), "+f"(d[3])
        : "r"(a[0]), "r"(a[1]), "r"(a[2]), "r"(a[3]), "r"(b0), "r"(b1));
}
__device__ __forceinline__ void cp16(uint32_t dst, const void* src) {
    asm volatile("cp.async.cg.shared.global [%0], [%1], 16;" :: "r"(dst), "l"(src));
}
__device__ __forceinline__ void cp_commit() {
    asm volatile("cp.async.commit_group;" ::: "memory");
}
template <int N>
__device__ __forceinline__ void cp_wait() {
    asm volatile("cp.async.wait_group %0;" :: "n"(N) : "memory");
}
// split (a,b) fp32 pair -> packed bf16x2 hi + residual-lo (lo half = a)
__device__ __forceinline__ void split_pair(float a, float b, uint32_t& hi, uint32_t& lo) {
    uint32_t h;
    asm("cvt.rn.bf16x2.f32 %0, %1, %2;" : "=r"(h) : "f"(b), "f"(a));
    __nv_bfloat162 hb = *(__nv_bfloat162*)&h;
    float ra = a - __bfloat162float(hb.x);
    float rb = b - __bfloat162float(hb.y);
    uint32_t l;
    asm("cvt.rn.bf16x2.f32 %0, %1, %2;" : "=r"(l) : "f"(rb), "f"(ra));
    hi = h; lo = l;
}

// ---------------------------------------------------------------------------
// Prep: split fp32 -> (bf16 hi, bf16 lo), elementwise (GEMM A layout).
// ---------------------------------------------------------------------------
__global__ __launch_bounds__(256) void split_kernel(
    const float* __restrict__ X, __nv_bfloat16* __restrict__ hi,
    __nv_bfloat16* __restrict__ lo, int n)
{
    int i = blockIdx.x * 1024 + threadIdx.x * 4;
    if (i + 3 < n) {
        float4 v = *(const float4*)&X[i];
        uint32_t h0, l0, h1, l1;
        split_pair(v.x, v.y, h0, l0);
        split_pair(v.z, v.w, h1, l1);
        *(uint2*)&hi[i] = make_uint2(h0, h1);
        *(uint2*)&lo[i] = make_uint2(l0, l1);
    }
}

// ---------------------------------------------------------------------------
// Prep: W[K][N] fp32 -> transposed bf16 splits Wt[N][K] (hi, lo).
// ---------------------------------------------------------------------------
__global__ __launch_bounds__(256) void splitT_kernel(
    const float* __restrict__ W, __nv_bfloat16* __restrict__ Thi,
    __nv_bfloat16* __restrict__ Tlo)
{
    __shared__ float t[32][33];
    const int n0 = blockIdx.x * 32, k0 = blockIdx.y * 32;
    const int tx = threadIdx.x, ty = threadIdx.y;
#pragma unroll
    for (int r = ty; r < 32; r += 8)
        t[r][tx] = W[(size_t)(k0 + r) * D + n0 + tx];
    __syncthreads();
#pragma unroll
    for (int r = ty; r < 32; r += 8) {
        float v = t[tx][r];
        __nv_bfloat16 h = __float2bfloat16(v);
        __nv_bfloat16 l = __float2bfloat16(v - __bfloat162float(h));
        Thi[(size_t)(n0 + r) * D + k0 + tx] = h;
        Tlo[(size_t)(n0 + r) * D + k0 + tx] = l;
    }
}

// ---------------------------------------------------------------------------
// Prep: head-major split. X[M][1024] -> out[bh][s][64] bf16 hi/lo (X * scale)
// ---------------------------------------------------------------------------
__global__ __launch_bounds__(256) void hm_split_kernel(
    const float* __restrict__ X, __nv_bfloat16* __restrict__ Oh,
    __nv_bfloat16* __restrict__ Ol, float scale)
{
    int id = blockIdx.x * 256 + threadIdx.x;     // 8B-unit index, 1M total
    int bh = id >> 15;
    int s  = (id >> 4) & 2047;
    int u  = id & 15;
    int b = bh >> 4, h = bh & 15;
    float4 v = *(const float4*)&X[(size_t)(b * SEQ + s) * D + h * DH + u * 4];
    uint32_t h0, l0, h1, l1;
    split_pair(v.x * scale, v.y * scale, h0, l0);
    split_pair(v.z * scale, v.w * scale, h1, l1);
    size_t o = (size_t)bh * (SEQ * DH) + s * DH + u * 4;
    *(uint2*)&Oh[o] = make_uint2(h0, h1);
    *(uint2*)&Ol[o] = make_uint2(l0, l1);
}

// ---------------------------------------------------------------------------
// Prep: V -> transposed head-major splits Vt[bh][dh][s].
// ---------------------------------------------------------------------------
__global__ __launch_bounds__(256) void vt_split_kernel(
    const float* __restrict__ V, __nv_bfloat16* __restrict__ Th,
    __nv_bfloat16* __restrict__ Tl)
{
    __shared__ float t[32][33];
    const int s0 = blockIdx.x * 32;
    const int d0 = blockIdx.y * 32;
    const int bh = blockIdx.z;
    const int b = bh >> 4, h = bh & 15;
    const int tx = threadIdx.x, ty = threadIdx.y;
#pragma unroll
    for (int r = ty; r < 32; r += 8)
        t[r][tx] = V[(size_t)(b * SEQ + s0 + r) * D + h * DH + d0 + tx];
    __syncthreads();
    size_t base = (size_t)bh * (DH * SEQ);
#pragma unroll
    for (int r = ty; r < 32; r += 8) {
        float v = t[tx][r];                 // V[s0+tx][d0+r]
        __nv_bfloat16 hh = __float2bfloat16(v);
        __nv_bfloat16 ll = __float2bfloat16(v - __bfloat162float(hh));
        Th[base + (size_t)(d0 + r) * SEQ + s0 + tx] = hh;
        Tl[base + (size_t)(d0 + r) * SEQ + s0 + tx] = ll;
    }
}

// ---------------------------------------------------------------------------
// Tensor-core GEMM via mma.sync bf16 split (passing round-5 version).
// ---------------------------------------------------------------------------
static constexpr int GK     = 1024;
static constexpr int BK     = 32;
static constexpr int NCHUNK = GK / BK;
static constexpr int RSTR   = 80;
static constexpr int ARR_B  = 128 * RSTR;
static constexpr int STAGE_B = 4 * ARR_B;
static constexpr int GSMEM   = 2 * STAGE_B;

__global__ __launch_bounds__(256) void gemm_tc(
    const __nv_bfloat16* __restrict__ Ahi, const __nv_bfloat16* __restrict__ Alo,
    const __nv_bfloat16* __restrict__ Bhi, const __nv_bfloat16* __restrict__ Blo,
    const float* __restrict__ bias, float* __restrict__ C)
{
    extern __shared__ __align__(128) char dsm[];
    const uint32_t sbase = smem_u32(dsm);

    const int tid  = threadIdx.x;
    const int wid  = tid >> 5, lane = tid & 31;
    const int m0 = blockIdx.x * 128;
    const int n0 = blockIdx.y * 128;
    const int wm = wid & 3;
    const int wn = wid >> 2;

    const char* srcs[4] = {(const char*)Ahi, (const char*)Alo,
                           (const char*)Bhi, (const char*)Blo};
    const int rowb[4] = {m0, m0, n0, n0};

    auto issue = [&](int chunk, int stage) {
#pragma unroll
        for (int t = 0; t < 8; t++) {
            int idx = tid + t * 256;
            int a = idx >> 9, rem = idx & 511, r = rem >> 2, q = rem & 3;
            uint32_t dst = sbase + stage * STAGE_B + a * ARR_B + r * RSTR + q * 16;
            const char* src = srcs[a] +
                ((size_t)(rowb[a] + r) * GK + chunk * BK) * 2 + q * 16;
            cp16(dst, src);
        }
        cp_commit();
    };

    float acc[2][8][4];
#pragma unroll
    for (int mi = 0; mi < 2; mi++)
#pragma unroll
        for (int nj = 0; nj < 8; nj++)
#pragma unroll
            for (int e = 0; e < 4; e++) acc[mi][nj][e] = 0.f;

    issue(0, 0);
    issue(1, 1);

    const int rA = lane & 15;
    const int half = (lane >> 4) * 16;

    for (int c = 0; c < NCHUNK; c++) {
        if (c + 1 < NCHUNK) cp_wait<1>(); else cp_wait<0>();
        __syncthreads();

        const uint32_t sb = sbase + (c & 1) * STAGE_B;
#pragma unroll
        for (int s = 0; s < 2; s++) {
            const int ko = s * 32 + half;
            uint32_t ah[2][4], al[2][4], bh[4][4], bl[4][4];
            uint32_t aAddr = sb + (wm * 32 + rA) * RSTR + ko;
            ldsm_x4(ah[0], aAddr);
            ldsm_x4(ah[1], aAddr + 16 * RSTR);
            ldsm_x4(al[0], aAddr + ARR_B);
            ldsm_x4(al[1], aAddr + ARR_B + 16 * RSTR);
            uint32_t bAddr = sb + 2 * ARR_B + (wn * 64 + rA) * RSTR + ko;
#pragma unroll
            for (int g = 0; g < 4; g++) {
                ldsm_x4(bh[g], bAddr + g * 16 * RSTR);
                ldsm_x4(bl[g], bAddr + ARR_B + g * 16 * RSTR);
            }
#pragma unroll
            for (int mi = 0; mi < 2; mi++)
#pragma unroll
                for (int nj = 0; nj < 8; nj++) {
                    const int g = nj >> 1, o = nj & 1;
                    mma_bf16(acc[mi][nj], ah[mi], bh[g][o], bh[g][o + 2]);
                    mma_bf16(acc[mi][nj], ah[mi], bl[g][o], bl[g][o + 2]);
                    mma_bf16(acc[mi][nj], al[mi], bh[g][o], bh[g][o + 2]);
                }
        }
        __syncthreads();
        if (c + 2 < NCHUNK) issue(c + 2, c & 1);
    }

#pragma unroll
    for (int mi = 0; mi < 2; mi++) {
        const int row = m0 + wm * 32 + mi * 16 + (lane >> 2);
#pragma unroll
        for (int nj = 0; nj < 8; nj++) {
            const int col = n0 + wn * 64 + nj * 8 + (lane & 3) * 2;
            float2 bb = *(const float2*)&bias[col];
            float2 v0 = {acc[mi][nj][0] + bb.x, acc[mi][nj][1] + bb.y};
            float2 v1 = {acc[mi][nj][2] + bb.x, acc[mi][nj][3] + bb.y};
            *(float2*)&C[(size_t)row * D + col]       = v0;
            *(float2*)&C[(size_t)(row + 8) * D + col] = v1;
        }
    }
}

// ---------------------------------------------------------------------------
// Tensor-core causal flash attention.
// Block = (b,h) x 128 q rows; 8 warps x 16 q rows. K/V tiles of 64 keys,
// cp.async double-buffered. bf16 split for S and PV (3 terms each).
// Writes ctx directly as bf16 hi/lo splits into the Wo-GEMM input buffers.
// ---------------------------------------------------------------------------
static constexpr int ARS  = 144;            // smem row stride (64 bf16 + pad)
static constexpr int AARR = 64 * ARS;       // 9216 B per 64-row array
static constexpr int ASTG = 4 * AARR;       // Khi,Klo,Vth,Vtl
static constexpr int ASMEM = 2 * ASTG;      // 73728 B

__global__ __launch_bounds__(256) void attn_tc(
    const __nv_bfloat16* __restrict__ Qh, const __nv_bfloat16* __restrict__ Ql,
    const __nv_bfloat16* __restrict__ Kh, const __nv_bfloat16* __restrict__ Kl,
    const __nv_bfloat16* __restrict__ Vth, const __nv_bfloat16* __restrict__ Vtl,
    __nv_bfloat16* __restrict__ Chi, __nv_bfloat16* __restrict__ Clo)
{
    extern __shared__ __align__(128) char dsm[];
    const uint32_t sb0 = smem_u32(dsm);

    const int tid = threadIdx.x;
    const int wid = tid >> 5, lane = tid & 31;
    const int qt  = (gridDim.x - 1) - blockIdx.x;    // heavy tiles first
    const int bh  = blockIdx.y;
    const size_t hB  = (size_t)bh * (SEQ * DH);      // Q/K base
    const size_t vB  = (size_t)bh * (DH * SEQ);      // Vt base
    const int rA = lane & 15;
    const int half = (lane >> 4) * 16;

    // ---- stage Q tile (hi->arrays 0-1, lo->arrays 2-3 of stage 0) ----
#pragma unroll
    for (int t = 0; t < 8; t++) {
        int idx = tid + t * 256;
        int a = idx >> 10, rem = idx & 1023, r = rem >> 3, sg = rem & 7;
        uint32_t dst = sb0 + a * (2 * AARR) + r * ARS + sg * 16;
        const __nv_bfloat16* src = (a ? Ql : Qh) + hB + (size_t)(qt * 128 + r) * DH + sg * 8;
        cp16(dst, src);
    }
    cp_commit();
    cp_wait<0>();
    __syncthreads();

    // ---- Q fragments (A operand), per warp 16 q rows ----
    uint32_t qh[4][4], ql[4][4];
    {
        uint32_t qAddrH = sb0 + (wid >> 2) * AARR + ((wid & 3) * 16 + rA) * ARS;
        uint32_t qAddrL = qAddrH + 2 * AARR;
#pragma unroll
        for (int kc = 0; kc < 4; kc++) {
            ldsm_x4(qh[kc], qAddrH + kc * 32 + half);
            ldsm_x4(ql[kc], qAddrL + kc * 32 + half);
        }
    }
    __syncthreads();

    float ctxa[8][4];
#pragma unroll
    for (int dj = 0; dj < 8; dj++)
#pragma unroll
        for (int e = 0; e < 4; e++) ctxa[dj][e] = 0.f;
    float m0 = -1e30f, m1 = -1e30f, l0 = 0.f, l1 = 0.f;

    const int nkt = 2 * qt + 2;
    auto issue = [&](int kt, int st) {
#pragma unroll
        for (int t = 0; t < 8; t++) {
            int idx = tid + t * 256;
            int a = idx >> 9, rem = idx & 511, r = rem >> 3, sg = rem & 7;
            uint32_t dst = sb0 + st * ASTG + a * AARR + r * ARS + sg * 16;
            const __nv_bfloat16* src;
            if (a == 0)      src = Kh  + hB + (size_t)(kt * 64 + r) * DH + sg * 8;
            else if (a == 1) src = Kl  + hB + (size_t)(kt * 64 + r) * DH + sg * 8;
            else if (a == 2) src = Vth + vB + (size_t)r * SEQ + kt * 64 + sg * 8;
            else             src = Vtl + vB + (size_t)r * SEQ + kt * 64 + sg * 8;
            cp16(dst, src);
        }
        cp_commit();
    };

    issue(0, 0);
    issue(1, 1);

    const int qmin = qt * 128 + wid * 16;
    const int q0r = qmin + (lane >> 2);
    const int q1r = q0r + 8;

    for (int kt = 0; kt < nkt; kt++) {
        if (kt + 1 < nkt) cp_wait<1>(); else cp_wait<0>();
        __syncthreads();

        const int ktb = kt * 64;
        const bool skip = (ktb > qmin + 15);
        if (!skip) {
            const uint32_t sk = sb0 + (kt & 1) * ASTG;
            float s[8][4];
#pragma unroll
            for (int nj = 0; nj < 8; nj++)
#pragma unroll
                for (int e = 0; e < 4; e++) s[nj][e] = 0.f;

            // ---- S = Q @ K^T (3-term split) ----
#pragma unroll
            for (int kc = 0; kc < 4; kc++) {
                uint32_t kbh[4][4], kbl[4][4];
#pragma unroll
                for (int g = 0; g < 4; g++) {
                    uint32_t ka = sk + (g * 16 + rA) * ARS + kc * 32 + half;
                    ldsm_x4(kbh[g], ka);
                    ldsm_x4(kbl[g], ka + AARR);
                }
#pragma unroll
                for (int nj = 0; nj < 8; nj++) {
                    const int g = nj >> 1, o = nj & 1;
                    mma_bf16(s[nj], qh[kc], kbh[g][o], kbh[g][o + 2]);
                    mma_bf16(s[nj], qh[kc], kbl[g][o], kbl[g][o + 2]);
                    mma_bf16(s[nj], ql[kc], kbh[g][o], kbh[g][o + 2]);
                }
            }

            // ---- causal mask (diagonal tiles only) ----
            if (ktb + 63 > qmin) {
#pragma unroll
                for (int nj = 0; nj < 8; nj++) {
                    int key = ktb + nj * 8 + ((lane & 3) << 1);
                    if (key     > q0r) s[nj][0] = -1e30f;
                    if (key + 1 > q0r) s[nj][1] = -1e30f;
                    if (key     > q1r) s[nj][2] = -1e30f;
                    if (key + 1 > q1r) s[nj][3] = -1e30f;
                }
            }

            // ---- online softmax ----
            float mx0 = -1e30f, mx1 = -1e30f;
#pragma unroll
            for (int nj = 0; nj < 8; nj++) {
                mx0 = fmaxf(mx0, fmaxf(s[nj][0], s[nj][1]));
                mx1 = fmaxf(mx1, fmaxf(s[nj][2], s[nj][3]));
            }
            mx0 = fmaxf(mx0, __shfl_xor_sync(0xFFFFFFFFu, mx0, 1));
            mx0 = fmaxf(mx0, __shfl_xor_sync(0xFFFFFFFFu, mx0, 2));
            mx1 = fmaxf(mx1, __shfl_xor_sync(0xFFFFFFFFu, mx1, 1));
            mx1 = fmaxf(mx1, __shfl_xor_sync(0xFFFFFFFFu, mx1, 2));
            float nm0 = fmaxf(m0, mx0), nm1 = fmaxf(m1, mx1);
            float f0 = __expf(m0 - nm0), f1 = __expf(m1 - nm1);
            m0 = nm0; m1 = nm1;

            float sum0 = 0.f, sum1 = 0.f;
#pragma unroll
            for (int nj = 0; nj < 8; nj++) {
                s[nj][0] = __expf(s[nj][0] - m0); sum0 += s[nj][0];
                s[nj][1] = __expf(s[nj][1] - m0); sum0 += s[nj][1];
                s[nj][2] = __expf(s[nj][2] - m1); sum1 += s[nj][2];
                s[nj][3] = __expf(s[nj][3] - m1); sum1 += s[nj][3];
            }
            sum0 += __shfl_xor_sync(0xFFFFFFFFu, sum0, 1);
            sum0 += __shfl_xor_sync(0xFFFFFFFFu, sum0, 2);
            sum1 += __shfl_xor_sync(0xFFFFFFFFu, sum1, 1);
            sum1 += __shfl_xor_sync(0xFFFFFFFFu, sum1, 2);
            l0 = l0 * f0 + sum0;
            l1 = l1 * f1 + sum1;
#pragma unroll
            for (int dj = 0; dj < 8; dj++) {
                ctxa[dj][0] *= f0; ctxa[dj][1] *= f0;
                ctxa[dj][2] *= f1; ctxa[dj][3] *= f1;
            }

            // ---- ctx += P @ V (3-term split) ----
#pragma unroll
            for (int kc = 0; kc < 4; kc++) {
                uint32_t pah[4], pal[4];
                split_pair(s[2 * kc][0],     s[2 * kc][1],     pah[0], pal[0]);
                split_pair(s[2 * kc][2],     s[2 * kc][3],     pah[1], pal[1]);
                split_pair(s[2 * kc + 1][0], s[2 * kc + 1][1], pah[2], pal[2]);
                split_pair(s[2 * kc + 1][2], s[2 * kc + 1][3], pah[3], pal[3]);

                uint32_t vh[4][4], vl[4][4];
#pragma unroll
                for (int g = 0; g < 4; g++) {
                    uint32_t va = sk + 2 * AARR + (g * 16 + rA) * ARS + kc * 32 + half;
                    ldsm_x4(vh[g], va);
                    ldsm_x4(vl[g], va + AARR);
                }
#pragma unroll
                for (int dj = 0; dj < 8; dj++) {
                    const int g = dj >> 1, o = dj & 1;
                    mma_bf16(ctxa[dj], pah, vh[g][o], vh[g][o + 2]);
                    mma_bf16(ctxa[dj], pah, vl[g][o], vl[g][o + 2]);
                    mma_bf16(ctxa[dj], pal, vh[g][o], vh[g][o + 2]);
                }
            }
        }
        __syncthreads();
        if (kt + 2 < nkt) issue(kt + 2, kt & 1);
    }

    // ---- normalize + write ctx as bf16 hi/lo splits (GEMM A layout) ----
    const float inv0 = 1.f / l0, inv1 = 1.f / l1;
    const int b = bh >> 4, h = bh & 15;
    const size_t row0 = (size_t)(b * SEQ + qt * 128 + wid * 16 + (lane >> 2));
#pragma unroll
    for (int dj = 0; dj < 8; dj++) {
        const int col = h * DH + dj * 8 + (lane & 3) * 2;
        uint32_t hh, ll;
        split_pair(ctxa[dj][0] * inv0, ctxa[dj][1] * inv0, hh, ll);
        *(uint32_t*)&Chi[row0 * D + col] = hh;
        *(uint32_t*)&Clo[row0 * D + col] = ll;
        split_pair(ctxa[dj][2] * inv1, ctxa[dj][3] * inv1, hh, ll);
        *(uint32_t*)&Chi[(row0 + 8) * D + col] = hh;
        *(uint32_t*)&Clo[(row0 + 8) * D + col] = ll;
    }
}

// ---------------------------------------------------------------------------
// Launch
// ---------------------------------------------------------------------------
extern "C" void kernel_launch(void* const* d_in, const int* in_sizes, int n_in,
                              void* d_out, int out_size)
{
    const float* x  = (const float*)d_in[0];
    const float* Wq = (const float*)d_in[1];
    const float* bq = (const float*)d_in[2];
    const float* Wk = (const float*)d_in[3];
    const float* bk = (const float*)d_in[4];
    const float* Wv = (const float*)d_in[5];
    const float* bv = (const float*)d_in[6];
    const float* Wo = (const float*)d_in[7];
    const float* bo = (const float*)d_in[8];
    float* out = (float*)d_out;

    float *Qp, *Kp, *Vp;
    cudaGetSymbolAddress((void**)&Qp, g_Q);
    cudaGetSymbolAddress((void**)&Kp, g_K);
    cudaGetSymbolAddress((void**)&Vp, g_V);

    __nv_bfloat16 *ahi, *alo, *wh, *wl;
    cudaGetSymbolAddress((void**)&ahi, g_ahi);
    cudaGetSymbolAddress((void**)&alo, g_alo);
    cudaGetSymbolAddress((void**)&wh, g_wh);
    cudaGetSymbolAddress((void**)&wl, g_wl);

    __nv_bfloat16 *qhp, *qlp, *khp, *klp, *vthp, *vtlp;
    cudaGetSymbolAddress((void**)&qhp, g_Qh);
    cudaGetSymbolAddress((void**)&qlp, g_Ql);
    cudaGetSymbolAddress((void**)&khp, g_Kh);
    cudaGetSymbolAddress((void**)&klp, g_Kl);
    cudaGetSymbolAddress((void**)&vthp, g_Vth);
    cudaGetSymbolAddress((void**)&vtlp, g_Vtl);

    cudaFuncSetAttribute(gemm_tc, cudaFuncAttributeMaxDynamicSharedMemorySize, GSMEM);
    cudaFuncSetAttribute(attn_tc, cudaFuncAttributeMaxDynamicSharedMemorySize, ASMEM);

    const int NELEM = M_TOT * D;

    // 1) split x -> bf16 hi/lo (GEMM A)
    split_kernel<<<NELEM / 1024, 256>>>(x, ahi, alo, NELEM);

    // 2) split+transpose weights
    dim3 tg(32, 32), tb(32, 8);
    splitT_kernel<<<tg, tb>>>(Wq, wh + 0 * (size_t)D * D, wl + 0 * (size_t)D * D);
    splitT_kernel<<<tg, tb>>>(Wk, wh + 1 * (size_t)D * D, wl + 1 * (size_t)D * D);
    splitT_kernel<<<tg, tb>>>(Wv, wh + 2 * (size_t)D * D, wl + 2 * (size_t)D * D);
    splitT_kernel<<<tg, tb>>>(Wo, wh + 3 * (size_t)D * D, wl + 3 * (size_t)D * D);

    // 3) QKV projections (tensor cores)
    dim3 gg(M_TOT / 128, D / 128);
    gemm_tc<<<gg, 256, GSMEM>>>(ahi, alo, wh + 0 * (size_t)D * D, wl + 0 * (size_t)D * D, bq, Qp);
    gemm_tc<<<gg, 256, GSMEM>>>(ahi, alo, wh + 1 * (size_t)D * D, wl + 1 * (size_t)D * D, bk, Kp);
    gemm_tc<<<gg, 256, GSMEM>>>(ahi, alo, wh + 2 * (size_t)D * D, wl + 2 * (size_t)D * D, bv, Vp);

    // 4) re-layout + split for attention
    hm_split_kernel<<<4096, 256>>>(Qp, qhp, qlp, 0.125f);
    hm_split_kernel<<<4096, 256>>>(Kp, khp, klp, 1.0f);
    dim3 vg(SEQ / 32, DH / 32, NBH);
    vt_split_kernel<<<vg, tb>>>(Vp, vthp, vtlp);

    // 5) tensor-core attention (writes ctx splits into ahi/alo)
    dim3 ga(SEQ / 128, NBH);
    attn_tc<<<ga, 256, ASMEM>>>(qhp, qlp, khp, klp, vthp, vtlp, ahi, alo);

    // 6) output projection
    gemm_tc<<<gg, 256, GSMEM>>>(ahi, alo, wh + 3 * (size_t)D * D, wl + 3 * (size_t)D * D, bo, out);
}

// round 10
// speedup vs baseline: 3.1171x; 1.0466x over previous
#include <cuda_runtime.h>
#include <cuda_bf16.h>
#include <cstdint>

static constexpr int SEQ = 2048;
static constexpr int NB  = 2;
static constexpr int D   = 1024;
static constexpr int NH  = 16;
static constexpr int DH  = 64;
static constexpr int M_TOT = NB * SEQ; // 4096
static constexpr int NBH  = NB * NH;   // 32

// ---------------- scratch (__device__ globals; no allocs allowed) ----------
__device__ float g_V[M_TOT * D];

__device__ __nv_bfloat16 g_ahi[M_TOT * D];   // GEMM A splits (x, then ctx)
__device__ __nv_bfloat16 g_alo[M_TOT * D];
__device__ __nv_bfloat16 g_wh[4][D * D];     // transposed weight splits [N][K]
__device__ __nv_bfloat16 g_wl[4][D * D];

// head-major attention operands: [bh][s][64] (Q,K) / [bh][64][s] (Vt)
static constexpr int HM = NBH * SEQ * DH;
__device__ __nv_bfloat16 g_Qh[HM], g_Ql[HM];
__device__ __nv_bfloat16 g_Kh[HM], g_Kl[HM];
__device__ __nv_bfloat16 g_Vth[HM], g_Vtl[HM];

// ---------------- mma.sync / ldmatrix / cp.async helpers -------------------
__device__ __forceinline__ uint32_t smem_u32(const void* p) {
    uint32_t a;
    asm("{ .reg .u64 t; cvta.to.shared.u64 t, %1; cvt.u32.u64 %0, t; }" : "=r"(a) : "l"(p));
    return a;
}
__device__ __forceinline__ void ldsm_x4(uint32_t* r, uint32_t addr) {
    asm volatile("ldmatrix.sync.aligned.m8n8.x4.shared.b16 {%0,%1,%2,%3}, [%4];"
                 : "=r"(r[0]), "=r"(r[1]), "=r"(r[2]), "=r"(r[3]) : "r"(addr));
}
__device__ __forceinline__ void mma_bf16(float* d, const uint32_t* a, uint32_t b0, uint32_t b1) {
    asm volatile(
        "mma.sync.aligned.m16n8k16.row.col.f32.bf16.bf16.f32 "
        "{%0,%1,%2,%3},{%4,%5,%6,%7},{%8,%9},{%0,%1,%2,%3};"
        : "+f"(d[0]), "+f"(d[1]), "+f"(d[2]), "+f"(d[3])
        : "r"(a[0]), "r"(a[1]), "r"(a[2]), "r"(a[3]), "r"(b0), "r"(b1));
}
__device__ __forceinline__ void cp16(uint32_t dst, const void* src) {
    asm volatile("cp.async.cg.shared.global [%0], [%1], 16;" :: "r"(dst), "l"(src));
}
__device__ __forceinline__ void cp_commit() {
    asm volatile("cp.async.commit_group;" ::: "memory");
}
template <int N>
__device__ __forceinline__ void cp_wait() {
    asm volatile("cp.async.wait_group %0;" :: "n"(N) : "memory");
}
// split (a,b) fp32 pair -> packed bf16x2 hi + residual-lo (lo half = a)
__device__ __forceinline__ void split_pair(float a, float b, uint32_t& hi, uint32_t& lo) {
    uint32_t h;
    asm("cvt.rn.bf16x2.f32 %0, %1, %2;" : "=r"(h) : "f"(b), "f"(a));
    __nv_bfloat162 hb = *(__nv_bfloat162*)&h;
    float ra = a - __bfloat162float(hb.x);
    float rb = b - __bfloat162float(hb.y);
    uint32_t l;
    asm("cvt.rn.bf16x2.f32 %0, %1, %2;" : "=r"(l) : "f"(rb), "f"(ra));
    hi = h; lo = l;
}

// ---------------------------------------------------------------------------
// Prep: split fp32 -> (bf16 hi, bf16 lo), elementwise (GEMM A layout).
// ---------------------------------------------------------------------------
__global__ __launch_bounds__(256) void split_kernel(
    const float* __restrict__ X, __nv_bfloat16* __restrict__ hi,
    __nv_bfloat16* __restrict__ lo, int n)
{
    int i = blockIdx.x * 1024 + threadIdx.x * 4;
    if (i + 3 < n) {
        float4 v = *(const float4*)&X[i];
        uint32_t h0, l0, h1, l1;
        split_pair(v.x, v.y, h0, l0);
        split_pair(v.z, v.w, h1, l1);
        *(uint2*)&hi[i] = make_uint2(h0, h1);
        *(uint2*)&lo[i] = make_uint2(l0, l1);
    }
}

// ---------------------------------------------------------------------------
// Prep: all 4 weights W[K][N] fp32 -> transposed bf16 splits Wt[N][K].
// grid.z selects the weight.
// ---------------------------------------------------------------------------
__global__ __launch_bounds__(256) void splitT_all(
    const float* __restrict__ W0, const float* __restrict__ W1,
    const float* __restrict__ W2, const float* __restrict__ W3,
    __nv_bfloat16* __restrict__ Thi, __nv_bfloat16* __restrict__ Tlo)
{
    __shared__ float t[32][33];
    const int z = blockIdx.z;
    const float* W = (z == 0) ? W0 : (z == 1) ? W1 : (z == 2) ? W2 : W3;
    __nv_bfloat16* oh = Thi + (size_t)z * D * D;
    __nv_bfloat16* ol = Tlo + (size_t)z * D * D;
    const int n0 = blockIdx.x * 32, k0 = blockIdx.y * 32;
    const int tx = threadIdx.x, ty = threadIdx.y;
#pragma unroll
    for (int r = ty; r < 32; r += 8)
        t[r][tx] = W[(size_t)(k0 + r) * D + n0 + tx];
    __syncthreads();
#pragma unroll
    for (int r = ty; r < 32; r += 8) {
        float v = t[tx][r];
        __nv_bfloat16 h = __float2bfloat16(v);
        __nv_bfloat16 l = __float2bfloat16(v - __bfloat162float(h));
        oh[(size_t)(n0 + r) * D + k0 + tx] = h;
        ol[(size_t)(n0 + r) * D + k0 + tx] = l;
    }
}

// ---------------------------------------------------------------------------
// Prep: V -> transposed head-major splits Vt[bh][dh][s].
// ---------------------------------------------------------------------------
__global__ __launch_bounds__(256) void vt_split_kernel(
    const float* __restrict__ V, __nv_bfloat16* __restrict__ Th,
    __nv_bfloat16* __restrict__ Tl)
{
    __shared__ float t[32][33];
    const int s0 = blockIdx.x * 32;
    const int d0 = blockIdx.y * 32;
    const int bh = blockIdx.z;
    const int b = bh >> 4, h = bh & 15;
    const int tx = threadIdx.x, ty = threadIdx.y;
#pragma unroll
    for (int r = ty; r < 32; r += 8)
        t[r][tx] = V[(size_t)(b * SEQ + s0 + r) * D + h * DH + d0 + tx];
    __syncthreads();
    size_t base = (size_t)bh * (DH * SEQ);
#pragma unroll
    for (int r = ty; r < 32; r += 8) {
        float v = t[tx][r];
        __nv_bfloat16 hh = __float2bfloat16(v);
        __nv_bfloat16 ll = __float2bfloat16(v - __bfloat162float(hh));
        Th[base + (size_t)(d0 + r) * SEQ + s0 + tx] = hh;
        Tl[base + (size_t)(d0 + r) * SEQ + s0 + tx] = ll;
    }
}

// ---------------------------------------------------------------------------
// GEMM mainloop (shared by qkv_gemm and gemm_tc). Computes acc[2][8][4] for
// warp tile 32x64 of a 128x128 block tile; bf16 split, cp.async 2-stage.
// ---------------------------------------------------------------------------
static constexpr int GK     = 1024;
static constexpr int BK     = 32;
static constexpr int NCHUNK = GK / BK;
static constexpr int RSTR   = 80;
static constexpr int ARR_B  = 128 * RSTR;
static constexpr int STAGE_B = 4 * ARR_B;
static constexpr int GSMEM   = 2 * STAGE_B;

struct GemmCore {
    uint32_t sbase;
    int tid, wid, lane, wm, wn, rA, half;
    const char* srcs[4];
    int rowb[4];

    __device__ __forceinline__ void init(uint32_t sb, int m0, int n0,
        const __nv_bfloat16* Ahi, const __nv_bfloat16* Alo,
        const __nv_bfloat16* Bhi, const __nv_bfloat16* Blo)
    {
        sbase = sb;
        tid = threadIdx.x; wid = tid >> 5; lane = tid & 31;
        wm = wid & 3; wn = wid >> 2;
        rA = lane & 15; half = (lane >> 4) * 16;
        srcs[0] = (const char*)Ahi; srcs[1] = (const char*)Alo;
        srcs[2] = (const char*)Bhi; srcs[3] = (const char*)Blo;
        rowb[0] = m0; rowb[1] = m0; rowb[2] = n0; rowb[3] = n0;
    }
    __device__ __forceinline__ void issue(int chunk, int stage) {
#pragma unroll
        for (int t = 0; t < 8; t++) {
            int idx = tid + t * 256;
            int a = idx >> 9, rem = idx & 511, r = rem >> 2, q = rem & 3;
            uint32_t dst = sbase + stage * STAGE_B + a * ARR_B + r * RSTR + q * 16;
            const char* src = srcs[a] +
                ((size_t)(rowb[a] + r) * GK + chunk * BK) * 2 + q * 16;
            cp16(dst, src);
        }
        cp_commit();
    }
    __device__ __forceinline__ void run(float acc[2][8][4]) {
#pragma unroll
        for (int mi = 0; mi < 2; mi++)
#pragma unroll
            for (int nj = 0; nj < 8; nj++)
#pragma unroll
                for (int e = 0; e < 4; e++) acc[mi][nj][e] = 0.f;

        issue(0, 0);
        issue(1, 1);

        for (int c = 0; c < NCHUNK; c++) {
            if (c + 1 < NCHUNK) cp_wait<1>(); else cp_wait<0>();
            __syncthreads();
            const uint32_t sb = sbase + (c & 1) * STAGE_B;
#pragma unroll
            for (int s = 0; s < 2; s++) {
                const int ko = s * 32 + half;
                uint32_t ah[2][4], al[2][4];
                uint32_t aAddr = sb + (wm * 32 + rA) * RSTR + ko;
                ldsm_x4(ah[0], aAddr);
                ldsm_x4(ah[1], aAddr + 16 * RSTR);
                ldsm_x4(al[0], aAddr + ARR_B);
                ldsm_x4(al[1], aAddr + ARR_B + 16 * RSTR);
                uint32_t bAddr = sb + 2 * ARR_B + (wn * 64 + rA) * RSTR + ko;
#pragma unroll
                for (int g = 0; g < 4; g++) {
                    uint32_t bh[4], bl[4];
                    ldsm_x4(bh, bAddr + g * 16 * RSTR);
                    ldsm_x4(bl, bAddr + ARR_B + g * 16 * RSTR);
#pragma unroll
                    for (int o = 0; o < 2; o++) {
                        const int nj = g * 2 + o;
#pragma unroll
                        for (int mi = 0; mi < 2; mi++) {
                            mma_bf16(acc[mi][nj], ah[mi], bh[o], bh[o + 2]);
                            mma_bf16(acc[mi][nj], ah[mi], bl[o], bl[o + 2]);
                            mma_bf16(acc[mi][nj], al[mi], bh[o], bh[o + 2]);
                        }
                    }
                }
            }
            __syncthreads();
            if (c + 2 < NCHUNK) issue(c + 2, c & 1);
        }
    }
};

// ---------------------------------------------------------------------------
// Fused QKV projection. grid (32, 24): blockIdx.y>>3 selects {Q,K,V}.
// Q/K epilogues write head-major bf16 hi/lo splits directly (Q pre-scaled);
// V epilogue writes fp32 (transposed split follows).
// ---------------------------------------------------------------------------
__global__ __launch_bounds__(256, 2) void qkv_gemm(
    const __nv_bfloat16* __restrict__ Ahi, const __nv_bfloat16* __restrict__ Alo,
    const __nv_bfloat16* __restrict__ Wh, const __nv_bfloat16* __restrict__ Wl,
    const float* __restrict__ bq, const float* __restrict__ bk,
    const float* __restrict__ bv,
    __nv_bfloat16* __restrict__ Qh, __nv_bfloat16* __restrict__ Ql,
    __nv_bfloat16* __restrict__ Kh, __nv_bfloat16* __restrict__ Kl,
    float* __restrict__ V)
{
    extern __shared__ __align__(128) char dsm[];
    const int which = blockIdx.y >> 3;           // 0=Q 1=K 2=V
    const int m0 = blockIdx.x * 128;
    const int n0 = (blockIdx.y & 7) * 128;
    const float* bias = (which == 0) ? bq : (which == 1) ? bk : bv;

    GemmCore core;
    core.init(smem_u32(dsm), m0, n0,
              Ahi, Alo, Wh + (size_t)which * D * D, Wl + (size_t)which * D * D);
    float acc[2][8][4];
    core.run(acc);

    const int lane = core.lane, wm = core.wm, wn = core.wn;
    const float scale = (which == 0) ? 0.125f : 1.0f;

#pragma unroll
    for (int mi = 0; mi < 2; mi++) {
        const int row = m0 + wm * 32 + mi * 16 + (lane >> 2);
#pragma unroll
        for (int nj = 0; nj < 8; nj++) {
            const int col = n0 + wn * 64 + nj * 8 + (lane & 3) * 2;
            float2 bb = *(const float2*)&bias[col];
            float v00 = acc[mi][nj][0] + bb.x, v01 = acc[mi][nj][1] + bb.y;
            float v10 = acc[mi][nj][2] + bb.x, v11 = acc[mi][nj][3] + bb.y;
            if (which == 2) {
                *(float2*)&V[(size_t)row * D + col]       = make_float2(v00, v01);
                *(float2*)&V[(size_t)(row + 8) * D + col] = make_float2(v10, v11);
            } else {
                __nv_bfloat16* OH = (which == 0) ? Qh : Kh;
                __nv_bfloat16* OL = (which == 0) ? Ql : Kl;
                const int bI = row >> 11, h = col >> 6, dd = col & 63;
#pragma unroll
                for (int rr = 0; rr < 2; rr++) {
                    const int s = (row + rr * 8) & 2047;
                    size_t o = ((size_t)(bI * NH + h) * SEQ + s) * DH + dd;
                    uint32_t hh, ll;
                    float a0 = (rr ? v10 : v00) * scale;
                    float a1 = (rr ? v11 : v01) * scale;
                    split_pair(a0, a1, hh, ll);
                    *(uint32_t*)&OH[o] = hh;
                    *(uint32_t*)&OL[o] = ll;
                }
            }
        }
    }
}

// ---------------------------------------------------------------------------
// Output-projection GEMM (fp32 out + bias).
// ---------------------------------------------------------------------------
__global__ __launch_bounds__(256, 2) void gemm_tc(
    const __nv_bfloat16* __restrict__ Ahi, const __nv_bfloat16* __restrict__ Alo,
    const __nv_bfloat16* __restrict__ Bhi, const __nv_bfloat16* __restrict__ Blo,
    const float* __restrict__ bias, float* __restrict__ C)
{
    extern __shared__ __align__(128) char dsm[];
    const int m0 = blockIdx.x * 128;
    const int n0 = blockIdx.y * 128;

    GemmCore core;
    core.init(smem_u32(dsm), m0, n0, Ahi, Alo, Bhi, Blo);
    float acc[2][8][4];
    core.run(acc);

    const int lane = core.lane, wm = core.wm, wn = core.wn;
#pragma unroll
    for (int mi = 0; mi < 2; mi++) {
        const int row = m0 + wm * 32 + mi * 16 + (lane >> 2);
#pragma unroll
        for (int nj = 0; nj < 8; nj++) {
            const int col = n0 + wn * 64 + nj * 8 + (lane & 3) * 2;
            float2 bb = *(const float2*)&bias[col];
            float2 v0 = {acc[mi][nj][0] + bb.x, acc[mi][nj][1] + bb.y};
            float2 v1 = {acc[mi][nj][2] + bb.x, acc[mi][nj][3] + bb.y};
            *(float2*)&C[(size_t)row * D + col]       = v0;
            *(float2*)&C[(size_t)(row + 8) * D + col] = v1;
        }
    }
}

// ---------------------------------------------------------------------------
// Tensor-core causal flash attention (round-6 passing version).
// ---------------------------------------------------------------------------
static constexpr int ARS  = 144;
static constexpr int AARR = 64 * ARS;
static constexpr int ASTG = 4 * AARR;
static constexpr int ASMEM = 2 * ASTG;

__global__ __launch_bounds__(256) void attn_tc(
    const __nv_bfloat16* __restrict__ Qh, const __nv_bfloat16* __restrict__ Ql,
    const __nv_bfloat16* __restrict__ Kh, const __nv_bfloat16* __restrict__ Kl,
    const __nv_bfloat16* __restrict__ Vth, const __nv_bfloat16* __restrict__ Vtl,
    __nv_bfloat16* __restrict__ Chi, __nv_bfloat16* __restrict__ Clo)
{
    extern __shared__ __align__(128) char dsm[];
    const uint32_t sb0 = smem_u32(dsm);

    const int tid = threadIdx.x;
    const int wid = tid >> 5, lane = tid & 31;
    const int qt  = (gridDim.x - 1) - blockIdx.x;
    const int bh  = blockIdx.y;
    const size_t hB  = (size_t)bh * (SEQ * DH);
    const size_t vB  = (size_t)bh * (DH * SEQ);
    const int rA = lane & 15;
    const int half = (lane >> 4) * 16;

#pragma unroll
    for (int t = 0; t < 8; t++) {
        int idx = tid + t * 256;
        int a = idx >> 10, rem = idx & 1023, r = rem >> 3, sg = rem & 7;
        uint32_t dst = sb0 + a * (2 * AARR) + r * ARS + sg * 16;
        const __nv_bfloat16* src = (a ? Ql : Qh) + hB + (size_t)(qt * 128 + r) * DH + sg * 8;
        cp16(dst, src);
    }
    cp_commit();
    cp_wait<0>();
    __syncthreads();

    uint32_t qh[4][4], ql[4][4];
    {
        uint32_t qAddrH = sb0 + (wid >> 2) * AARR + ((wid & 3) * 16 + rA) * ARS;
        uint32_t qAddrL = qAddrH + 2 * AARR;
#pragma unroll
        for (int kc = 0; kc < 4; kc++) {
            ldsm_x4(qh[kc], qAddrH + kc * 32 + half);
            ldsm_x4(ql[kc], qAddrL + kc * 32 + half);
        }
    }
    __syncthreads();

    float ctxa[8][4];
#pragma unroll
    for (int dj = 0; dj < 8; dj++)
#pragma unroll
        for (int e = 0; e < 4; e++) ctxa[dj][e] = 0.f;
    float m0 = -1e30f, m1 = -1e30f, l0 = 0.f, l1 = 0.f;

    const int nkt = 2 * qt + 2;
    auto issue = [&](int kt, int st) {
#pragma unroll
        for (int t = 0; t < 8; t++) {
            int idx = tid + t * 256;
            int a = idx >> 9, rem = idx & 511, r = rem >> 3, sg = rem & 7;
            uint32_t dst = sb0 + st * ASTG + a * AARR + r * ARS + sg * 16;
            const __nv_bfloat16* src;
            if (a == 0)      src = Kh  + hB + (size_t)(kt * 64 + r) * DH + sg * 8;
            else if (a == 1) src = Kl  + hB + (size_t)(kt * 64 + r) * DH + sg * 8;
            else if (a == 2) src = Vth + vB + (size_t)r * SEQ + kt * 64 + sg * 8;
            else             src = Vtl + vB + (size_t)r * SEQ + kt * 64 + sg * 8;
            cp16(dst, src);
        }
        cp_commit();
    };

    issue(0, 0);
    issue(1, 1);

    const int qmin = qt * 128 + wid * 16;
    const int q0r = qmin + (lane >> 2);
    const int q1r = q0r + 8;

    for (int kt = 0; kt < nkt; kt++) {
        if (kt + 1 < nkt) cp_wait<1>(); else cp_wait<0>();
        __syncthreads();

        const int ktb = kt * 64;
        const bool skip = (ktb > qmin + 15);
        if (!skip) {
            const uint32_t sk = sb0 + (kt & 1) * ASTG;
            float s[8][4];
#pragma unroll
            for (int nj = 0; nj < 8; nj++)
#pragma unroll
                for (int e = 0; e < 4; e++) s[nj][e] = 0.f;

#pragma unroll
            for (int kc = 0; kc < 4; kc++) {
                uint32_t kbh[4][4], kbl[4][4];
#pragma unroll
                for (int g = 0; g < 4; g++) {
                    uint32_t ka = sk + (g * 16 + rA) * ARS + kc * 32 + half;
                    ldsm_x4(kbh[g], ka);
                    ldsm_x4(kbl[g], ka + AARR);
                }
#pragma unroll
                for (int nj = 0; nj < 8; nj++) {
                    const int g = nj >> 1, o = nj & 1;
                    mma_bf16(s[nj], qh[kc], kbh[g][o], kbh[g][o + 2]);
                    mma_bf16(s[nj], qh[kc], kbl[g][o], kbl[g][o + 2]);
                    mma_bf16(s[nj], ql[kc], kbh[g][o], kbh[g][o + 2]);
                }
            }

            if (ktb + 63 > qmin) {
#pragma unroll
                for (int nj = 0; nj < 8; nj++) {
                    int key = ktb + nj * 8 + ((lane & 3) << 1);
                    if (key     > q0r) s[nj][0] = -1e30f;
                    if (key + 1 > q0r) s[nj][1] = -1e30f;
                    if (key     > q1r) s[nj][2] = -1e30f;
                    if (key + 1 > q1r) s[nj][3] = -1e30f;
                }
            }

            float mx0 = -1e30f, mx1 = -1e30f;
#pragma unroll
            for (int nj = 0; nj < 8; nj++) {
                mx0 = fmaxf(mx0, fmaxf(s[nj][0], s[nj][1]));
                mx1 = fmaxf(mx1, fmaxf(s[nj][2], s[nj][3]));
            }
            mx0 = fmaxf(mx0, __shfl_xor_sync(0xFFFFFFFFu, mx0, 1));
            mx0 = fmaxf(mx0, __shfl_xor_sync(0xFFFFFFFFu, mx0, 2));
            mx1 = fmaxf(mx1, __shfl_xor_sync(0xFFFFFFFFu, mx1, 1));
            mx1 = fmaxf(mx1, __shfl_xor_sync(0xFFFFFFFFu, mx1, 2));
            float nm0 = fmaxf(m0, mx0), nm1 = fmaxf(m1, mx1);
            float f0 = __expf(m0 - nm0), f1 = __expf(m1 - nm1);
            m0 = nm0; m1 = nm1;

            float sum0 = 0.f, sum1 = 0.f;
#pragma unroll
            for (int nj = 0; nj < 8; nj++) {
                s[nj][0] = __expf(s[nj][0] - m0); sum0 += s[nj][0];
                s[nj][1] = __expf(s[nj][1] - m0); sum0 += s[nj][1];
                s[nj][2] = __expf(s[nj][2] - m1); sum1 += s[nj][2];
                s[nj][3] = __expf(s[nj][3] - m1); sum1 += s[nj][3];
            }
            sum0 += __shfl_xor_sync(0xFFFFFFFFu, sum0, 1);
            sum0 += __shfl_xor_sync(0xFFFFFFFFu, sum0, 2);
            sum1 += __shfl_xor_sync(0xFFFFFFFFu, sum1, 1);
            sum1 += __shfl_xor_sync(0xFFFFFFFFu, sum1, 2);
            l0 = l0 * f0 + sum0;
            l1 = l1 * f1 + sum1;
#pragma unroll
            for (int dj = 0; dj < 8; dj++) {
                ctxa[dj][0] *= f0; ctxa[dj][1] *= f0;
                ctxa[dj][2] *= f1; ctxa[dj][3] *= f1;
            }

#pragma unroll
            for (int kc = 0; kc < 4; kc++) {
                uint32_t pah[4], pal[4];
                split_pair(s[2 * kc][0],     s[2 * kc][1],     pah[0], pal[0]);
                split_pair(s[2 * kc][2],     s[2 * kc][3],     pah[1], pal[1]);
                split_pair(s[2 * kc + 1][0], s[2 * kc + 1][1], pah[2], pal[2]);
                split_pair(s[2 * kc + 1][2], s[2 * kc + 1][3], pah[3], pal[3]);

                uint32_t vh[4][4], vl[4][4];
#pragma unroll
                for (int g = 0; g < 4; g++) {
                    uint32_t va = sk + 2 * AARR + (g * 16 + rA) * ARS + kc * 32 + half;
                    ldsm_x4(vh[g], va);
                    ldsm_x4(vl[g], va + AARR);
                }
#pragma unroll
                for (int dj = 0; dj < 8; dj++) {
                    const int g = dj >> 1, o = dj & 1;
                    mma_bf16(ctxa[dj], pah, vh[g][o], vh[g][o + 2]);
                    mma_bf16(ctxa[dj], pah, vl[g][o], vl[g][o + 2]);
                    mma_bf16(ctxa[dj], pal, vh[g][o], vh[g][o + 2]);
                }
            }
        }
        __syncthreads();
        if (kt + 2 < nkt) issue(kt + 2, kt & 1);
    }

    const float inv0 = 1.f / l0, inv1 = 1.f / l1;
    const int b = bh >> 4, h = bh & 15;
    const size_t row0 = (size_t)(b * SEQ + qt * 128 + wid * 16 + (lane >> 2));
#pragma unroll
    for (int dj = 0; dj < 8; dj++) {
        const int col = h * DH + dj * 8 + (lane & 3) * 2;
        uint32_t hh, ll;
        split_pair(ctxa[dj][0] * inv0, ctxa[dj][1] * inv0, hh, ll);
        *(uint32_t*)&Chi[row0 * D + col] = hh;
        *(uint32_t*)&Clo[row0 * D + col] = ll;
        split_pair(ctxa[dj][2] * inv1, ctxa[dj][3] * inv1, hh, ll);
        *(uint32_t*)&Chi[(row0 + 8) * D + col] = hh;
        *(uint32_t*)&Clo[(row0 + 8) * D + col] = ll;
    }
}

// ---------------------------------------------------------------------------
// Launch
// ---------------------------------------------------------------------------
extern "C" void kernel_launch(void* const* d_in, const int* in_sizes, int n_in,
                              void* d_out, int out_size)
{
    const float* x  = (const float*)d_in[0];
    const float* Wq = (const float*)d_in[1];
    const float* bq = (const float*)d_in[2];
    const float* Wk = (const float*)d_in[3];
    const float* bk = (const float*)d_in[4];
    const float* Wv = (const float*)d_in[5];
    const float* bv = (const float*)d_in[6];
    const float* Wo = (const float*)d_in[7];
    const float* bo = (const float*)d_in[8];
    float* out = (float*)d_out;

    float *Vp;
    cudaGetSymbolAddress((void**)&Vp, g_V);

    __nv_bfloat16 *ahi, *alo, *wh, *wl;
    cudaGetSymbolAddress((void**)&ahi, g_ahi);
    cudaGetSymbolAddress((void**)&alo, g_alo);
    cudaGetSymbolAddress((void**)&wh, g_wh);
    cudaGetSymbolAddress((void**)&wl, g_wl);

    __nv_bfloat16 *qhp, *qlp, *khp, *klp, *vthp, *vtlp;
    cudaGetSymbolAddress((void**)&qhp, g_Qh);
    cudaGetSymbolAddress((void**)&qlp, g_Ql);
    cudaGetSymbolAddress((void**)&khp, g_Kh);
    cudaGetSymbolAddress((void**)&klp, g_Kl);
    cudaGetSymbolAddress((void**)&vthp, g_Vth);
    cudaGetSymbolAddress((void**)&vtlp, g_Vtl);

    cudaFuncSetAttribute(qkv_gemm, cudaFuncAttributeMaxDynamicSharedMemorySize, GSMEM);
    cudaFuncSetAttribute(gemm_tc, cudaFuncAttributeMaxDynamicSharedMemorySize, GSMEM);
    cudaFuncSetAttribute(attn_tc, cudaFuncAttributeMaxDynamicSharedMemorySize, ASMEM);

    const int NELEM = M_TOT * D;

    // 1) split x -> bf16 hi/lo (GEMM A)
    split_kernel<<<NELEM / 1024, 256>>>(x, ahi, alo, NELEM);

    // 2) split+transpose all 4 weights (one launch)
    dim3 tg(32, 32, 4), tb(32, 8);
    splitT_all<<<tg, tb>>>(Wq, Wk, Wv, Wo, wh, wl);

    // 3) fused QKV projection (Q/K epilogues write head-major splits)
    dim3 gq(M_TOT / 128, 24);
    qkv_gemm<<<gq, 256, GSMEM>>>(ahi, alo, wh, wl, bq, bk, bv,
                                 qhp, qlp, khp, klp, Vp);

    // 4) V transpose+split
    dim3 vg(SEQ / 32, DH / 32, NBH);
    vt_split_kernel<<<vg, tb>>>(Vp, vthp, vtlp);

    // 5) tensor-core attention (writes ctx splits into ahi/alo)
    dim3 ga(SEQ / 128, NBH);
    attn_tc<<<ga, 256, ASMEM>>>(qhp, qlp, khp, klp, vthp, vtlp, ahi, alo);

    // 6) output projection
    gemm_tc<<<dim3(M_TOT / 128, D / 128), 256, GSMEM>>>(
        ahi, alo, wh + 3 * (size_t)D * D, wl + 3 * (size_t)D * D, bo, out);
}

// round 14
// speedup vs baseline: 3.3541x; 1.0760x over previous
#include <cuda_runtime.h>
#include <cuda_bf16.h>
#include <cuda_fp16.h>
#include <cstdint>

static constexpr int SEQ = 2048;
static constexpr int NB  = 2;
static constexpr int D   = 1024;
static constexpr int NH  = 16;
static constexpr int DH  = 64;
static constexpr int M_TOT = NB * SEQ; // 4096
static constexpr int NBH  = NB * NH;   // 32

// ---------------- scratch (__device__ globals; no allocs allowed) ----------
__device__ __nv_bfloat16 g_ahi[M_TOT * D];   // GEMM A splits (x, then ctx)
__device__ __nv_bfloat16 g_alo[M_TOT * D];
__device__ __nv_bfloat16 g_wh[4][D * D];     // transposed weight splits [N][K]
__device__ __nv_bfloat16 g_wl[4][D * D];

// head-major attention operands: [bh][s][64] (Q,K bf16) / [bh][64][s] (Vt fp16)
static constexpr int HM = NBH * SEQ * DH;
__device__ __nv_bfloat16 g_Qh[HM], g_Ql[HM];
__device__ __nv_bfloat16 g_Kh[HM], g_Kl[HM];
__device__ __half        g_Vth[HM], g_Vtl[HM];

// ---------------- mma.sync / ldmatrix / cp.async helpers -------------------
__device__ __forceinline__ uint32_t smem_u32(const void* p) {
    uint32_t a;
    asm("{ .reg .u64 t; cvta.to.shared.u64 t, %1; cvt.u32.u64 %0, t; }" : "=r"(a) : "l"(p));
    return a;
}
__device__ __forceinline__ void ldsm_x4(uint32_t* r, uint32_t addr) {
    asm volatile("ldmatrix.sync.aligned.m8n8.x4.shared.b16 {%0,%1,%2,%3}, [%4];"
                 : "=r"(r[0]), "=r"(r[1]), "=r"(r[2]), "=r"(r[3]) : "r"(addr));
}
__device__ __forceinline__ void mma_bf16(float* d, const uint32_t* a, uint32_t b0, uint32_t b1) {
    asm volatile(
        "mma.sync.aligned.m16n8k16.row.col.f32.bf16.bf16.f32 "
        "{%0,%1,%2,%3},{%4,%5,%6,%7},{%8,%9},{%0,%1,%2,%3};"
        : "+f"(d[0]), "+f"(d[1]), "+f"(d[2]), "+f"(d[3])
        : "r"(a[0]), "r"(a[1]), "r"(a[2]), "r"(a[3]), "r"(b0), "r"(b1));
}
__device__ __forceinline__ void mma_f16(float* d, const uint32_t* a, uint32_t b0, uint32_t b1) {
    asm volatile(
        "mma.sync.aligned.m16n8k16.row.col.f32.f16.f16.f32 "
        "{%0,%1,%2,%3},{%4,%5,%6,%7},{%8,%9},{%0,%1,%2,%3};"
        : "+f"(d[0]), "+f"(d[1]), "+f"(d[2]), "+f"(d[3])
        : "r"(a[0]), "r"(a[1]), "r"(a[2]), "r"(a[3]), "r"(b0), "r"(b1));
}
__device__ __forceinline__ void cp16(uint32_t dst, const void* src) {
    asm volatile("cp.async.cg.shared.global [%0], [%1], 16;" :: "r"(dst), "l"(src));
}
__device__ __forceinline__ void cp_commit() {
    asm volatile("cp.async.commit_group;" ::: "memory");
}
template <int N>
__device__ __forceinline__ void cp_wait() {
    asm volatile("cp.async.wait_group %0;" :: "n"(N) : "memory");
}
// split (a,b) fp32 pair -> packed bf16x2 hi + residual-lo (lo half = a)
__device__ __forceinline__ void split_pair(float a, float b, uint32_t& hi, uint32_t& lo) {
    uint32_t h;
    asm("cvt.rn.bf16x2.f32 %0, %1, %2;" : "=r"(h) : "f"(b), "f"(a));
    __nv_bfloat162 hb = *(__nv_bfloat162*)&h;
    float ra = a - __bfloat162float(hb.x);
    float rb = b - __bfloat162float(hb.y);
    uint32_t l;
    asm("cvt.rn.bf16x2.f32 %0, %1, %2;" : "=r"(l) : "f"(rb), "f"(ra));
    hi = h; lo = l;
}
__device__ __forceinline__ uint32_t pack_h2(float a, float b) {
    __half2 t = __floats2half2_rn(a, b);   // x = a (lower), y = b (upper)
    return *(uint32_t*)&t;
}

// ---------------------------------------------------------------------------
// Fused prep: blocks [0,4096): x fp32 -> bf16 hi/lo (GEMM A layout)
//             blocks [4096,8192): weight z transpose+split Wt[N][K]
// ---------------------------------------------------------------------------
__global__ __launch_bounds__(256) void prep_all(
    const float* __restrict__ X, __nv_bfloat16* __restrict__ hi,
    __nv_bfloat16* __restrict__ lo,
    const float* __restrict__ W0, const float* __restrict__ W1,
    const float* __restrict__ W2, const float* __restrict__ W3,
    __nv_bfloat16* __restrict__ Thi, __nv_bfloat16* __restrict__ Tlo)
{
    __shared__ float t[32][33];
    const int bx = blockIdx.x;
    const int tid = threadIdx.x;
    if (bx < 4096) {
        int i = bx * 1024 + tid * 4;
        float4 v = *(const float4*)&X[i];
        uint32_t h0, l0, h1, l1;
        split_pair(v.x, v.y, h0, l0);
        split_pair(v.z, v.w, h1, l1);
        *(uint2*)&hi[i] = make_uint2(h0, h1);
        *(uint2*)&lo[i] = make_uint2(l0, l1);
    } else {
        const int r0 = bx - 4096;
        const int z = r0 >> 10;
        const int rem = r0 & 1023;
        const float* W = (z == 0) ? W0 : (z == 1) ? W1 : (z == 2) ? W2 : W3;
        __nv_bfloat16* oh = Thi + (size_t)z * D * D;
        __nv_bfloat16* ol = Tlo + (size_t)z * D * D;
        const int n0 = (rem & 31) * 32, k0 = (rem >> 5) * 32;
        const int tx = tid & 31, ty = tid >> 5;
#pragma unroll
        for (int r = ty; r < 32; r += 8)
            t[r][tx] = W[(size_t)(k0 + r) * D + n0 + tx];
        __syncthreads();
#pragma unroll
        for (int r = ty; r < 32; r += 8) {
            float v = t[tx][r];
            __nv_bfloat16 h = __float2bfloat16(v);
            __nv_bfloat16 l = __float2bfloat16(v - __bfloat162float(h));
            oh[(size_t)(n0 + r) * D + k0 + tx] = h;
            ol[(size_t)(n0 + r) * D + k0 + tx] = l;
        }
    }
}

// ---------------------------------------------------------------------------
// GEMM mainloop (shared). 128x128 block, warp tile 32x64, BK=32, 2-stage.
// ---------------------------------------------------------------------------
static constexpr int GK     = 1024;
static constexpr int BK     = 32;
static constexpr int NCHUNK = GK / BK;
static constexpr int RSTR   = 80;
static constexpr int ARR_B  = 128 * RSTR;
static constexpr int STAGE_B = 4 * ARR_B;
static constexpr int GSMEM   = 2 * STAGE_B;      // 81920

struct GemmCore {
    uint32_t sbase;
    int tid, wid, lane, wm, wn, rA, half;
    const char* srcs[4];
    int rowb[4];

    __device__ __forceinline__ void init(uint32_t sb, int m0, int n0,
        const __nv_bfloat16* Ahi, const __nv_bfloat16* Alo,
        const __nv_bfloat16* Bhi, const __nv_bfloat16* Blo)
    {
        sbase = sb;
        tid = threadIdx.x; wid = tid >> 5; lane = tid & 31;
        wm = wid & 3; wn = wid >> 2;
        rA = lane & 15; half = (lane >> 4) * 16;
        srcs[0] = (const char*)Ahi; srcs[1] = (const char*)Alo;
        srcs[2] = (const char*)Bhi; srcs[3] = (const char*)Blo;
        rowb[0] = m0; rowb[1] = m0; rowb[2] = n0; rowb[3] = n0;
    }
    __device__ __forceinline__ void issue(int chunk, int stage) {
#pragma unroll
        for (int t = 0; t < 8; t++) {
            int idx = tid + t * 256;
            int a = idx >> 9, rem = idx & 511, r = rem >> 2, q = rem & 3;
            uint32_t dst = sbase + stage * STAGE_B + a * ARR_B + r * RSTR + q * 16;
            const char* src = srcs[a] +
                ((size_t)(rowb[a] + r) * GK + chunk * BK) * 2 + q * 16;
            cp16(dst, src);
        }
        cp_commit();
    }
    __device__ __forceinline__ void run(float acc[2][8][4]) {
#pragma unroll
        for (int mi = 0; mi < 2; mi++)
#pragma unroll
            for (int nj = 0; nj < 8; nj++)
#pragma unroll
                for (int e = 0; e < 4; e++) acc[mi][nj][e] = 0.f;

        issue(0, 0);
        issue(1, 1);

        for (int c = 0; c < NCHUNK; c++) {
            if (c + 1 < NCHUNK) cp_wait<1>(); else cp_wait<0>();
            __syncthreads();
            const uint32_t sb = sbase + (c & 1) * STAGE_B;
#pragma unroll
            for (int s = 0; s < 2; s++) {
                const int ko = s * 32 + half;
                uint32_t ah[2][4], al[2][4];
                uint32_t aAddr = sb + (wm * 32 + rA) * RSTR + ko;
                ldsm_x4(ah[0], aAddr);
                ldsm_x4(ah[1], aAddr + 16 * RSTR);
                ldsm_x4(al[0], aAddr + ARR_B);
                ldsm_x4(al[1], aAddr + ARR_B + 16 * RSTR);
                uint32_t bAddr = sb + 2 * ARR_B + (wn * 64 + rA) * RSTR + ko;
#pragma unroll
                for (int g = 0; g < 4; g++) {
                    uint32_t bh[4], bl[4];
                    ldsm_x4(bh, bAddr + g * 16 * RSTR);
                    ldsm_x4(bl, bAddr + ARR_B + g * 16 * RSTR);
#pragma unroll
                    for (int o = 0; o < 2; o++) {
                        const int nj = g * 2 + o;
#pragma unroll
                        for (int mi = 0; mi < 2; mi++) {
                            mma_bf16(acc[mi][nj], ah[mi], bh[o], bh[o + 2]);
                            mma_bf16(acc[mi][nj], ah[mi], bl[o], bl[o + 2]);
                            mma_bf16(acc[mi][nj], al[mi], bh[o], bh[o + 2]);
                        }
                    }
                }
            }
            __syncthreads();
            if (c + 2 < NCHUNK) issue(c + 2, c & 1);
        }
    }
};

// ---------------------------------------------------------------------------
// Fused QKV projection. grid (32, 24): blockIdx.y>>3 selects {Q,K,V}.
// Q/K epilogues write head-major bf16 hi/lo splits (Q pre-scaled).
// V epilogue: smem transpose -> fp16 hi/lo head-major Vt[bh][d][s].
// ---------------------------------------------------------------------------
static constexpr int VTP = 136;   // fp16 transpose pitch (elems)

__global__ __launch_bounds__(256, 2) void qkv_gemm(
    const __nv_bfloat16* __restrict__ Ahi, const __nv_bfloat16* __restrict__ Alo,
    const __nv_bfloat16* __restrict__ Wh, const __nv_bfloat16* __restrict__ Wl,
    const float* __restrict__ bq, const float* __restrict__ bk,
    const float* __restrict__ bv,
    __nv_bfloat16* __restrict__ Qh, __nv_bfloat16* __restrict__ Ql,
    __nv_bfloat16* __restrict__ Kh, __nv_bfloat16* __restrict__ Kl,
    __half* __restrict__ Vth, __half* __restrict__ Vtl)
{
    extern __shared__ __align__(128) char dsm[];
    const int which = blockIdx.y >> 3;           // 0=Q 1=K 2=V
    const int m0 = blockIdx.x * 128;
    const int n0 = (blockIdx.y & 7) * 128;
    const float* bias = (which == 0) ? bq : (which == 1) ? bk : bv;

    GemmCore core;
    core.init(smem_u32(dsm), m0, n0,
              Ahi, Alo, Wh + (size_t)which * D * D, Wl + (size_t)which * D * D);
    float acc[2][8][4];
    core.run(acc);

    const int tid = core.tid, lane = core.lane, wm = core.wm, wn = core.wn;

    if (which == 2) {
        // ---- V: transpose via smem, write fp16 hi/lo [bh][d][s] ----
        __half* SH = (__half*)dsm;
        __half* SL = SH + 128 * VTP;
#pragma unroll
        for (int mi = 0; mi < 2; mi++) {
            const int rl = wm * 32 + mi * 16 + (lane >> 2);
#pragma unroll
            for (int nj = 0; nj < 8; nj++) {
                const int cl = wn * 64 + nj * 8 + (lane & 3) * 2;
                float2 bb = *(const float2*)&bias[n0 + cl];
                float v[2][2] = {{acc[mi][nj][0] + bb.x, acc[mi][nj][1] + bb.y},
                                 {acc[mi][nj][2] + bb.x, acc[mi][nj][3] + bb.y}};
#pragma unroll
                for (int rr = 0; rr < 2; rr++)
#pragma unroll
                    for (int cc = 0; cc < 2; cc++) {
                        __half h = __float2half_rn(v[rr][cc]);
                        __half l = __float2half_rn(v[rr][cc] - __half2float(h));
                        int o = (cl + cc) * VTP + rl + rr * 8;
                        SH[o] = h; SL[o] = l;
                    }
            }
        }
        __syncthreads();
        // each thread copies one full column (128 rows = 16 uint4)
        const int a = tid >> 7, c = tid & 127;
        const __half* S = a ? SL : SH;
        const int n = n0 + c, hh = n >> 6, dd = n & 63;
        const int bI = m0 >> 11, s0 = m0 & 2047;
        __half* dst = (a ? Vtl : Vth) +
            ((size_t)(bI * NH + hh) * DH + dd) * SEQ + s0;
        const uint4* srow = (const uint4*)(S + (size_t)c * VTP);
#pragma unroll
        for (int i = 0; i < 16; i++) ((uint4*)dst)[i] = srow[i];
    } else {
        const float scale = (which == 0) ? 0.125f : 1.0f;
        __nv_bfloat16* OH = (which == 0) ? Qh : Kh;
        __nv_bfloat16* OL = (which == 0) ? Ql : Kl;
#pragma unroll
        for (int mi = 0; mi < 2; mi++) {
            const int row = m0 + wm * 32 + mi * 16 + (lane >> 2);
#pragma unroll
            for (int nj = 0; nj < 8; nj++) {
                const int col = n0 + wn * 64 + nj * 8 + (lane & 3) * 2;
                float2 bb = *(const float2*)&bias[col];
                float v00 = acc[mi][nj][0] + bb.x, v01 = acc[mi][nj][1] + bb.y;
                float v10 = acc[mi][nj][2] + bb.x, v11 = acc[mi][nj][3] + bb.y;
                const int bI = row >> 11, h = col >> 6, dd = col & 63;
#pragma unroll
                for (int rr = 0; rr < 2; rr++) {
                    const int s = (row + rr * 8) & 2047;
                    size_t o = ((size_t)(bI * NH + h) * SEQ + s) * DH + dd;
                    uint32_t hh, ll;
                    float a0 = (rr ? v10 : v00) * scale;
                    float a1 = (rr ? v11 : v01) * scale;
                    split_pair(a0, a1, hh, ll);
                    *(uint32_t*)&OH[o] = hh;
                    *(uint32_t*)&OL[o] = ll;
                }
            }
        }
    }
}

// ---------------------------------------------------------------------------
// Output-projection GEMM (fp32 out + bias).
// ---------------------------------------------------------------------------
__global__ __launch_bounds__(256, 2) void gemm_tc(
    const __nv_bfloat16* __restrict__ Ahi, const __nv_bfloat16* __restrict__ Alo,
    const __nv_bfloat16* __restrict__ Bhi, const __nv_bfloat16* __restrict__ Blo,
    const float* __restrict__ bias, float* __restrict__ C)
{
    extern __shared__ __align__(128) char dsm[];
    const int m0 = blockIdx.x * 128;
    const int n0 = blockIdx.y * 128;

    GemmCore core;
    core.init(smem_u32(dsm), m0, n0, Ahi, Alo, Bhi, Blo);
    float acc[2][8][4];
    core.run(acc);

    const int lane = core.lane, wm = core.wm, wn = core.wn;
#pragma unroll
    for (int mi = 0; mi < 2; mi++) {
        const int row = m0 + wm * 32 + mi * 16 + (lane >> 2);
#pragma unroll
        for (int nj = 0; nj < 8; nj++) {
            const int col = n0 + wn * 64 + nj * 8 + (lane & 3) * 2;
            float2 bb = *(const float2*)&bias[col];
            float2 v0 = {acc[mi][nj][0] + bb.x, acc[mi][nj][1] + bb.y};
            float2 v1 = {acc[mi][nj][2] + bb.x, acc[mi][nj][3] + bb.y};
            *(float2*)&C[(size_t)row * D + col]       = v0;
            *(float2*)&C[(size_t)(row + 8) * D + col] = v1;
        }
    }
}

// ---------------------------------------------------------------------------
// Tensor-core causal flash attention.
// S = QK^T: bf16 3-term split. PV: fp16 P (single) x fp16 V hi/lo (2 terms).
// ---------------------------------------------------------------------------
static constexpr int ARS  = 144;
static constexpr int AARR = 64 * ARS;
static constexpr int ASTG = 4 * AARR;
static constexpr int ASMEM = 2 * ASTG;

__global__ __launch_bounds__(256) void attn_tc(
    const __nv_bfloat16* __restrict__ Qh, const __nv_bfloat16* __restrict__ Ql,
    const __nv_bfloat16* __restrict__ Kh, const __nv_bfloat16* __restrict__ Kl,
    const __half* __restrict__ Vth, const __half* __restrict__ Vtl,
    __nv_bfloat16* __restrict__ Chi, __nv_bfloat16* __restrict__ Clo)
{
    extern __shared__ __align__(128) char dsm[];
    const uint32_t sb0 = smem_u32(dsm);

    const int tid = threadIdx.x;
    const int wid = tid >> 5, lane = tid & 31;
    const int qt  = (gridDim.x - 1) - blockIdx.x;
    const int bh  = blockIdx.y;
    const size_t hB  = (size_t)bh * (SEQ * DH);
    const size_t vB  = (size_t)bh * (DH * SEQ);
    const int rA = lane & 15;
    const int half = (lane >> 4) * 16;

#pragma unroll
    for (int t = 0; t < 8; t++) {
        int idx = tid + t * 256;
        int a = idx >> 10, rem = idx & 1023, r = rem >> 3, sg = rem & 7;
        uint32_t dst = sb0 + a * (2 * AARR) + r * ARS + sg * 16;
        const __nv_bfloat16* src = (a ? Ql : Qh) + hB + (size_t)(qt * 128 + r) * DH + sg * 8;
        cp16(dst, src);
    }
    cp_commit();
    cp_wait<0>();
    __syncthreads();

    uint32_t qh[4][4], ql[4][4];
    {
        uint32_t qAddrH = sb0 + (wid >> 2) * AARR + ((wid & 3) * 16 + rA) * ARS;
        uint32_t qAddrL = qAddrH + 2 * AARR;
#pragma unroll
        for (int kc = 0; kc < 4; kc++) {
            ldsm_x4(qh[kc], qAddrH + kc * 32 + half);
            ldsm_x4(ql[kc], qAddrL + kc * 32 + half);
        }
    }
    __syncthreads();

    float ctxa[8][4];
#pragma unroll
    for (int dj = 0; dj < 8; dj++)
#pragma unroll
        for (int e = 0; e < 4; e++) ctxa[dj][e] = 0.f;
    float m0 = -1e30f, m1 = -1e30f, l0 = 0.f, l1 = 0.f;

    const int nkt = 2 * qt + 2;
    auto issue = [&](int kt, int st) {
#pragma unroll
        for (int t = 0; t < 8; t++) {
            int idx = tid + t * 256;
            int a = idx >> 9, rem = idx & 511, r = rem >> 3, sg = rem & 7;
            uint32_t dst = sb0 + st * ASTG + a * AARR + r * ARS + sg * 16;
            const void* src;
            if (a == 0)      src = Kh  + hB + (size_t)(kt * 64 + r) * DH + sg * 8;
            else if (a == 1) src = Kl  + hB + (size_t)(kt * 64 + r) * DH + sg * 8;
            else if (a == 2) src = Vth + vB + (size_t)r * SEQ + kt * 64 + sg * 8;
            else             src = Vtl + vB + (size_t)r * SEQ + kt * 64 + sg * 8;
            cp16(dst, src);
        }
        cp_commit();
    };

    issue(0, 0);
    issue(1, 1);

    const int qmin = qt * 128 + wid * 16;
    const int q0r = qmin + (lane >> 2);
    const int q1r = q0r + 8;

    for (int kt = 0; kt < nkt; kt++) {
        if (kt + 1 < nkt) cp_wait<1>(); else cp_wait<0>();
        __syncthreads();

        const int ktb = kt * 64;
        const bool skip = (ktb > qmin + 15);
        if (!skip) {
            const uint32_t sk = sb0 + (kt & 1) * ASTG;
            float s[8][4];
#pragma unroll
            for (int nj = 0; nj < 8; nj++)
#pragma unroll
                for (int e = 0; e < 4; e++) s[nj][e] = 0.f;

#pragma unroll
            for (int kc = 0; kc < 4; kc++) {
                uint32_t kbh[4][4], kbl[4][4];
#pragma unroll
                for (int g = 0; g < 4; g++) {
                    uint32_t ka = sk + (g * 16 + rA) * ARS + kc * 32 + half;
                    ldsm_x4(kbh[g], ka);
                    ldsm_x4(kbl[g], ka + AARR);
                }
#pragma unroll
                for (int nj = 0; nj < 8; nj++) {
                    const int g = nj >> 1, o = nj & 1;
                    mma_bf16(s[nj], qh[kc], kbh[g][o], kbh[g][o + 2]);
                    mma_bf16(s[nj], qh[kc], kbl[g][o], kbl[g][o + 2]);
                    mma_bf16(s[nj], ql[kc], kbh[g][o], kbh[g][o + 2]);
                }
            }

            if (ktb + 63 > qmin) {
#pragma unroll
                for (int nj = 0; nj < 8; nj++) {
                    int key = ktb + nj * 8 + ((lane & 3) << 1);
                    if (key     > q0r) s[nj][0] = -1e30f;
                    if (key + 1 > q0r) s[nj][1] = -1e30f;
                    if (key     > q1r) s[nj][2] = -1e30f;
                    if (key + 1 > q1r) s[nj][3] = -1e30f;
                }
            }

            float mx0 = -1e30f, mx1 = -1e30f;
#pragma unroll
            for (int nj = 0; nj < 8; nj++) {
                mx0 = fmaxf(mx0, fmaxf(s[nj][0], s[nj][1]));
                mx1 = fmaxf(mx1, fmaxf(s[nj][2], s[nj][3]));
            }
            mx0 = fmaxf(mx0, __shfl_xor_sync(0xFFFFFFFFu, mx0, 1));
            mx0 = fmaxf(mx0, __shfl_xor_sync(0xFFFFFFFFu, mx0, 2));
            mx1 = fmaxf(mx1, __shfl_xor_sync(0xFFFFFFFFu, mx1, 1));
            mx1 = fmaxf(mx1, __shfl_xor_sync(0xFFFFFFFFu, mx1, 2));
            float nm0 = fmaxf(m0, mx0), nm1 = fmaxf(m1, mx1);
            float f0 = __expf(m0 - nm0), f1 = __expf(m1 - nm1);
            m0 = nm0; m1 = nm1;

            float sum0 = 0.f, sum1 = 0.f;
#pragma unroll
            for (int nj = 0; nj < 8; nj++) {
                s[nj][0] = __expf(s[nj][0] - m0); sum0 += s[nj][0];
                s[nj][1] = __expf(s[nj][1] - m0); sum0 += s[nj][1];
                s[nj][2] = __expf(s[nj][2] - m1); sum1 += s[nj][2];
                s[nj][3] = __expf(s[nj][3] - m1); sum1 += s[nj][3];
            }
            sum0 += __shfl_xor_sync(0xFFFFFFFFu, sum0, 1);
            sum0 += __shfl_xor_sync(0xFFFFFFFFu, sum0, 2);
            sum1 += __shfl_xor_sync(0xFFFFFFFFu, sum1, 1);
            sum1 += __shfl_xor_sync(0xFFFFFFFFu, sum1, 2);
            l0 = l0 * f0 + sum0;
            l1 = l1 * f1 + sum1;
#pragma unroll
            for (int dj = 0; dj < 8; dj++) {
                ctxa[dj][0] *= f0; ctxa[dj][1] *= f0;
                ctxa[dj][2] *= f1; ctxa[dj][3] *= f1;
            }

            // ---- ctx += P @ V : P single fp16, V fp16 hi+lo (2 terms) ----
#pragma unroll
            for (int kc = 0; kc < 4; kc++) {
                uint32_t ph[4];
                ph[0] = pack_h2(s[2 * kc][0],     s[2 * kc][1]);
                ph[1] = pack_h2(s[2 * kc][2],     s[2 * kc][3]);
                ph[2] = pack_h2(s[2 * kc + 1][0], s[2 * kc + 1][1]);
                ph[3] = pack_h2(s[2 * kc + 1][2], s[2 * kc + 1][3]);

                uint32_t vh[4][4], vl[4][4];
#pragma unroll
                for (int g = 0; g < 4; g++) {
                    uint32_t va = sk + 2 * AARR + (g * 16 + rA) * ARS + kc * 32 + half;
                    ldsm_x4(vh[g], va);
                    ldsm_x4(vl[g], va + AARR);
                }
#pragma unroll
                for (int dj = 0; dj < 8; dj++) {
                    const int g = dj >> 1, o = dj & 1;
                    mma_f16(ctxa[dj], ph, vh[g][o], vh[g][o + 2]);
                    mma_f16(ctxa[dj], ph, vl[g][o], vl[g][o + 2]);
                }
            }
        }
        __syncthreads();
        if (kt + 2 < nkt) issue(kt + 2, kt & 1);
    }

    const float inv0 = 1.f / l0, inv1 = 1.f / l1;
    const int b = bh >> 4, h = bh & 15;
    const size_t row0 = (size_t)(b * SEQ + qt * 128 + wid * 16 + (lane >> 2));
#pragma unroll
    for (int dj = 0; dj < 8; dj++) {
        const int col = h * DH + dj * 8 + (lane & 3) * 2;
        uint32_t hh, ll;
        split_pair(ctxa[dj][0] * inv0, ctxa[dj][1] * inv0, hh, ll);
        *(uint32_t*)&Chi[row0 * D + col] = hh;
        *(uint32_t*)&Clo[row0 * D + col] = ll;
        split_pair(ctxa[dj][2] * inv1, ctxa[dj][3] * inv1, hh, ll);
        *(uint32_t*)&Chi[(row0 + 8) * D + col] = hh;
        *(uint32_t*)&Clo[(row0 + 8) * D + col] = ll;
    }
}

// ---------------------------------------------------------------------------
// Launch
// ---------------------------------------------------------------------------
extern "C" void kernel_launch(void* const* d_in, const int* in_sizes, int n_in,
                              void* d_out, int out_size)
{
    const float* x  = (const float*)d_in[0];
    const float* Wq = (const float*)d_in[1];
    const float* bq = (const float*)d_in[2];
    const float* Wk = (const float*)d_in[3];
    const float* bk = (const float*)d_in[4];
    const float* Wv = (const float*)d_in[5];
    const float* bv = (const float*)d_in[6];
    const float* Wo = (const float*)d_in[7];
    const float* bo = (const float*)d_in[8];
    float* out = (float*)d_out;

    __nv_bfloat16 *ahi, *alo, *wh, *wl;
    cudaGetSymbolAddress((void**)&ahi, g_ahi);
    cudaGetSymbolAddress((void**)&alo, g_alo);
    cudaGetSymbolAddress((void**)&wh, g_wh);
    cudaGetSymbolAddress((void**)&wl, g_wl);

    __nv_bfloat16 *qhp, *qlp, *khp, *klp;
    __half *vthp, *vtlp;
    cudaGetSymbolAddress((void**)&qhp, g_Qh);
    cudaGetSymbolAddress((void**)&qlp, g_Ql);
    cudaGetSymbolAddress((void**)&khp, g_Kh);
    cudaGetSymbolAddress((void**)&klp, g_Kl);
    cudaGetSymbolAddress((void**)&vthp, g_Vth);
    cudaGetSymbolAddress((void**)&vtlp, g_Vtl);

    cudaFuncSetAttribute(qkv_gemm, cudaFuncAttributeMaxDynamicSharedMemorySize, GSMEM);
    cudaFuncSetAttribute(gemm_tc, cudaFuncAttributeMaxDynamicSharedMemorySize, GSMEM);
    cudaFuncSetAttribute(attn_tc, cudaFuncAttributeMaxDynamicSharedMemorySize, ASMEM);

    // 1) fused prep: x split + all 4 weight transposes (one launch)
    prep_all<<<8192, 256>>>(x, ahi, alo, Wq, Wk, Wv, Wo, wh, wl);

    // 2) fused QKV projection (Q/K head-major splits; V transposed fp16 splits)
    dim3 gq(M_TOT / 128, 24);
    qkv_gemm<<<gq, 256, GSMEM>>>(ahi, alo, wh, wl, bq, bk, bv,
                                 qhp, qlp, khp, klp, vthp, vtlp);

    // 3) tensor-core attention (writes ctx splits into ahi/alo)
    dim3 ga(SEQ / 128, NBH);
    attn_tc<<<ga, 256, ASMEM>>>(qhp, qlp, khp, klp, vthp, vtlp, ahi, alo);

    // 4) output projection
    gemm_tc<<<dim3(M_TOT / 128, D / 128), 256, GSMEM>>>(
        ahi, alo, wh + 3 * (size_t)D * D, wl + 3 * (size_t)D * D, bo, out);
}

// round 15
// speedup vs baseline: 3.5276x; 1.0517x over previous
#include <cuda_runtime.h>
#include <cuda_bf16.h>
#include <cuda_fp16.h>
#include <cstdint>

static constexpr int SEQ = 2048;
static constexpr int NB  = 2;
static constexpr int D   = 1024;
static constexpr int NH  = 16;
static constexpr int DH  = 64;
static constexpr int M_TOT = NB * SEQ; // 4096
static constexpr int NBH  = NB * NH;   // 32

// ---------------- scratch (__device__ globals; no allocs allowed) ----------
__device__ __nv_bfloat16 g_ahi[M_TOT * D];   // GEMM A splits (x, then ctx)
__device__ __nv_bfloat16 g_alo[M_TOT * D];
__device__ __nv_bfloat16 g_wh[4][D * D];     // transposed weight splits [N][K]
__device__ __nv_bfloat16 g_wl[4][D * D];

// head-major attention operands: [bh][s][64] (Q,K bf16) / [bh][64][s] (Vt fp16)
static constexpr int HM = NBH * SEQ * DH;
__device__ __nv_bfloat16 g_Qh[HM], g_Ql[HM];
__device__ __nv_bfloat16 g_Kh[HM], g_Kl[HM];
__device__ __half        g_Vth[HM], g_Vtl[HM];

// ---------------- mma.sync / ldmatrix / cp.async helpers -------------------
__device__ __forceinline__ uint32_t smem_u32(const void* p) {
    uint32_t a;
    asm("{ .reg .u64 t; cvta.to.shared.u64 t, %1; cvt.u32.u64 %0, t; }" : "=r"(a) : "l"(p));
    return a;
}
__device__ __forceinline__ void ldsm_x4(uint32_t* r, uint32_t addr) {
    asm volatile("ldmatrix.sync.aligned.m8n8.x4.shared.b16 {%0,%1,%2,%3}, [%4];"
                 : "=r"(r[0]), "=r"(r[1]), "=r"(r[2]), "=r"(r[3]) : "r"(addr));
}
__device__ __forceinline__ void mma_bf16(float* d, const uint32_t* a, uint32_t b0, uint32_t b1) {
    asm volatile(
        "mma.sync.aligned.m16n8k16.row.col.f32.bf16.bf16.f32 "
        "{%0,%1,%2,%3},{%4,%5,%6,%7},{%8,%9},{%0,%1,%2,%3};"
        : "+f"(d[0]), "+f"(d[1]), "+f"(d[2]), "+f"(d[3])
        : "r"(a[0]), "r"(a[1]), "r"(a[2]), "r"(a[3]), "r"(b0), "r"(b1));
}
__device__ __forceinline__ void mma_f16(float* d, const uint32_t* a, uint32_t b0, uint32_t b1) {
    asm volatile(
        "mma.sync.aligned.m16n8k16.row.col.f32.f16.f16.f32 "
        "{%0,%1,%2,%3},{%4,%5,%6,%7},{%8,%9},{%0,%1,%2,%3};"
        : "+f"(d[0]), "+f"(d[1]), "+f"(d[2]), "+f"(d[3])
        : "r"(a[0]), "r"(a[1]), "r"(a[2]), "r"(a[3]), "r"(b0), "r"(b1));
}
__device__ __forceinline__ void cp16(uint32_t dst, const void* src) {
    asm volatile("cp.async.cg.shared.global [%0], [%1], 16;" :: "r"(dst), "l"(src));
}
__device__ __forceinline__ void cp_commit() {
    asm volatile("cp.async.commit_group;" ::: "memory");
}
template <int N>
__device__ __forceinline__ void cp_wait() {
    asm volatile("cp.async.wait_group %0;" :: "n"(N) : "memory");
}
// split (a,b) fp32 pair -> packed bf16x2 hi + residual-lo (lo half = a)
__device__ __forceinline__ void split_pair(float a, float b, uint32_t& hi, uint32_t& lo) {
    uint32_t h;
    asm("cvt.rn.bf16x2.f32 %0, %1, %2;" : "=r"(h) : "f"(b), "f"(a));
    __nv_bfloat162 hb = *(__nv_bfloat162*)&h;
    float ra = a - __bfloat162float(hb.x);
    float rb = b - __bfloat162float(hb.y);
    uint32_t l;
    asm("cvt.rn.bf16x2.f32 %0, %1, %2;" : "=r"(l) : "f"(rb), "f"(ra));
    hi = h; lo = l;
}
__device__ __forceinline__ uint32_t pack_h2(float a, float b) {
    __half2 t = __floats2half2_rn(a, b);   // x = a (lower), y = b (upper)
    return *(uint32_t*)&t;
}

// ---------------------------------------------------------------------------
// Fused prep: blocks [0,4096): x fp32 -> bf16 hi/lo (GEMM A layout)
//             blocks [4096,8192): weight z transpose+split Wt[N][K]
// ---------------------------------------------------------------------------
__global__ __launch_bounds__(256) void prep_all(
    const float* __restrict__ X, __nv_bfloat16* __restrict__ hi,
    __nv_bfloat16* __restrict__ lo,
    const float* __restrict__ W0, const float* __restrict__ W1,
    const float* __restrict__ W2, const float* __restrict__ W3,
    __nv_bfloat16* __restrict__ Thi, __nv_bfloat16* __restrict__ Tlo)
{
    __shared__ float t[32][33];
    const int bx = blockIdx.x;
    const int tid = threadIdx.x;
    if (bx < 4096) {
        int i = bx * 1024 + tid * 4;
        float4 v = *(const float4*)&X[i];
        uint32_t h0, l0, h1, l1;
        split_pair(v.x, v.y, h0, l0);
        split_pair(v.z, v.w, h1, l1);
        *(uint2*)&hi[i] = make_uint2(h0, h1);
        *(uint2*)&lo[i] = make_uint2(l0, l1);
    } else {
        const int r0 = bx - 4096;
        const int z = r0 >> 10;
        const int rem = r0 & 1023;
        const float* W = (z == 0) ? W0 : (z == 1) ? W1 : (z == 2) ? W2 : W3;
        __nv_bfloat16* oh = Thi + (size_t)z * D * D;
        __nv_bfloat16* ol = Tlo + (size_t)z * D * D;
        const int n0 = (rem & 31) * 32, k0 = (rem >> 5) * 32;
        const int tx = tid & 31, ty = tid >> 5;
#pragma unroll
        for (int r = ty; r < 32; r += 8)
            t[r][tx] = W[(size_t)(k0 + r) * D + n0 + tx];
        __syncthreads();
#pragma unroll
        for (int r = ty; r < 32; r += 8) {
            float v = t[tx][r];
            __nv_bfloat16 h = __float2bfloat16(v);
            __nv_bfloat16 l = __float2bfloat16(v - __bfloat162float(h));
            oh[(size_t)(n0 + r) * D + k0 + tx] = h;
            ol[(size_t)(n0 + r) * D + k0 + tx] = l;
        }
    }
}

// ---------------------------------------------------------------------------
// GEMM mainloop (shared). 128x128 block, warp tile 32x64, BK=32.
// 3-stage cp.async pipeline, ONE barrier per chunk.
// Smem layout: paired-row XOR swizzle — K-rows 2r,2r+1 packed in one 128B
// line; 16B unit index (0..7) XOR'd with (line&7). Conflict-free for both
// cp.async writes and ldmatrix reads. 64B/row effective (no padding).
// ---------------------------------------------------------------------------
static constexpr int GK     = 1024;
static constexpr int BK     = 32;
static constexpr int NCHUNK = GK / BK;
static constexpr int ARR_B  = 64 * 128;          // 8192 B per operand tile
static constexpr int STAGE_B = 4 * ARR_B;        // 32768 B per stage
static constexpr int GSMEM   = 3 * STAGE_B;      // 98304 B

// smem byte offset of 16B unit u (0..3) of logical row m (0..127)
__device__ __forceinline__ uint32_t swz(int m, int u) {
    const int R = m >> 1;
    const int unit = ((m & 1) << 2) | u;
    return (uint32_t)(R * 128 + ((unit ^ (R & 7)) << 4));
}

struct GemmCore {
    uint32_t sbase;
    int tid, wid, lane, wm, wn, rA;
    const char* srcs[4];
    int rowb[4];

    __device__ __forceinline__ void init(uint32_t sb, int m0, int n0,
        const __nv_bfloat16* Ahi, const __nv_bfloat16* Alo,
        const __nv_bfloat16* Bhi, const __nv_bfloat16* Blo)
    {
        sbase = sb;
        tid = threadIdx.x; wid = tid >> 5; lane = tid & 31;
        wm = wid & 3; wn = wid >> 2;
        rA = lane & 15;
        srcs[0] = (const char*)Ahi; srcs[1] = (const char*)Alo;
        srcs[2] = (const char*)Bhi; srcs[3] = (const char*)Blo;
        rowb[0] = m0; rowb[1] = m0; rowb[2] = n0; rowb[3] = n0;
    }
    __device__ __forceinline__ void issue(int chunk, int stage) {
#pragma unroll
        for (int t = 0; t < 8; t++) {
            int idx = tid + t * 256;
            int a = idx >> 9, rem = idx & 511, r = rem >> 2, q = rem & 3;
            uint32_t dst = sbase + stage * STAGE_B + a * ARR_B + swz(r, q);
            const char* src = srcs[a] +
                ((size_t)(rowb[a] + r) * GK + chunk * BK) * 2 + q * 16;
            cp16(dst, src);
        }
        cp_commit();
    }
    __device__ __forceinline__ void run(float acc[2][8][4]) {
#pragma unroll
        for (int mi = 0; mi < 2; mi++)
#pragma unroll
            for (int nj = 0; nj < 8; nj++)
#pragma unroll
                for (int e = 0; e < 4; e++) acc[mi][nj][e] = 0.f;

        issue(0, 0);
        issue(1, 1);

        int stg = 0;
        for (int c = 0; c < NCHUNK; c++) {
            if (c + 1 < NCHUNK) cp_wait<1>(); else cp_wait<0>();
            __syncthreads();
            if (c + 2 < NCHUNK) {
                int nstg = stg + 2; if (nstg >= 3) nstg -= 3;
                issue(c + 2, nstg);
            }
            const uint32_t sb = sbase + stg * STAGE_B;
#pragma unroll
            for (int s = 0; s < 2; s++) {
                const int u = s * 2 + (lane >> 4);   // 16B k-unit 0..3
                uint32_t ah[2][4], al[2][4];
                {
                    const int m = wm * 32 + rA;
                    uint32_t a0 = sb + swz(m, u);
                    uint32_t a1 = sb + swz(m + 16, u);
                    ldsm_x4(ah[0], a0);
                    ldsm_x4(ah[1], a1);
                    ldsm_x4(al[0], a0 + ARR_B);
                    ldsm_x4(al[1], a1 + ARR_B);
                }
#pragma unroll
                for (int g = 0; g < 4; g++) {
                    uint32_t bh[4], bl[4];
                    const int n = wn * 64 + g * 16 + rA;
                    uint32_t b0 = sb + 2 * ARR_B + swz(n, u);
                    ldsm_x4(bh, b0);
                    ldsm_x4(bl, b0 + ARR_B);
#pragma unroll
                    for (int o = 0; o < 2; o++) {
                        const int nj = g * 2 + o;
#pragma unroll
                        for (int mi = 0; mi < 2; mi++) {
                            mma_bf16(acc[mi][nj], ah[mi], bh[o], bh[o + 2]);
                            mma_bf16(acc[mi][nj], ah[mi], bl[o], bl[o + 2]);
                            mma_bf16(acc[mi][nj], al[mi], bh[o], bh[o + 2]);
                        }
                    }
                }
            }
            if (++stg >= 3) stg = 0;
        }
        __syncthreads();   // protect smem reuse by epilogues
    }
};

// ---------------------------------------------------------------------------
// Fused QKV projection. grid (32, 24): blockIdx.y>>3 selects {Q,K,V}.
// Q/K epilogues write head-major bf16 hi/lo splits (Q pre-scaled).
// V epilogue: smem transpose -> fp16 hi/lo head-major Vt[bh][d][s].
// ---------------------------------------------------------------------------
static constexpr int VTP = 136;   // fp16 transpose pitch (elems)

__global__ __launch_bounds__(256, 2) void qkv_gemm(
    const __nv_bfloat16* __restrict__ Ahi, const __nv_bfloat16* __restrict__ Alo,
    const __nv_bfloat16* __restrict__ Wh, const __nv_bfloat16* __restrict__ Wl,
    const float* __restrict__ bq, const float* __restrict__ bk,
    const float* __restrict__ bv,
    __nv_bfloat16* __restrict__ Qh, __nv_bfloat16* __restrict__ Ql,
    __nv_bfloat16* __restrict__ Kh, __nv_bfloat16* __restrict__ Kl,
    __half* __restrict__ Vth, __half* __restrict__ Vtl)
{
    extern __shared__ __align__(128) char dsm[];
    const int which = blockIdx.y >> 3;           // 0=Q 1=K 2=V
    const int m0 = blockIdx.x * 128;
    const int n0 = (blockIdx.y & 7) * 128;
    const float* bias = (which == 0) ? bq : (which == 1) ? bk : bv;

    GemmCore core;
    core.init(smem_u32(dsm), m0, n0,
              Ahi, Alo, Wh + (size_t)which * D * D, Wl + (size_t)which * D * D);
    float acc[2][8][4];
    core.run(acc);

    const int tid = core.tid, lane = core.lane, wm = core.wm, wn = core.wn;

    if (which == 2) {
        // ---- V: transpose via smem, write fp16 hi/lo [bh][d][s] ----
        __half* SH = (__half*)dsm;
        __half* SL = SH + 128 * VTP;
#pragma unroll
        for (int mi = 0; mi < 2; mi++) {
            const int rl = wm * 32 + mi * 16 + (lane >> 2);
#pragma unroll
            for (int nj = 0; nj < 8; nj++) {
                const int cl = wn * 64 + nj * 8 + (lane & 3) * 2;
                float2 bb = *(const float2*)&bias[n0 + cl];
                float v[2][2] = {{acc[mi][nj][0] + bb.x, acc[mi][nj][1] + bb.y},
                                 {acc[mi][nj][2] + bb.x, acc[mi][nj][3] + bb.y}};
#pragma unroll
                for (int rr = 0; rr < 2; rr++)
#pragma unroll
                    for (int cc = 0; cc < 2; cc++) {
                        __half h = __float2half_rn(v[rr][cc]);
                        __half l = __float2half_rn(v[rr][cc] - __half2float(h));
                        int o = (cl + cc) * VTP + rl + rr * 8;
                        SH[o] = h; SL[o] = l;
                    }
            }
        }
        __syncthreads();
        // each thread copies one full column (128 rows = 16 uint4)
        const int a = tid >> 7, c = tid & 127;
        const __half* S = a ? SL : SH;
        const int n = n0 + c, hh = n >> 6, dd = n & 63;
        const int bI = m0 >> 11, s0 = m0 & 2047;
        __half* dst = (a ? Vtl : Vth) +
            ((size_t)(bI * NH + hh) * DH + dd) * SEQ + s0;
        const uint4* srow = (const uint4*)(S + (size_t)c * VTP);
#pragma unroll
        for (int i = 0; i < 16; i++) ((uint4*)dst)[i] = srow[i];
    } else {
        const float scale = (which == 0) ? 0.125f : 1.0f;
        __nv_bfloat16* OH = (which == 0) ? Qh : Kh;
        __nv_bfloat16* OL = (which == 0) ? Ql : Kl;
#pragma unroll
        for (int mi = 0; mi < 2; mi++) {
            const int row = m0 + wm * 32 + mi * 16 + (lane >> 2);
#pragma unroll
            for (int nj = 0; nj < 8; nj++) {
                const int col = n0 + wn * 64 + nj * 8 + (lane & 3) * 2;
                float2 bb = *(const float2*)&bias[col];
                float v00 = acc[mi][nj][0] + bb.x, v01 = acc[mi][nj][1] + bb.y;
                float v10 = acc[mi][nj][2] + bb.x, v11 = acc[mi][nj][3] + bb.y;
                const int bI = row >> 11, h = col >> 6, dd = col & 63;
#pragma unroll
                for (int rr = 0; rr < 2; rr++) {
                    const int s = (row + rr * 8) & 2047;
                    size_t o = ((size_t)(bI * NH + h) * SEQ + s) * DH + dd;
                    uint32_t hh, ll;
                    float a0 = (rr ? v10 : v00) * scale;
                    float a1 = (rr ? v11 : v01) * scale;
                    split_pair(a0, a1, hh, ll);
                    *(uint32_t*)&OH[o] = hh;
                    *(uint32_t*)&OL[o] = ll;
                }
            }
        }
    }
}

// ---------------------------------------------------------------------------
// Output-projection GEMM (fp32 out + bias).
// ---------------------------------------------------------------------------
__global__ __launch_bounds__(256, 2) void gemm_tc(
    const __nv_bfloat16* __restrict__ Ahi, const __nv_bfloat16* __restrict__ Alo,
    const __nv_bfloat16* __restrict__ Bhi, const __nv_bfloat16* __restrict__ Blo,
    const float* __restrict__ bias, float* __restrict__ C)
{
    extern __shared__ __align__(128) char dsm[];
    const int m0 = blockIdx.x * 128;
    const int n0 = blockIdx.y * 128;

    GemmCore core;
    core.init(smem_u32(dsm), m0, n0, Ahi, Alo, Bhi, Blo);
    float acc[2][8][4];
    core.run(acc);

    const int lane = core.lane, wm = core.wm, wn = core.wn;
#pragma unroll
    for (int mi = 0; mi < 2; mi++) {
        const int row = m0 + wm * 32 + mi * 16 + (lane >> 2);
#pragma unroll
        for (int nj = 0; nj < 8; nj++) {
            const int col = n0 + wn * 64 + nj * 8 + (lane & 3) * 2;
            float2 bb = *(const float2*)&bias[col];
            float2 v0 = {acc[mi][nj][0] + bb.x, acc[mi][nj][1] + bb.y};
            float2 v1 = {acc[mi][nj][2] + bb.x, acc[mi][nj][3] + bb.y};
            *(float2*)&C[(size_t)row * D + col]       = v0;
            *(float2*)&C[(size_t)(row + 8) * D + col] = v1;
        }
    }
}

// ---------------------------------------------------------------------------
// Tensor-core causal flash attention (round-14 passing version).
// S = QK^T: bf16 3-term split. PV: fp16 P (single) x fp16 V hi/lo (2 terms).
// ---------------------------------------------------------------------------
static constexpr int ARS  = 144;
static constexpr int AARR = 64 * ARS;
static constexpr int ASTG = 4 * AARR;
static constexpr int ASMEM = 2 * ASTG;

__global__ __launch_bounds__(256) void attn_tc(
    const __nv_bfloat16* __restrict__ Qh, const __nv_bfloat16* __restrict__ Ql,
    const __nv_bfloat16* __restrict__ Kh, const __nv_bfloat16* __restrict__ Kl,
    const __half* __restrict__ Vth, const __half* __restrict__ Vtl,
    __nv_bfloat16* __restrict__ Chi, __nv_bfloat16* __restrict__ Clo)
{
    extern __shared__ __align__(128) char dsm[];
    const uint32_t sb0 = smem_u32(dsm);

    const int tid = threadIdx.x;
    const int wid = tid >> 5, lane = tid & 31;
    const int qt  = (gridDim.x - 1) - blockIdx.x;
    const int bh  = blockIdx.y;
    const size_t hB  = (size_t)bh * (SEQ * DH);
    const size_t vB  = (size_t)bh * (DH * SEQ);
    const int rA = lane & 15;
    const int half = (lane >> 4) * 16;

#pragma unroll
    for (int t = 0; t < 8; t++) {
        int idx = tid + t * 256;
        int a = idx >> 10, rem = idx & 1023, r = rem >> 3, sg = rem & 7;
        uint32_t dst = sb0 + a * (2 * AARR) + r * ARS + sg * 16;
        const __nv_bfloat16* src = (a ? Ql : Qh) + hB + (size_t)(qt * 128 + r) * DH + sg * 8;
        cp16(dst, src);
    }
    cp_commit();
    cp_wait<0>();
    __syncthreads();

    uint32_t qh[4][4], ql[4][4];
    {
        uint32_t qAddrH = sb0 + (wid >> 2) * AARR + ((wid & 3) * 16 + rA) * ARS;
        uint32_t qAddrL = qAddrH + 2 * AARR;
#pragma unroll
        for (int kc = 0; kc < 4; kc++) {
            ldsm_x4(qh[kc], qAddrH + kc * 32 + half);
            ldsm_x4(ql[kc], qAddrL + kc * 32 + half);
        }
    }
    __syncthreads();

    float ctxa[8][4];
#pragma unroll
    for (int dj = 0; dj < 8; dj++)
#pragma unroll
        for (int e = 0; e < 4; e++) ctxa[dj][e] = 0.f;
    float m0 = -1e30f, m1 = -1e30f, l0 = 0.f, l1 = 0.f;

    const int nkt = 2 * qt + 2;
    auto issue = [&](int kt, int st) {
#pragma unroll
        for (int t = 0; t < 8; t++) {
            int idx = tid + t * 256;
            int a = idx >> 9, rem = idx & 511, r = rem >> 3, sg = rem & 7;
            uint32_t dst = sb0 + st * ASTG + a * AARR + r * ARS + sg * 16;
            const void* src;
            if (a == 0)      src = Kh  + hB + (size_t)(kt * 64 + r) * DH + sg * 8;
            else if (a == 1) src = Kl  + hB + (size_t)(kt * 64 + r) * DH + sg * 8;
            else if (a == 2) src = Vth + vB + (size_t)r * SEQ + kt * 64 + sg * 8;
            else             src = Vtl + vB + (size_t)r * SEQ + kt * 64 + sg * 8;
            cp16(dst, src);
        }
        cp_commit();
    };

    issue(0, 0);
    issue(1, 1);

    const int qmin = qt * 128 + wid * 16;
    const int q0r = qmin + (lane >> 2);
    const int q1r = q0r + 8;

    for (int kt = 0; kt < nkt; kt++) {
        if (kt + 1 < nkt) cp_wait<1>(); else cp_wait<0>();
        __syncthreads();

        const int ktb = kt * 64;
        const bool skip = (ktb > qmin + 15);
        if (!skip) {
            const uint32_t sk = sb0 + (kt & 1) * ASTG;
            float s[8][4];
#pragma unroll
            for (int nj = 0; nj < 8; nj++)
#pragma unroll
                for (int e = 0; e < 4; e++) s[nj][e] = 0.f;

#pragma unroll
            for (int kc = 0; kc < 4; kc++) {
                uint32_t kbh[4][4], kbl[4][4];
#pragma unroll
                for (int g = 0; g < 4; g++) {
                    uint32_t ka = sk + (g * 16 + rA) * ARS + kc * 32 + half;
                    ldsm_x4(kbh[g], ka);
                    ldsm_x4(kbl[g], ka + AARR);
                }
#pragma unroll
                for (int nj = 0; nj < 8; nj++) {
                    const int g = nj >> 1, o = nj & 1;
                    mma_bf16(s[nj], qh[kc], kbh[g][o], kbh[g][o + 2]);
                    mma_bf16(s[nj], qh[kc], kbl[g][o], kbl[g][o + 2]);
                    mma_bf16(s[nj], ql[kc], kbh[g][o], kbh[g][o + 2]);
                }
            }

            if (ktb + 63 > qmin) {
#pragma unroll
                for (int nj = 0; nj < 8; nj++) {
                    int key = ktb + nj * 8 + ((lane & 3) << 1);
                    if (key     > q0r) s[nj][0] = -1e30f;
                    if (key + 1 > q0r) s[nj][1] = -1e30f;
                    if (key     > q1r) s[nj][2] = -1e30f;
                    if (key + 1 > q1r) s[nj][3] = -1e30f;
                }
            }

            float mx0 = -1e30f, mx1 = -1e30f;
#pragma unroll
            for (int nj = 0; nj < 8; nj++) {
                mx0 = fmaxf(mx0, fmaxf(s[nj][0], s[nj][1]));
                mx1 = fmaxf(mx1, fmaxf(s[nj][2], s[nj][3]));
            }
            mx0 = fmaxf(mx0, __shfl_xor_sync(0xFFFFFFFFu, mx0, 1));
            mx0 = fmaxf(mx0, __shfl_xor_sync(0xFFFFFFFFu, mx0, 2));
            mx1 = fmaxf(mx1, __shfl_xor_sync(0xFFFFFFFFu, mx1, 1));
            mx1 = fmaxf(mx1, __shfl_xor_sync(0xFFFFFFFFu, mx1, 2));
            float nm0 = fmaxf(m0, mx0), nm1 = fmaxf(m1, mx1);
            float f0 = __expf(m0 - nm0), f1 = __expf(m1 - nm1);
            m0 = nm0; m1 = nm1;

            float sum0 = 0.f, sum1 = 0.f;
#pragma unroll
            for (int nj = 0; nj < 8; nj++) {
                s[nj][0] = __expf(s[nj][0] - m0); sum0 += s[nj][0];
                s[nj][1] = __expf(s[nj][1] - m0); sum0 += s[nj][1];
                s[nj][2] = __expf(s[nj][2] - m1); sum1 += s[nj][2];
                s[nj][3] = __expf(s[nj][3] - m1); sum1 += s[nj][3];
            }
            sum0 += __shfl_xor_sync(0xFFFFFFFFu, sum0, 1);
            sum0 += __shfl_xor_sync(0xFFFFFFFFu, sum0, 2);
            sum1 += __shfl_xor_sync(0xFFFFFFFFu, sum1, 1);
            sum1 += __shfl_xor_sync(0xFFFFFFFFu, sum1, 2);
            l0 = l0 * f0 + sum0;
            l1 = l1 * f1 + sum1;
#pragma unroll
            for (int dj = 0; dj < 8; dj++) {
                ctxa[dj][0] *= f0; ctxa[dj][1] *= f0;
                ctxa[dj][2] *= f1; ctxa[dj][3] *= f1;
            }

            // ---- ctx += P @ V : P single fp16, V fp16 hi+lo (2 terms) ----
#pragma unroll
            for (int kc = 0; kc < 4; kc++) {
                uint32_t ph[4];
                ph[0] = pack_h2(s[2 * kc][0],     s[2 * kc][1]);
                ph[1] = pack_h2(s[2 * kc][2],     s[2 * kc][3]);
                ph[2] = pack_h2(s[2 * kc + 1][0], s[2 * kc + 1][1]);
                ph[3] = pack_h2(s[2 * kc + 1][2], s[2 * kc + 1][3]);

                uint32_t vh[4][4], vl[4][4];
#pragma unroll
                for (int g = 0; g < 4; g++) {
                    uint32_t va = sk + 2 * AARR + (g * 16 + rA) * ARS + kc * 32 + half;
                    ldsm_x4(vh[g], va);
                    ldsm_x4(vl[g], va + AARR);
                }
#pragma unroll
                for (int dj = 0; dj < 8; dj++) {
                    const int g = dj >> 1, o = dj & 1;
                    mma_f16(ctxa[dj], ph, vh[g][o], vh[g][o + 2]);
                    mma_f16(ctxa[dj], ph, vl[g][o], vl[g][o + 2]);
                }
            }
        }
        __syncthreads();
        if (kt + 2 < nkt) issue(kt + 2, kt & 1);
    }

    const float inv0 = 1.f / l0, inv1 = 1.f / l1;
    const int b = bh >> 4, h = bh & 15;
    const size_t row0 = (size_t)(b * SEQ + qt * 128 + wid * 16 + (lane >> 2));
#pragma unroll
    for (int dj = 0; dj < 8; dj++) {
        const int col = h * DH + dj * 8 + (lane & 3) * 2;
        uint32_t hh, ll;
        split_pair(ctxa[dj][0] * inv0, ctxa[dj][1] * inv0, hh, ll);
        *(uint32_t*)&Chi[row0 * D + col] = hh;
        *(uint32_t*)&Clo[row0 * D + col] = ll;
        split_pair(ctxa[dj][2] * inv1, ctxa[dj][3] * inv1, hh, ll);
        *(uint32_t*)&Chi[(row0 + 8) * D + col] = hh;
        *(uint32_t*)&Clo[(row0 + 8) * D + col] = ll;
    }
}

// ---------------------------------------------------------------------------
// Launch
// ---------------------------------------------------------------------------
extern "C" void kernel_launch(void* const* d_in, const int* in_sizes, int n_in,
                              void* d_out, int out_size)
{
    const float* x  = (const float*)d_in[0];
    const float* Wq = (const float*)d_in[1];
    const float* bq = (const float*)d_in[2];
    const float* Wk = (const float*)d_in[3];
    const float* bk = (const float*)d_in[4];
    const float* Wv = (const float*)d_in[5];
    const float* bv = (const float*)d_in[6];
    const float* Wo = (const float*)d_in[7];
    const float* bo = (const float*)d_in[8];
    float* out = (float*)d_out;

    __nv_bfloat16 *ahi, *alo, *wh, *wl;
    cudaGetSymbolAddress((void**)&ahi, g_ahi);
    cudaGetSymbolAddress((void**)&alo, g_alo);
    cudaGetSymbolAddress((void**)&wh, g_wh);
    cudaGetSymbolAddress((void**)&wl, g_wl);

    __nv_bfloat16 *qhp, *qlp, *khp, *klp;
    __half *vthp, *vtlp;
    cudaGetSymbolAddress((void**)&qhp, g_Qh);
    cudaGetSymbolAddress((void**)&qlp, g_Ql);
    cudaGetSymbolAddress((void**)&khp, g_Kh);
    cudaGetSymbolAddress((void**)&klp, g_Kl);
    cudaGetSymbolAddress((void**)&vthp, g_Vth);
    cudaGetSymbolAddress((void**)&vtlp, g_Vtl);

    cudaFuncSetAttribute(qkv_gemm, cudaFuncAttributeMaxDynamicSharedMemorySize, GSMEM);
    cudaFuncSetAttribute(gemm_tc, cudaFuncAttributeMaxDynamicSharedMemorySize, GSMEM);
    cudaFuncSetAttribute(attn_tc, cudaFuncAttributeMaxDynamicSharedMemorySize, ASMEM);

    // 1) fused prep: x split + all 4 weight transposes (one launch)
    prep_all<<<8192, 256>>>(x, ahi, alo, Wq, Wk, Wv, Wo, wh, wl);

    // 2) fused QKV projection (Q/K head-major splits; V transposed fp16 splits)
    dim3 gq(M_TOT / 128, 24);
    qkv_gemm<<<gq, 256, GSMEM>>>(ahi, alo, wh, wl, bq, bk, bv,
                                 qhp, qlp, khp, klp, vthp, vtlp);

    // 3) tensor-core attention (writes ctx splits into ahi/alo)
    dim3 ga(SEQ / 128, NBH);
    attn_tc<<<ga, 256, ASMEM>>>(qhp, qlp, khp, klp, vthp, vtlp, ahi, alo);

    // 4) output projection
    gemm_tc<<<dim3(M_TOT / 128, D / 128), 256, GSMEM>>>(
        ahi, alo, wh + 3 * (size_t)D * D, wl + 3 * (size_t)D * D, bo, out);
}

// round 16
// speedup vs baseline: 4.5065x; 1.2775x over previous
#include <cuda_runtime.h>
#include <cuda_bf16.h>
#include <cuda_fp16.h>
#include <cstdint>

static constexpr int SEQ = 2048;
static constexpr int NB  = 2;
static constexpr int D   = 1024;
static constexpr int NH  = 16;
static constexpr int DH  = 64;
static constexpr int M_TOT = NB * SEQ; // 4096
static constexpr int NBH  = NB * NH;   // 32

// ---------------- scratch (__device__ globals; no allocs allowed) ----------
__device__ __half        g_a16[M_TOT * D];   // GEMM A operand (x, then ctx) fp16
__device__ __half        g_wh[4][D * D];     // transposed weight splits [N][K], x64
__device__ __half        g_wl[4][D * D];

// head-major attention operands: [bh][s][64] (Q,K bf16) / [bh][64][s] (Vt fp16)
static constexpr int HM = NBH * SEQ * DH;
__device__ __nv_bfloat16 g_Qh[HM], g_Ql[HM];
__device__ __nv_bfloat16 g_Kh[HM], g_Kl[HM];
__device__ __half        g_Vth[HM], g_Vtl[HM];

// ---------------- mma.sync / ldmatrix / cp.async helpers -------------------
__device__ __forceinline__ uint32_t smem_u32(const void* p) {
    uint32_t a;
    asm("{ .reg .u64 t; cvta.to.shared.u64 t, %1; cvt.u32.u64 %0, t; }" : "=r"(a) : "l"(p));
    return a;
}
__device__ __forceinline__ void ldsm_x4(uint32_t* r, uint32_t addr) {
    asm volatile("ldmatrix.sync.aligned.m8n8.x4.shared.b16 {%0,%1,%2,%3}, [%4];"
                 : "=r"(r[0]), "=r"(r[1]), "=r"(r[2]), "=r"(r[3]) : "r"(addr));
}
__device__ __forceinline__ void mma_bf16(float* d, const uint32_t* a, uint32_t b0, uint32_t b1) {
    asm volatile(
        "mma.sync.aligned.m16n8k16.row.col.f32.bf16.bf16.f32 "
        "{%0,%1,%2,%3},{%4,%5,%6,%7},{%8,%9},{%0,%1,%2,%3};"
        : "+f"(d[0]), "+f"(d[1]), "+f"(d[2]), "+f"(d[3])
        : "r"(a[0]), "r"(a[1]), "r"(a[2]), "r"(a[3]), "r"(b0), "r"(b1));
}
__device__ __forceinline__ void mma_f16(float* d, const uint32_t* a, uint32_t b0, uint32_t b1) {
    asm volatile(
        "mma.sync.aligned.m16n8k16.row.col.f32.f16.f16.f32 "
        "{%0,%1,%2,%3},{%4,%5,%6,%7},{%8,%9},{%0,%1,%2,%3};"
        : "+f"(d[0]), "+f"(d[1]), "+f"(d[2]), "+f"(d[3])
        : "r"(a[0]), "r"(a[1]), "r"(a[2]), "r"(a[3]), "r"(b0), "r"(b1));
}
__device__ __forceinline__ void cp16(uint32_t dst, const void* src) {
    asm volatile("cp.async.cg.shared.global [%0], [%1], 16;" :: "r"(dst), "l"(src));
}
__device__ __forceinline__ void cp_commit() {
    asm volatile("cp.async.commit_group;" ::: "memory");
}
template <int N>
__device__ __forceinline__ void cp_wait() {
    asm volatile("cp.async.wait_group %0;" :: "n"(N) : "memory");
}
// split (a,b) fp32 pair -> packed bf16x2 hi + residual-lo (lo half = a)
__device__ __forceinline__ void split_pair(float a, float b, uint32_t& hi, uint32_t& lo) {
    uint32_t h;
    asm("cvt.rn.bf16x2.f32 %0, %1, %2;" : "=r"(h) : "f"(b), "f"(a));
    __nv_bfloat162 hb = *(__nv_bfloat162*)&h;
    float ra = a - __bfloat162float(hb.x);
    float rb = b - __bfloat162float(hb.y);
    uint32_t l;
    asm("cvt.rn.bf16x2.f32 %0, %1, %2;" : "=r"(l) : "f"(rb), "f"(ra));
    hi = h; lo = l;
}
__device__ __forceinline__ uint32_t pack_h2(float a, float b) {
    __half2 t = __floats2half2_rn(a, b);   // x = a (lower), y = b (upper)
    return *(uint32_t*)&t;
}

// ---------------------------------------------------------------------------
// Fused prep: blocks [0,4096): x fp32 -> fp16 single (GEMM A layout)
//             blocks [4096,8192): weight z transpose+split (x64) fp16 hi/lo
// ---------------------------------------------------------------------------
__global__ __launch_bounds__(256) void prep_all(
    const float* __restrict__ X, __half* __restrict__ A16,
    const float* __restrict__ W0, const float* __restrict__ W1,
    const float* __restrict__ W2, const float* __restrict__ W3,
    __half* __restrict__ Thi, __half* __restrict__ Tlo)
{
    __shared__ float t[32][33];
    const int bx = blockIdx.x;
    const int tid = threadIdx.x;
    if (bx < 4096) {
        int i = bx * 1024 + tid * 4;
        float4 v = *(const float4*)&X[i];
        *(uint2*)&A16[i] = make_uint2(pack_h2(v.x, v.y), pack_h2(v.z, v.w));
    } else {
        const int r0 = bx - 4096;
        const int z = r0 >> 10;
        const int rem = r0 & 1023;
        const float* W = (z == 0) ? W0 : (z == 1) ? W1 : (z == 2) ? W2 : W3;
        __half* oh = Thi + (size_t)z * D * D;
        __half* ol = Tlo + (size_t)z * D * D;
        const int n0 = (rem & 31) * 32, k0 = (rem >> 5) * 32;
        const int tx = tid & 31, ty = tid >> 5;
#pragma unroll
        for (int r = ty; r < 32; r += 8)
            t[r][tx] = W[(size_t)(k0 + r) * D + n0 + tx];
        __syncthreads();
#pragma unroll
        for (int r = ty; r < 32; r += 8) {
            float v = t[tx][r] * 64.f;
            __half h = __float2half_rn(v);
            __half l = __float2half_rn(v - __half2float(h));
            oh[(size_t)(n0 + r) * D + k0 + tx] = h;
            ol[(size_t)(n0 + r) * D + k0 + tx] = l;
        }
    }
}

// ---------------------------------------------------------------------------
// GEMM mainloop. 128x128 block, warp tile 32x64, BK=32. 3-stage cp.async,
// one barrier per chunk. A = fp16 single; W = fp16 hi/lo (x64): 2 MMA terms.
// Paired-row XOR swizzle, 64B/row effective.
// ---------------------------------------------------------------------------
static constexpr int GK     = 1024;
static constexpr int BK     = 32;
static constexpr int NCHUNK = GK / BK;
static constexpr int ARR_B  = 64 * 128;          // 8192 B per operand tile
static constexpr int STAGE_B = 3 * ARR_B;        // 24576 B per stage (A, Wh, Wl)
static constexpr int GSMEM   = 3 * STAGE_B;      // 73728 B
static constexpr float INV64 = 1.f / 64.f;

// smem byte offset of 16B unit u (0..3) of logical row m (0..127)
__device__ __forceinline__ uint32_t swz(int m, int u) {
    const int R = m >> 1;
    const int unit = ((m & 1) << 2) | u;
    return (uint32_t)(R * 128 + ((unit ^ (R & 7)) << 4));
}

struct GemmCore {
    uint32_t sbase;
    int tid, wid, lane, wm, wn, rA;
    const char* srcs[3];
    int rowb[3];

    __device__ __forceinline__ void init(uint32_t sb, int m0, int n0,
        const __half* A16, const __half* Bhi, const __half* Blo)
    {
        sbase = sb;
        tid = threadIdx.x; wid = tid >> 5; lane = tid & 31;
        wm = wid & 3; wn = wid >> 2;
        rA = lane & 15;
        srcs[0] = (const char*)A16; srcs[1] = (const char*)Bhi;
        srcs[2] = (const char*)Blo;
        rowb[0] = m0; rowb[1] = n0; rowb[2] = n0;
    }
    __device__ __forceinline__ void issue(int chunk, int stage) {
#pragma unroll
        for (int t = 0; t < 6; t++) {
            int idx = tid + t * 256;
            int a = idx >> 9, rem = idx & 511, r = rem >> 2, q = rem & 3;
            uint32_t dst = sbase + stage * STAGE_B + a * ARR_B + swz(r, q);
            const char* src = srcs[a] +
                ((size_t)(rowb[a] + r) * GK + chunk * BK) * 2 + q * 16;
            cp16(dst, src);
        }
        cp_commit();
    }
    __device__ __forceinline__ void run(float acc[2][8][4]) {
#pragma unroll
        for (int mi = 0; mi < 2; mi++)
#pragma unroll
            for (int nj = 0; nj < 8; nj++)
#pragma unroll
                for (int e = 0; e < 4; e++) acc[mi][nj][e] = 0.f;

        issue(0, 0);
        issue(1, 1);

        int stg = 0;
        for (int c = 0; c < NCHUNK; c++) {
            if (c + 1 < NCHUNK) cp_wait<1>(); else cp_wait<0>();
            __syncthreads();
            if (c + 2 < NCHUNK) {
                int nstg = stg + 2; if (nstg >= 3) nstg -= 3;
                issue(c + 2, nstg);
            }
            const uint32_t sb = sbase + stg * STAGE_B;
#pragma unroll
            for (int s = 0; s < 2; s++) {
                const int u = s * 2 + (lane >> 4);   // 16B k-unit 0..3
                uint32_t ah[2][4];
                {
                    const int m = wm * 32 + rA;
                    ldsm_x4(ah[0], sb + swz(m, u));
                    ldsm_x4(ah[1], sb + swz(m + 16, u));
                }
#pragma unroll
                for (int g = 0; g < 4; g++) {
                    uint32_t bh[4], bl[4];
                    const int n = wn * 64 + g * 16 + rA;
                    uint32_t b0 = sb + ARR_B + swz(n, u);
                    ldsm_x4(bh, b0);
                    ldsm_x4(bl, b0 + ARR_B);
#pragma unroll
                    for (int o = 0; o < 2; o++) {
                        const int nj = g * 2 + o;
#pragma unroll
                        for (int mi = 0; mi < 2; mi++) {
                            mma_f16(acc[mi][nj], ah[mi], bh[o], bh[o + 2]);
                            mma_f16(acc[mi][nj], ah[mi], bl[o], bl[o + 2]);
                        }
                    }
                }
            }
            if (++stg >= 3) stg = 0;
        }
        __syncthreads();   // protect smem reuse by epilogues
    }
};

// ---------------------------------------------------------------------------
// Fused QKV projection. grid (32, 24): blockIdx.y>>3 selects {Q,K,V}.
// Q/K epilogues write head-major bf16 hi/lo splits (Q pre-scaled).
// V epilogue: smem transpose -> fp16 hi/lo head-major Vt[bh][d][s].
// All accumulators carry the x64 weight scale -> multiply by 1/64.
// ---------------------------------------------------------------------------
static constexpr int VTP = 136;   // fp16 transpose pitch (elems)

__global__ __launch_bounds__(256, 2) void qkv_gemm(
    const __half* __restrict__ A16,
    const __half* __restrict__ Wh, const __half* __restrict__ Wl,
    const float* __restrict__ bq, const float* __restrict__ bk,
    const float* __restrict__ bv,
    __nv_bfloat16* __restrict__ Qh, __nv_bfloat16* __restrict__ Ql,
    __nv_bfloat16* __restrict__ Kh, __nv_bfloat16* __restrict__ Kl,
    __half* __restrict__ Vth, __half* __restrict__ Vtl)
{
    extern __shared__ __align__(128) char dsm[];
    const int which = blockIdx.y >> 3;           // 0=Q 1=K 2=V
    const int m0 = blockIdx.x * 128;
    const int n0 = (blockIdx.y & 7) * 128;
    const float* bias = (which == 0) ? bq : (which == 1) ? bk : bv;

    GemmCore core;
    core.init(smem_u32(dsm), m0, n0,
              A16, Wh + (size_t)which * D * D, Wl + (size_t)which * D * D);
    float acc[2][8][4];
    core.run(acc);

    const int tid = core.tid, lane = core.lane, wm = core.wm, wn = core.wn;

    if (which == 2) {
        // ---- V: transpose via smem, write fp16 hi/lo [bh][d][s] ----
        __half* SH = (__half*)dsm;
        __half* SL = SH + 128 * VTP;
#pragma unroll
        for (int mi = 0; mi < 2; mi++) {
            const int rl = wm * 32 + mi * 16 + (lane >> 2);
#pragma unroll
            for (int nj = 0; nj < 8; nj++) {
                const int cl = wn * 64 + nj * 8 + (lane & 3) * 2;
                float2 bb = *(const float2*)&bias[n0 + cl];
                float v[2][2] = {{acc[mi][nj][0] * INV64 + bb.x, acc[mi][nj][1] * INV64 + bb.y},
                                 {acc[mi][nj][2] * INV64 + bb.x, acc[mi][nj][3] * INV64 + bb.y}};
#pragma unroll
                for (int rr = 0; rr < 2; rr++)
#pragma unroll
                    for (int cc = 0; cc < 2; cc++) {
                        __half h = __float2half_rn(v[rr][cc]);
                        __half l = __float2half_rn(v[rr][cc] - __half2float(h));
                        int o = (cl + cc) * VTP + rl + rr * 8;
                        SH[o] = h; SL[o] = l;
                    }
            }
        }
        __syncthreads();
        // each thread copies one full column (128 rows = 16 uint4)
        const int a = tid >> 7, c = tid & 127;
        const __half* S = a ? SL : SH;
        const int n = n0 + c, hh = n >> 6, dd = n & 63;
        const int bI = m0 >> 11, s0 = m0 & 2047;
        __half* dst = (a ? Vtl : Vth) +
            ((size_t)(bI * NH + hh) * DH + dd) * SEQ + s0;
        const uint4* srow = (const uint4*)(S + (size_t)c * VTP);
#pragma unroll
        for (int i = 0; i < 16; i++) ((uint4*)dst)[i] = srow[i];
    } else {
        const float scale = (which == 0) ? 0.125f : 1.0f;
        __nv_bfloat16* OH = (which == 0) ? Qh : Kh;
        __nv_bfloat16* OL = (which == 0) ? Ql : Kl;
#pragma unroll
        for (int mi = 0; mi < 2; mi++) {
            const int row = m0 + wm * 32 + mi * 16 + (lane >> 2);
#pragma unroll
            for (int nj = 0; nj < 8; nj++) {
                const int col = n0 + wn * 64 + nj * 8 + (lane & 3) * 2;
                float2 bb = *(const float2*)&bias[col];
                float v00 = acc[mi][nj][0] * INV64 + bb.x, v01 = acc[mi][nj][1] * INV64 + bb.y;
                float v10 = acc[mi][nj][2] * INV64 + bb.x, v11 = acc[mi][nj][3] * INV64 + bb.y;
                const int bI = row >> 11, h = col >> 6, dd = col & 63;
#pragma unroll
                for (int rr = 0; rr < 2; rr++) {
                    const int s = (row + rr * 8) & 2047;
                    size_t o = ((size_t)(bI * NH + h) * SEQ + s) * DH + dd;
                    uint32_t hh, ll;
                    float a0 = (rr ? v10 : v00) * scale;
                    float a1 = (rr ? v11 : v01) * scale;
                    split_pair(a0, a1, hh, ll);
                    *(uint32_t*)&OH[o] = hh;
                    *(uint32_t*)&OL[o] = ll;
                }
            }
        }
    }
}

// ---------------------------------------------------------------------------
// Output-projection GEMM (fp32 out + bias, /64 weight scale).
// ---------------------------------------------------------------------------
__global__ __launch_bounds__(256, 2) void gemm_tc(
    const __half* __restrict__ A16,
    const __half* __restrict__ Bhi, const __half* __restrict__ Blo,
    const float* __restrict__ bias, float* __restrict__ C)
{
    extern __shared__ __align__(128) char dsm[];
    const int m0 = blockIdx.x * 128;
    const int n0 = blockIdx.y * 128;

    GemmCore core;
    core.init(smem_u32(dsm), m0, n0, A16, Bhi, Blo);
    float acc[2][8][4];
    core.run(acc);

    const int lane = core.lane, wm = core.wm, wn = core.wn;
#pragma unroll
    for (int mi = 0; mi < 2; mi++) {
        const int row = m0 + wm * 32 + mi * 16 + (lane >> 2);
#pragma unroll
        for (int nj = 0; nj < 8; nj++) {
            const int col = n0 + wn * 64 + nj * 8 + (lane & 3) * 2;
            float2 bb = *(const float2*)&bias[col];
            float2 v0 = {acc[mi][nj][0] * INV64 + bb.x, acc[mi][nj][1] * INV64 + bb.y};
            float2 v1 = {acc[mi][nj][2] * INV64 + bb.x, acc[mi][nj][3] * INV64 + bb.y};
            *(float2*)&C[(size_t)row * D + col]       = v0;
            *(float2*)&C[(size_t)(row + 8) * D + col] = v1;
        }
    }
}

// ---------------------------------------------------------------------------
// Tensor-core causal flash attention.
// S = QK^T: bf16 3-term split. PV: fp16 P (single) x fp16 V hi/lo (2 terms).
// Epilogue writes ctx as SINGLE fp16 (A operand of output projection).
// ---------------------------------------------------------------------------
static constexpr int ARS  = 144;
static constexpr int AARR = 64 * ARS;
static constexpr int ASTG = 4 * AARR;
static constexpr int ASMEM = 2 * ASTG;

__global__ __launch_bounds__(256) void attn_tc(
    const __nv_bfloat16* __restrict__ Qh, const __nv_bfloat16* __restrict__ Ql,
    const __nv_bfloat16* __restrict__ Kh, const __nv_bfloat16* __restrict__ Kl,
    const __half* __restrict__ Vth, const __half* __restrict__ Vtl,
    __half* __restrict__ C16)
{
    extern __shared__ __align__(128) char dsm[];
    const uint32_t sb0 = smem_u32(dsm);

    const int tid = threadIdx.x;
    const int wid = tid >> 5, lane = tid & 31;
    const int qt  = (gridDim.x - 1) - blockIdx.x;
    const int bh  = blockIdx.y;
    const size_t hB  = (size_t)bh * (SEQ * DH);
    const size_t vB  = (size_t)bh * (DH * SEQ);
    const int rA = lane & 15;
    const int half = (lane >> 4) * 16;

#pragma unroll
    for (int t = 0; t < 8; t++) {
        int idx = tid + t * 256;
        int a = idx >> 10, rem = idx & 1023, r = rem >> 3, sg = rem & 7;
        uint32_t dst = sb0 + a * (2 * AARR) + r * ARS + sg * 16;
        const __nv_bfloat16* src = (a ? Ql : Qh) + hB + (size_t)(qt * 128 + r) * DH + sg * 8;
        cp16(dst, src);
    }
    cp_commit();
    cp_wait<0>();
    __syncthreads();

    uint32_t qh[4][4], ql[4][4];
    {
        uint32_t qAddrH = sb0 + (wid >> 2) * AARR + ((wid & 3) * 16 + rA) * ARS;
        uint32_t qAddrL = qAddrH + 2 * AARR;
#pragma unroll
        for (int kc = 0; kc < 4; kc++) {
            ldsm_x4(qh[kc], qAddrH + kc * 32 + half);
            ldsm_x4(ql[kc], qAddrL + kc * 32 + half);
        }
    }
    __syncthreads();

    float ctxa[8][4];
#pragma unroll
    for (int dj = 0; dj < 8; dj++)
#pragma unroll
        for (int e = 0; e < 4; e++) ctxa[dj][e] = 0.f;
    float m0 = -1e30f, m1 = -1e30f, l0 = 0.f, l1 = 0.f;

    const int nkt = 2 * qt + 2;
    auto issue = [&](int kt, int st) {
#pragma unroll
        for (int t = 0; t < 8; t++) {
            int idx = tid + t * 256;
            int a = idx >> 9, rem = idx & 511, r = rem >> 3, sg = rem & 7;
            uint32_t dst = sb0 + st * ASTG + a * AARR + r * ARS + sg * 16;
            const void* src;
            if (a == 0)      src = Kh  + hB + (size_t)(kt * 64 + r) * DH + sg * 8;
            else if (a == 1) src = Kl  + hB + (size_t)(kt * 64 + r) * DH + sg * 8;
            else if (a == 2) src = Vth + vB + (size_t)r * SEQ + kt * 64 + sg * 8;
            else             src = Vtl + vB + (size_t)r * SEQ + kt * 64 + sg * 8;
            cp16(dst, src);
        }
        cp_commit();
    };

    issue(0, 0);
    issue(1, 1);

    const int qmin = qt * 128 + wid * 16;
    const int q0r = qmin + (lane >> 2);
    const int q1r = q0r + 8;

    for (int kt = 0; kt < nkt; kt++) {
        if (kt + 1 < nkt) cp_wait<1>(); else cp_wait<0>();
        __syncthreads();

        const int ktb = kt * 64;
        const bool skip = (ktb > qmin + 15);
        if (!skip) {
            const uint32_t sk = sb0 + (kt & 1) * ASTG;
            float s[8][4];
#pragma unroll
            for (int nj = 0; nj < 8; nj++)
#pragma unroll
                for (int e = 0; e < 4; e++) s[nj][e] = 0.f;

#pragma unroll
            for (int kc = 0; kc < 4; kc++) {
                uint32_t kbh[4][4], kbl[4][4];
#pragma unroll
                for (int g = 0; g < 4; g++) {
                    uint32_t ka = sk + (g * 16 + rA) * ARS + kc * 32 + half;
                    ldsm_x4(kbh[g], ka);
                    ldsm_x4(kbl[g], ka + AARR);
                }
#pragma unroll
                for (int nj = 0; nj < 8; nj++) {
                    const int g = nj >> 1, o = nj & 1;
                    mma_bf16(s[nj], qh[kc], kbh[g][o], kbh[g][o + 2]);
                    mma_bf16(s[nj], qh[kc], kbl[g][o], kbl[g][o + 2]);
                    mma_bf16(s[nj], ql[kc], kbh[g][o], kbh[g][o + 2]);
                }
            }

            if (ktb + 63 > qmin) {
#pragma unroll
                for (int nj = 0; nj < 8; nj++) {
                    int key = ktb + nj * 8 + ((lane & 3) << 1);
                    if (key     > q0r) s[nj][0] = -1e30f;
                    if (key + 1 > q0r) s[nj][1] = -1e30f;
                    if (key     > q1r) s[nj][2] = -1e30f;
                    if (key + 1 > q1r) s[nj][3] = -1e30f;
                }
            }

            float mx0 = -1e30f, mx1 = -1e30f;
#pragma unroll
            for (int nj = 0; nj < 8; nj++) {
                mx0 = fmaxf(mx0, fmaxf(s[nj][0], s[nj][1]));
                mx1 = fmaxf(mx1, fmaxf(s[nj][2], s[nj][3]));
            }
            mx0 = fmaxf(mx0, __shfl_xor_sync(0xFFFFFFFFu, mx0, 1));
            mx0 = fmaxf(mx0, __shfl_xor_sync(0xFFFFFFFFu, mx0, 2));
            mx1 = fmaxf(mx1, __shfl_xor_sync(0xFFFFFFFFu, mx1, 1));
            mx1 = fmaxf(mx1, __shfl_xor_sync(0xFFFFFFFFu, mx1, 2));
            float nm0 = fmaxf(m0, mx0), nm1 = fmaxf(m1, mx1);
            float f0 = __expf(m0 - nm0), f1 = __expf(m1 - nm1);
            m0 = nm0; m1 = nm1;

            float sum0 = 0.f, sum1 = 0.f;
#pragma unroll
            for (int nj = 0; nj < 8; nj++) {
                s[nj][0] = __expf(s[nj][0] - m0); sum0 += s[nj][0];
                s[nj][1] = __expf(s[nj][1] - m0); sum0 += s[nj][1];
                s[nj][2] = __expf(s[nj][2] - m1); sum1 += s[nj][2];
                s[nj][3] = __expf(s[nj][3] - m1); sum1 += s[nj][3];
            }
            sum0 += __shfl_xor_sync(0xFFFFFFFFu, sum0, 1);
            sum0 += __shfl_xor_sync(0xFFFFFFFFu, sum0, 2);
            sum1 += __shfl_xor_sync(0xFFFFFFFFu, sum1, 1);
            sum1 += __shfl_xor_sync(0xFFFFFFFFu, sum1, 2);
            l0 = l0 * f0 + sum0;
            l1 = l1 * f1 + sum1;
#pragma unroll
            for (int dj = 0; dj < 8; dj++) {
                ctxa[dj][0] *= f0; ctxa[dj][1] *= f0;
                ctxa[dj][2] *= f1; ctxa[dj][3] *= f1;
            }

            // ---- ctx += P @ V : P single fp16, V fp16 hi+lo (2 terms) ----
#pragma unroll
            for (int kc = 0; kc < 4; kc++) {
                uint32_t ph[4];
                ph[0] = pack_h2(s[2 * kc][0],     s[2 * kc][1]);
                ph[1] = pack_h2(s[2 * kc][2],     s[2 * kc][3]);
                ph[2] = pack_h2(s[2 * kc + 1][0], s[2 * kc + 1][1]);
                ph[3] = pack_h2(s[2 * kc + 1][2], s[2 * kc + 1][3]);

                uint32_t vh[4][4], vl[4][4];
#pragma unroll
                for (int g = 0; g < 4; g++) {
                    uint32_t va = sk + 2 * AARR + (g * 16 + rA) * ARS + kc * 32 + half;
                    ldsm_x4(vh[g], va);
                    ldsm_x4(vl[g], va + AARR);
                }
#pragma unroll
                for (int dj = 0; dj < 8; dj++) {
                    const int g = dj >> 1, o = dj & 1;
                    mma_f16(ctxa[dj], ph, vh[g][o], vh[g][o + 2]);
                    mma_f16(ctxa[dj], ph, vl[g][o], vl[g][o + 2]);
                }
            }
        }
        __syncthreads();
        if (kt + 2 < nkt) issue(kt + 2, kt & 1);
    }

    const float inv0 = 1.f / l0, inv1 = 1.f / l1;
    const int b = bh >> 4, h = bh & 15;
    const size_t row0 = (size_t)(b * SEQ + qt * 128 + wid * 16 + (lane >> 2));
#pragma unroll
    for (int dj = 0; dj < 8; dj++) {
        const int col = h * DH + dj * 8 + (lane & 3) * 2;
        *(uint32_t*)&C16[row0 * D + col] =
            pack_h2(ctxa[dj][0] * inv0, ctxa[dj][1] * inv0);
        *(uint32_t*)&C16[(row0 + 8) * D + col] =
            pack_h2(ctxa[dj][2] * inv1, ctxa[dj][3] * inv1);
    }
}

// ---------------------------------------------------------------------------
// Launch
// ---------------------------------------------------------------------------
extern "C" void kernel_launch(void* const* d_in, const int* in_sizes, int n_in,
                              void* d_out, int out_size)
{
    const float* x  = (const float*)d_in[0];
    const float* Wq = (const float*)d_in[1];
    const float* bq = (const float*)d_in[2];
    const float* Wk = (const float*)d_in[3];
    const float* bk = (const float*)d_in[4];
    const float* Wv = (const float*)d_in[5];
    const float* bv = (const float*)d_in[6];
    const float* Wo = (const float*)d_in[7];
    const float* bo = (const float*)d_in[8];
    float* out = (float*)d_out;

    __half *a16, *wh, *wl;
    cudaGetSymbolAddress((void**)&a16, g_a16);
    cudaGetSymbolAddress((void**)&wh, g_wh);
    cudaGetSymbolAddress((void**)&wl, g_wl);

    __nv_bfloat16 *qhp, *qlp, *khp, *klp;
    __half *vthp, *vtlp;
    cudaGetSymbolAddress((void**)&qhp, g_Qh);
    cudaGetSymbolAddress((void**)&qlp, g_Ql);
    cudaGetSymbolAddress((void**)&khp, g_Kh);
    cudaGetSymbolAddress((void**)&klp, g_Kl);
    cudaGetSymbolAddress((void**)&vthp, g_Vth);
    cudaGetSymbolAddress((void**)&vtlp, g_Vtl);

    cudaFuncSetAttribute(qkv_gemm, cudaFuncAttributeMaxDynamicSharedMemorySize, GSMEM);
    cudaFuncSetAttribute(gemm_tc, cudaFuncAttributeMaxDynamicSharedMemorySize, GSMEM);
    cudaFuncSetAttribute(attn_tc, cudaFuncAttributeMaxDynamicSharedMemorySize, ASMEM);

    // 1) fused prep: x -> fp16 + all 4 weight transposes/splits (one launch)
    prep_all<<<8192, 256>>>(x, a16, Wq, Wk, Wv, Wo, wh, wl);

    // 2) fused QKV projection (Q/K head-major splits; V transposed fp16 splits)
    dim3 gq(M_TOT / 128, 24);
    qkv_gemm<<<gq, 256, GSMEM>>>(a16, wh, wl, bq, bk, bv,
                                 qhp, qlp, khp, klp, vthp, vtlp);

    // 3) tensor-core attention (writes ctx fp16 into a16)
    dim3 ga(SEQ / 128, NBH);
    attn_tc<<<ga, 256, ASMEM>>>(qhp, qlp, khp, klp, vthp, vtlp, a16);

    // 4) output projection
    gemm_tc<<<dim3(M_TOT / 128, D / 128), 256, GSMEM>>>(
        a16, wh + 3 * (size_t)D * D, wl + 3 * (size_t)D * D, bo, out);
}

// round 17
// speedup vs baseline: 5.4611x; 1.2118x over previous
#include <cuda_runtime.h>
#include <cuda_bf16.h>
#include <cuda_fp16.h>
#include <cstdint>

static constexpr int SEQ = 2048;
static constexpr int NB  = 2;
static constexpr int D   = 1024;
static constexpr int NH  = 16;
static constexpr int DH  = 64;
static constexpr int M_TOT = NB * SEQ; // 4096
static constexpr int NBH  = NB * NH;   // 32

// ---------------- scratch (__device__ globals; no allocs allowed) ----------
__device__ __half g_a16[M_TOT * D];   // GEMM A operand (x, then ctx) fp16
__device__ __half g_wh[4][D * D];     // transposed weight splits [N][K], x64
__device__ __half g_wl[4][D * D];

// head-major attention operands: Q single fp16, K fp16 hi/lo [bh][s][64];
// V single fp16 transposed [bh][64][s]
static constexpr int HM = NBH * SEQ * DH;
__device__ __half g_Q16[HM];
__device__ __half g_Kh[HM], g_Kl[HM];
__device__ __half g_Vt[HM];

// ---------------- mma.sync / ldmatrix / cp.async helpers -------------------
__device__ __forceinline__ uint32_t smem_u32(const void* p) {
    uint32_t a;
    asm("{ .reg .u64 t; cvta.to.shared.u64 t, %1; cvt.u32.u64 %0, t; }" : "=r"(a) : "l"(p));
    return a;
}
__device__ __forceinline__ void ldsm_x4(uint32_t* r, uint32_t addr) {
    asm volatile("ldmatrix.sync.aligned.m8n8.x4.shared.b16 {%0,%1,%2,%3}, [%4];"
                 : "=r"(r[0]), "=r"(r[1]), "=r"(r[2]), "=r"(r[3]) : "r"(addr));
}
__device__ __forceinline__ void mma_f16(float* d, const uint32_t* a, uint32_t b0, uint32_t b1) {
    asm volatile(
        "mma.sync.aligned.m16n8k16.row.col.f32.f16.f16.f32 "
        "{%0,%1,%2,%3},{%4,%5,%6,%7},{%8,%9},{%0,%1,%2,%3};"
        : "+f"(d[0]), "+f"(d[1]), "+f"(d[2]), "+f"(d[3])
        : "r"(a[0]), "r"(a[1]), "r"(a[2]), "r"(a[3]), "r"(b0), "r"(b1));
}
__device__ __forceinline__ void cp16(uint32_t dst, const void* src) {
    asm volatile("cp.async.cg.shared.global [%0], [%1], 16;" :: "r"(dst), "l"(src));
}
__device__ __forceinline__ void cp_commit() {
    asm volatile("cp.async.commit_group;" ::: "memory");
}
template <int N>
__device__ __forceinline__ void cp_wait() {
    asm volatile("cp.async.wait_group %0;" :: "n"(N) : "memory");
}
__device__ __forceinline__ uint32_t pack_h2(float a, float b) {
    __half2 t = __floats2half2_rn(a, b);   // x = a (lower), y = b (upper)
    return *(uint32_t*)&t;
}
// split (a,b) fp32 pair -> packed fp16x2 hi + residual-lo
__device__ __forceinline__ void split_pair_h(float a, float b, uint32_t& hi, uint32_t& lo) {
    uint32_t h = pack_h2(a, b);
    __half2 hb = *(__half2*)&h;
    float ra = a - __half2float(hb.x);
    float rb = b - __half2float(hb.y);
    hi = h;
    lo = pack_h2(ra, rb);
}

// ---------------------------------------------------------------------------
// Fused prep: blocks [0,4096): x fp32 -> fp16 single (GEMM A layout)
//             blocks [4096,8192): weight z transpose+split (x64) fp16 hi/lo
// ---------------------------------------------------------------------------
__global__ __launch_bounds__(256) void prep_all(
    const float* __restrict__ X, __half* __restrict__ A16,
    const float* __restrict__ W0, const float* __restrict__ W1,
    const float* __restrict__ W2, const float* __restrict__ W3,
    __half* __restrict__ Thi, __half* __restrict__ Tlo)
{
    __shared__ float t[32][33];
    const int bx = blockIdx.x;
    const int tid = threadIdx.x;
    if (bx < 4096) {
        int i = bx * 1024 + tid * 4;
        float4 v = *(const float4*)&X[i];
        *(uint2*)&A16[i] = make_uint2(pack_h2(v.x, v.y), pack_h2(v.z, v.w));
    } else {
        const int r0 = bx - 4096;
        const int z = r0 >> 10;
        const int rem = r0 & 1023;
        const float* W = (z == 0) ? W0 : (z == 1) ? W1 : (z == 2) ? W2 : W3;
        __half* oh = Thi + (size_t)z * D * D;
        __half* ol = Tlo + (size_t)z * D * D;
        const int n0 = (rem & 31) * 32, k0 = (rem >> 5) * 32;
        const int tx = tid & 31, ty = tid >> 5;
#pragma unroll
        for (int r = ty; r < 32; r += 8)
            t[r][tx] = W[(size_t)(k0 + r) * D + n0 + tx];
        __syncthreads();
#pragma unroll
        for (int r = ty; r < 32; r += 8) {
            float v = t[tx][r] * 64.f;
            __half h = __float2half_rn(v);
            __half l = __float2half_rn(v - __half2float(h));
            oh[(size_t)(n0 + r) * D + k0 + tx] = h;
            ol[(size_t)(n0 + r) * D + k0 + tx] = l;
        }
    }
}

// ---------------------------------------------------------------------------
// GEMM mainloop. 128x128 block, warp tile 32x64, BK=32. 3-stage cp.async,
// one barrier per chunk. A = fp16 single; W = fp16 hi/lo (x64): 2 MMA terms.
// Paired-row XOR swizzle, 64B/row effective.
// ---------------------------------------------------------------------------
static constexpr int GK     = 1024;
static constexpr int BK     = 32;
static constexpr int NCHUNK = GK / BK;
static constexpr int ARR_B  = 64 * 128;          // 8192 B per operand tile
static constexpr int STAGE_B = 3 * ARR_B;        // 24576 B per stage (A, Wh, Wl)
static constexpr int GSMEM   = 3 * STAGE_B;      // 73728 B
static constexpr float INV64 = 1.f / 64.f;

// smem byte offset of 16B unit u (0..3) of logical row m (0..127)
__device__ __forceinline__ uint32_t swz(int m, int u) {
    const int R = m >> 1;
    const int unit = ((m & 1) << 2) | u;
    return (uint32_t)(R * 128 + ((unit ^ (R & 7)) << 4));
}

struct GemmCore {
    uint32_t sbase;
    int tid, wid, lane, wm, wn, rA;
    const char* srcs[3];
    int rowb[3];

    __device__ __forceinline__ void init(uint32_t sb, int m0, int n0,
        const __half* A16, const __half* Bhi, const __half* Blo)
    {
        sbase = sb;
        tid = threadIdx.x; wid = tid >> 5; lane = tid & 31;
        wm = wid & 3; wn = wid >> 2;
        rA = lane & 15;
        srcs[0] = (const char*)A16; srcs[1] = (const char*)Bhi;
        srcs[2] = (const char*)Blo;
        rowb[0] = m0; rowb[1] = n0; rowb[2] = n0;
    }
    __device__ __forceinline__ void issue(int chunk, int stage) {
#pragma unroll
        for (int t = 0; t < 6; t++) {
            int idx = tid + t * 256;
            int a = idx >> 9, rem = idx & 511, r = rem >> 2, q = rem & 3;
            uint32_t dst = sbase + stage * STAGE_B + a * ARR_B + swz(r, q);
            const char* src = srcs[a] +
                ((size_t)(rowb[a] + r) * GK + chunk * BK) * 2 + q * 16;
            cp16(dst, src);
        }
        cp_commit();
    }
    __device__ __forceinline__ void run(float acc[2][8][4]) {
#pragma unroll
        for (int mi = 0; mi < 2; mi++)
#pragma unroll
            for (int nj = 0; nj < 8; nj++)
#pragma unroll
                for (int e = 0; e < 4; e++) acc[mi][nj][e] = 0.f;

        issue(0, 0);
        issue(1, 1);

        int stg = 0;
        for (int c = 0; c < NCHUNK; c++) {
            if (c + 1 < NCHUNK) cp_wait<1>(); else cp_wait<0>();
            __syncthreads();
            if (c + 2 < NCHUNK) {
                int nstg = stg + 2; if (nstg >= 3) nstg -= 3;
                issue(c + 2, nstg);
            }
            const uint32_t sb = sbase + stg * STAGE_B;
#pragma unroll
            for (int s = 0; s < 2; s++) {
                const int u = s * 2 + (lane >> 4);   // 16B k-unit 0..3
                uint32_t ah[2][4];
                {
                    const int m = wm * 32 + rA;
                    ldsm_x4(ah[0], sb + swz(m, u));
                    ldsm_x4(ah[1], sb + swz(m + 16, u));
                }
#pragma unroll
                for (int g = 0; g < 4; g++) {
                    uint32_t bh[4], bl[4];
                    const int n = wn * 64 + g * 16 + rA;
                    uint32_t b0 = sb + ARR_B + swz(n, u);
                    ldsm_x4(bh, b0);
                    ldsm_x4(bl, b0 + ARR_B);
#pragma unroll
                    for (int o = 0; o < 2; o++) {
                        const int nj = g * 2 + o;
#pragma unroll
                        for (int mi = 0; mi < 2; mi++) {
                            mma_f16(acc[mi][nj], ah[mi], bh[o], bh[o + 2]);
                            mma_f16(acc[mi][nj], ah[mi], bl[o], bl[o + 2]);
                        }
                    }
                }
            }
            if (++stg >= 3) stg = 0;
        }
        __syncthreads();   // protect smem reuse by epilogues
    }
};

// ---------------------------------------------------------------------------
// Fused QKV projection. grid (32, 24): blockIdx.y>>3 selects {Q,K,V}.
// Q epilogue: single fp16 head-major (pre-scaled 0.125).
// K epilogue: fp16 hi/lo head-major splits.
// V epilogue: smem transpose -> single fp16 head-major Vt[bh][d][s].
// All accumulators carry the x64 weight scale -> multiply by 1/64.
// ---------------------------------------------------------------------------
static constexpr int VTP = 136;   // fp16 transpose pitch (elems)

__global__ __launch_bounds__(256, 2) void qkv_gemm(
    const __half* __restrict__ A16,
    const __half* __restrict__ Wh, const __half* __restrict__ Wl,
    const float* __restrict__ bq, const float* __restrict__ bk,
    const float* __restrict__ bv,
    __half* __restrict__ Q16,
    __half* __restrict__ Kh, __half* __restrict__ Kl,
    __half* __restrict__ Vt)
{
    extern __shared__ __align__(128) char dsm[];
    const int which = blockIdx.y >> 3;           // 0=Q 1=K 2=V
    const int m0 = blockIdx.x * 128;
    const int n0 = (blockIdx.y & 7) * 128;
    const float* bias = (which == 0) ? bq : (which == 1) ? bk : bv;

    GemmCore core;
    core.init(smem_u32(dsm), m0, n0,
              A16, Wh + (size_t)which * D * D, Wl + (size_t)which * D * D);
    float acc[2][8][4];
    core.run(acc);

    const int tid = core.tid, lane = core.lane, wm = core.wm, wn = core.wn;

    if (which == 2) {
        // ---- V: transpose via smem, write single fp16 [bh][d][s] ----
        __half* SH = (__half*)dsm;
#pragma unroll
        for (int mi = 0; mi < 2; mi++) {
            const int rl = wm * 32 + mi * 16 + (lane >> 2);
#pragma unroll
            for (int nj = 0; nj < 8; nj++) {
                const int cl = wn * 64 + nj * 8 + (lane & 3) * 2;
                float2 bb = *(const float2*)&bias[n0 + cl];
                float v[2][2] = {{acc[mi][nj][0] * INV64 + bb.x, acc[mi][nj][1] * INV64 + bb.y},
                                 {acc[mi][nj][2] * INV64 + bb.x, acc[mi][nj][3] * INV64 + bb.y}};
#pragma unroll
                for (int rr = 0; rr < 2; rr++)
#pragma unroll
                    for (int cc = 0; cc < 2; cc++) {
                        int o = (cl + cc) * VTP + rl + rr * 8;
                        SH[o] = __float2half_rn(v[rr][cc]);
                    }
            }
        }
        __syncthreads();
        // two threads per column: each copies 8 uint4 (128 B) of 256 B column
        const int c = tid >> 1, i0 = (tid & 1) * 8;
        const int n = n0 + c, hh = n >> 6, dd = n & 63;
        const int bI = m0 >> 11, s0 = m0 & 2047;
        __half* dst = Vt + ((size_t)(bI * NH + hh) * DH + dd) * SEQ + s0;
        const uint4* srow = (const uint4*)(SH + (size_t)c * VTP);
#pragma unroll
        for (int i = 0; i < 8; i++) ((uint4*)dst)[i0 + i] = srow[i0 + i];
    } else {
        const float scale = (which == 0) ? 0.125f : 1.0f;
#pragma unroll
        for (int mi = 0; mi < 2; mi++) {
            const int row = m0 + wm * 32 + mi * 16 + (lane >> 2);
#pragma unroll
            for (int nj = 0; nj < 8; nj++) {
                const int col = n0 + wn * 64 + nj * 8 + (lane & 3) * 2;
                float2 bb = *(const float2*)&bias[col];
                float v00 = acc[mi][nj][0] * INV64 + bb.x, v01 = acc[mi][nj][1] * INV64 + bb.y;
                float v10 = acc[mi][nj][2] * INV64 + bb.x, v11 = acc[mi][nj][3] * INV64 + bb.y;
                const int bI = row >> 11, h = col >> 6, dd = col & 63;
#pragma unroll
                for (int rr = 0; rr < 2; rr++) {
                    const int s = (row + rr * 8) & 2047;
                    size_t o = ((size_t)(bI * NH + h) * SEQ + s) * DH + dd;
                    float a0 = (rr ? v10 : v00) * scale;
                    float a1 = (rr ? v11 : v01) * scale;
                    if (which == 0) {
                        *(uint32_t*)&Q16[o] = pack_h2(a0, a1);
                    } else {
                        uint32_t hh2, ll2;
                        split_pair_h(a0, a1, hh2, ll2);
                        *(uint32_t*)&Kh[o] = hh2;
                        *(uint32_t*)&Kl[o] = ll2;
                    }
                }
            }
        }
    }
}

// ---------------------------------------------------------------------------
// Output-projection GEMM (fp32 out + bias, /64 weight scale).
// ---------------------------------------------------------------------------
__global__ __launch_bounds__(256, 2) void gemm_tc(
    const __half* __restrict__ A16,
    const __half* __restrict__ Bhi, const __half* __restrict__ Blo,
    const float* __restrict__ bias, float* __restrict__ C)
{
    extern __shared__ __align__(128) char dsm[];
    const int m0 = blockIdx.x * 128;
    const int n0 = blockIdx.y * 128;

    GemmCore core;
    core.init(smem_u32(dsm), m0, n0, A16, Bhi, Blo);
    float acc[2][8][4];
    core.run(acc);

    const int lane = core.lane, wm = core.wm, wn = core.wn;
#pragma unroll
    for (int mi = 0; mi < 2; mi++) {
        const int row = m0 + wm * 32 + mi * 16 + (lane >> 2);
#pragma unroll
        for (int nj = 0; nj < 8; nj++) {
            const int col = n0 + wn * 64 + nj * 8 + (lane & 3) * 2;
            float2 bb = *(const float2*)&bias[col];
            float2 v0 = {acc[mi][nj][0] * INV64 + bb.x, acc[mi][nj][1] * INV64 + bb.y};
            float2 v1 = {acc[mi][nj][2] * INV64 + bb.x, acc[mi][nj][3] * INV64 + bb.y};
            *(float2*)&C[(size_t)row * D + col]       = v0;
            *(float2*)&C[(size_t)(row + 8) * D + col] = v1;
        }
    }
}

// ---------------------------------------------------------------------------
// Tensor-core causal flash attention.
// S = QK^T: Q single fp16 x K fp16 hi/lo (2 terms).
// PV: P single fp16 x V single fp16 (1 term).
// Epilogue writes ctx as SINGLE fp16 (A operand of output projection).
// ---------------------------------------------------------------------------
static constexpr int ARS  = 144;
static constexpr int AARR = 64 * ARS;       // 9216 B per 64-row array
static constexpr int ASTG = 3 * AARR;       // Kh, Kl, Vt
static constexpr int ASMEM = 2 * ASTG;      // 55296 B

__global__ __launch_bounds__(256) void attn_tc(
    const __half* __restrict__ Q16,
    const __half* __restrict__ Kh, const __half* __restrict__ Kl,
    const __half* __restrict__ Vt,
    __half* __restrict__ C16)
{
    extern __shared__ __align__(128) char dsm[];
    const uint32_t sb0 = smem_u32(dsm);

    const int tid = threadIdx.x;
    const int wid = tid >> 5, lane = tid & 31;
    const int qt  = (gridDim.x - 1) - blockIdx.x;
    const int bh  = blockIdx.y;
    const size_t hB  = (size_t)bh * (SEQ * DH);
    const size_t vB  = (size_t)bh * (DH * SEQ);
    const int rA = lane & 15;
    const int half = (lane >> 4) * 16;

    // ---- stage Q tile (128 rows x 128B) into stage-0 region ----
#pragma unroll
    for (int t = 0; t < 4; t++) {
        int idx = tid + t * 256;
        int r = idx >> 3, sg = idx & 7;
        uint32_t dst = sb0 + r * ARS + sg * 16;
        cp16(dst, Q16 + hB + (size_t)(qt * 128 + r) * DH + sg * 8);
    }
    cp_commit();
    cp_wait<0>();
    __syncthreads();

    // ---- Q fragments (A operand), per warp 16 q rows ----
    uint32_t qf[4][4];
    {
        uint32_t qAddr = sb0 + (wid * 16 + rA) * ARS;
#pragma unroll
        for (int kc = 0; kc < 4; kc++)
            ldsm_x4(qf[kc], qAddr + kc * 32 + half);
    }
    __syncthreads();

    float ctxa[8][4];
#pragma unroll
    for (int dj = 0; dj < 8; dj++)
#pragma unroll
        for (int e = 0; e < 4; e++) ctxa[dj][e] = 0.f;
    float m0 = -1e30f, m1 = -1e30f, l0 = 0.f, l1 = 0.f;

    const int nkt = 2 * qt + 2;
    auto issue = [&](int kt, int st) {
#pragma unroll
        for (int t = 0; t < 6; t++) {
            int idx = tid + t * 256;
            int a = idx >> 9, rem = idx & 511, r = rem >> 3, sg = rem & 7;
            uint32_t dst = sb0 + st * ASTG + a * AARR + r * ARS + sg * 16;
            const void* src;
            if (a == 0)      src = Kh + hB + (size_t)(kt * 64 + r) * DH + sg * 8;
            else if (a == 1) src = Kl + hB + (size_t)(kt * 64 + r) * DH + sg * 8;
            else             src = Vt + vB + (size_t)r * SEQ + kt * 64 + sg * 8;
            cp16(dst, src);
        }
        cp_commit();
    };

    issue(0, 0);
    issue(1, 1);

    const int qmin = qt * 128 + wid * 16;
    const int q0r = qmin + (lane >> 2);
    const int q1r = q0r + 8;

    for (int kt = 0; kt < nkt; kt++) {
        if (kt + 1 < nkt) cp_wait<1>(); else cp_wait<0>();
        __syncthreads();

        const int ktb = kt * 64;
        const bool skip = (ktb > qmin + 15);
        if (!skip) {
            const uint32_t sk = sb0 + (kt & 1) * ASTG;
            float s[8][4];
#pragma unroll
            for (int nj = 0; nj < 8; nj++)
#pragma unroll
                for (int e = 0; e < 4; e++) s[nj][e] = 0.f;

            // ---- S = Q @ K^T : Q single x K hi/lo (2 terms) ----
#pragma unroll
            for (int kc = 0; kc < 4; kc++) {
                uint32_t kbh[4][4], kbl[4][4];
#pragma unroll
                for (int g = 0; g < 4; g++) {
                    uint32_t ka = sk + (g * 16 + rA) * ARS + kc * 32 + half;
                    ldsm_x4(kbh[g], ka);
                    ldsm_x4(kbl[g], ka + AARR);
                }
#pragma unroll
                for (int nj = 0; nj < 8; nj++) {
                    const int g = nj >> 1, o = nj & 1;
                    mma_f16(s[nj], qf[kc], kbh[g][o], kbh[g][o + 2]);
                    mma_f16(s[nj], qf[kc], kbl[g][o], kbl[g][o + 2]);
                }
            }

            if (ktb + 63 > qmin) {
#pragma unroll
                for (int nj = 0; nj < 8; nj++) {
                    int key = ktb + nj * 8 + ((lane & 3) << 1);
                    if (key     > q0r) s[nj][0] = -1e30f;
                    if (key + 1 > q0r) s[nj][1] = -1e30f;
                    if (key     > q1r) s[nj][2] = -1e30f;
                    if (key + 1 > q1r) s[nj][3] = -1e30f;
                }
            }

            float mx0 = -1e30f, mx1 = -1e30f;
#pragma unroll
            for (int nj = 0; nj < 8; nj++) {
                mx0 = fmaxf(mx0, fmaxf(s[nj][0], s[nj][1]));
                mx1 = fmaxf(mx1, fmaxf(s[nj][2], s[nj][3]));
            }
            mx0 = fmaxf(mx0, __shfl_xor_sync(0xFFFFFFFFu, mx0, 1));
            mx0 = fmaxf(mx0, __shfl_xor_sync(0xFFFFFFFFu, mx0, 2));
            mx1 = fmaxf(mx1, __shfl_xor_sync(0xFFFFFFFFu, mx1, 1));
            mx1 = fmaxf(mx1, __shfl_xor_sync(0xFFFFFFFFu, mx1, 2));
            float nm0 = fmaxf(m0, mx0), nm1 = fmaxf(m1, mx1);
            float f0 = __expf(m0 - nm0), f1 = __expf(m1 - nm1);
            m0 = nm0; m1 = nm1;

            float sum0 = 0.f, sum1 = 0.f;
#pragma unroll
            for (int nj = 0; nj < 8; nj++) {
                s[nj][0] = __expf(s[nj][0] - m0); sum0 += s[nj][0];
                s[nj][1] = __expf(s[nj][1] - m0); sum0 += s[nj][1];
                s[nj][2] = __expf(s[nj][2] - m1); sum1 += s[nj][2];
                s[nj][3] = __expf(s[nj][3] - m1); sum1 += s[nj][3];
            }
            sum0 += __shfl_xor_sync(0xFFFFFFFFu, sum0, 1);
            sum0 += __shfl_xor_sync(0xFFFFFFFFu, sum0, 2);
            sum1 += __shfl_xor_sync(0xFFFFFFFFu, sum1, 1);
            sum1 += __shfl_xor_sync(0xFFFFFFFFu, sum1, 2);
            l0 = l0 * f0 + sum0;
            l1 = l1 * f1 + sum1;
#pragma unroll
            for (int dj = 0; dj < 8; dj++) {
                ctxa[dj][0] *= f0; ctxa[dj][1] *= f0;
                ctxa[dj][2] *= f1; ctxa[dj][3] *= f1;
            }

            // ---- ctx += P @ V : P single fp16 x V single fp16 (1 term) ----
#pragma unroll
            for (int kc = 0; kc < 4; kc++) {
                uint32_t ph[4];
                ph[0] = pack_h2(s[2 * kc][0],     s[2 * kc][1]);
                ph[1] = pack_h2(s[2 * kc][2],     s[2 * kc][3]);
                ph[2] = pack_h2(s[2 * kc + 1][0], s[2 * kc + 1][1]);
                ph[3] = pack_h2(s[2 * kc + 1][2], s[2 * kc + 1][3]);

                uint32_t vh[4][4];
#pragma unroll
                for (int g = 0; g < 4; g++) {
                    uint32_t va = sk + 2 * AARR + (g * 16 + rA) * ARS + kc * 32 + half;
                    ldsm_x4(vh[g], va);
                }
#pragma unroll
                for (int dj = 0; dj < 8; dj++) {
                    const int g = dj >> 1, o = dj & 1;
                    mma_f16(ctxa[dj], ph, vh[g][o], vh[g][o + 2]);
                }
            }
        }
        __syncthreads();
        if (kt + 2 < nkt) issue(kt + 2, kt & 1);
    }

    const float inv0 = 1.f / l0, inv1 = 1.f / l1;
    const int b = bh >> 4, h = bh & 15;
    const size_t row0 = (size_t)(b * SEQ + qt * 128 + wid * 16 + (lane >> 2));
#pragma unroll
    for (int dj = 0; dj < 8; dj++) {
        const int col = h * DH + dj * 8 + (lane & 3) * 2;
        *(uint32_t*)&C16[row0 * D + col] =
            pack_h2(ctxa[dj][0] * inv0, ctxa[dj][1] * inv0);
        *(uint32_t*)&C16[(row0 + 8) * D + col] =
            pack_h2(ctxa[dj][2] * inv1, ctxa[dj][3] * inv1);
    }
}

// ---------------------------------------------------------------------------
// Launch
// ---------------------------------------------------------------------------
extern "C" void kernel_launch(void* const* d_in, const int* in_sizes, int n_in,
                              void* d_out, int out_size)
{
    const float* x  = (const float*)d_in[0];
    const float* Wq = (const float*)d_in[1];
    const float* bq = (const float*)d_in[2];
    const float* Wk = (const float*)d_in[3];
    const float* bk = (const float*)d_in[4];
    const float* Wv = (const float*)d_in[5];
    const float* bv = (const float*)d_in[6];
    const float* Wo = (const float*)d_in[7];
    const float* bo = (const float*)d_in[8];
    float* out = (float*)d_out;

    __half *a16, *wh, *wl;
    cudaGetSymbolAddress((void**)&a16, g_a16);
    cudaGetSymbolAddress((void**)&wh, g_wh);
    cudaGetSymbolAddress((void**)&wl, g_wl);

    __half *q16, *khp, *klp, *vtp;
    cudaGetSymbolAddress((void**)&q16, g_Q16);
    cudaGetSymbolAddress((void**)&khp, g_Kh);
    cudaGetSymbolAddress((void**)&klp, g_Kl);
    cudaGetSymbolAddress((void**)&vtp, g_Vt);

    cudaFuncSetAttribute(qkv_gemm, cudaFuncAttributeMaxDynamicSharedMemorySize, GSMEM);
    cudaFuncSetAttribute(gemm_tc, cudaFuncAttributeMaxDynamicSharedMemorySize, GSMEM);
    cudaFuncSetAttribute(attn_tc, cudaFuncAttributeMaxDynamicSharedMemorySize, ASMEM);

    // 1) fused prep: x -> fp16 + all 4 weight transposes/splits (one launch)
    prep_all<<<8192, 256>>>(x, a16, Wq, Wk, Wv, Wo, wh, wl);

    // 2) fused QKV projection (Q single fp16; K fp16 hi/lo; V transposed fp16)
    dim3 gq(M_TOT / 128, 24);
    qkv_gemm<<<gq, 256, GSMEM>>>(a16, wh, wl, bq, bk, bv,
                                 q16, khp, klp, vtp);

    // 3) tensor-core attention (writes ctx fp16 into a16)
    dim3 ga(SEQ / 128, NBH);
    attn_tc<<<ga, 256, ASMEM>>>(q16, khp, klp, vtp, a16);

    // 4) output projection
    gemm_tc<<<dim3(M_TOT / 128, D / 128), 256, GSMEM>>>(
        a16, wh + 3 * (size_t)D * D, wl + 3 * (size_t)D * D, bo, out);
}